// round 8
// baseline (speedup 1.0000x reference)
#include <cuda_runtime.h>
#include <math.h>

// ODE-RNN persistent kernel, round 8 (base = round 6, 37.4ms):
//  - Activations for MLP B-operands stored PRE-CONVERTED to tf32 in
//    m-interleaved layout p[k][2*(m&7)+(m>>3)] (row stride 18): the mma
//    B-fragment pair (m, m+8) is a single LDS.64, no per-read CVT.
//    MLP inner loop: 1 LDG.128 + 2 LDS.64 + 2 MMA (was +4 LDS.32 +4 CVT).
//  - a1/a2 live only in packed form; hT/yT keep fp32 state (stride 20,
//    for RK4/GRU/gates) plus a packed tf32 mirror written in the epilogues.
// Grid: 64 CTAs x 512 threads, MB=16 rows per CTA.

#define NT 512
#define MBR 16
#define NCTA 64
#define T_LEN 200
#define XSF 20   // fp32 state row stride (float4-aligned)
#define XSP 18   // packed tf32 row stride (float2-aligned)

typedef unsigned long long ull;

__device__ float g_WihT[16 * 768 * 4];
__device__ float g_WhhT[64 * 768 * 4];
// MLP tf32 fragment-packed weights: [nt(16)][kt(32)][lane(32)][a0..a3]
__device__ unsigned g_W1F[16 * 32 * 32 * 4];
__device__ unsigned g_W2F[16 * 32 * 32 * 4];
__device__ unsigned g_W3F[16 * 32 * 32 * 4];
__device__ float g_W1last[256];

__device__ __forceinline__ unsigned tf32r(float f) {
    unsigned u;
    asm("cvt.rna.tf32.f32 %0, %1;" : "=r"(u) : "f"(f));
    return u;
}
__device__ __forceinline__ float tf32f(float f) {
    return __uint_as_float(tf32r(f));
}

__global__ void prep_kernel(const float* __restrict__ W_ih,
                            const float* __restrict__ W_hh,
                            const float* __restrict__ W1,
                            const float* __restrict__ W2,
                            const float* __restrict__ W3) {
    int idx = blockIdx.x * blockDim.x + threadIdx.x;
    int stride = gridDim.x * blockDim.x;
    for (int t = idx; t < 16 * 768 * 4; t += stride) {
        int j = t & 3, nk = t >> 2;
        int n = nk % 768, k4 = nk / 768;
        g_WihT[t] = W_ih[n * 64 + k4 * 4 + j];
    }
    for (int t = idx; t < 64 * 768 * 4; t += stride) {
        int j = t & 3, nk = t >> 2;
        int n = nk % 768, k4 = nk / 768;
        g_WhhT[t] = W_hh[n * 256 + k4 * 4 + j];
    }
    for (int tI = idx; tI < 16 * 32 * 32; tI += stride) {
        int l = tI & 31, kt = (tI >> 5) & 31, nt = tI >> 10;
        int gid = l >> 2, tig = l & 3;
        int r0 = nt * 16 + gid, r1 = r0 + 8;
        int c0 = kt * 8 + tig, c1 = c0 + 4;
        g_W1F[tI * 4 + 0] = tf32r(W1[r0 * 257 + c0]);
        g_W1F[tI * 4 + 1] = tf32r(W1[r1 * 257 + c0]);
        g_W1F[tI * 4 + 2] = tf32r(W1[r0 * 257 + c1]);
        g_W1F[tI * 4 + 3] = tf32r(W1[r1 * 257 + c1]);
        g_W2F[tI * 4 + 0] = tf32r(W2[r0 * 256 + c0]);
        g_W2F[tI * 4 + 1] = tf32r(W2[r1 * 256 + c0]);
        g_W2F[tI * 4 + 2] = tf32r(W2[r0 * 256 + c1]);
        g_W2F[tI * 4 + 3] = tf32r(W2[r1 * 256 + c1]);
        g_W3F[tI * 4 + 0] = tf32r(W3[r0 * 256 + c0]);
        g_W3F[tI * 4 + 1] = tf32r(W3[r1 * 256 + c0]);
        g_W3F[tI * 4 + 2] = tf32r(W3[r0 * 256 + c1]);
        g_W3F[tI * 4 + 3] = tf32r(W3[r1 * 256 + c1]);
    }
    for (int n = idx; n < 256; n += stride) g_W1last[n] = W1[n * 257 + 256];
}

__device__ __forceinline__ float sigm(float v) {
    return 1.0f / (1.0f + __expf(-v));
}
__device__ __forceinline__ float tanha(float v) {
    float r;
    asm("tanh.approx.f32 %0, %1;" : "=f"(r) : "f"(v));
    return r;
}
__device__ __forceinline__ ull pk2(float a, float b) {
    ull r;
    asm("mov.b64 %0, {%1, %2};" : "=l"(r) : "f"(a), "f"(b));
    return r;
}
__device__ __forceinline__ ull ffma2(ull a, ull b, ull c) {
    ull d;
    asm("fma.rn.f32x2 %0, %1, %2, %3;" : "=l"(d) : "l"(a), "l"(b), "l"(c));
    return d;
}

#define MMA_TF32(c0, c1, c2, c3, A0, A1, A2, A3, B0, B1)                      \
    asm volatile(                                                             \
        "mma.sync.aligned.m16n8k8.row.col.f32.tf32.tf32.f32 "                 \
        "{%0,%1,%2,%3}, {%4,%5,%6,%7}, {%8,%9}, {%0,%1,%2,%3};"               \
        : "+f"(c0), "+f"(c1), "+f"(c2), "+f"(c3)                              \
        : "r"(A0), "r"(A1), "r"(A2), "r"(A3), "r"(B0), "r"(B1))

// One MLP GEMM: D[256][16] = W @ B, warp w owns n-rows [16w,16w+16), full K.
// Bp: packed tf32 activations, layout p[k*XSP + 2*(m&7) + (m>>3)].
// EPI 0: bias(+tt*w1l)+tanh -> dstp (packed tf32 only).
// EPI 1..4: RK4 stage update fused, writing fp32 state + packed mirrors.
template<int EPI>
__device__ __forceinline__ void gemm16(const unsigned* __restrict__ WF,
                                       const float* __restrict__ Bp,
                                       float* __restrict__ dstp,
                                       const float* __restrict__ bias,
                                       const float* __restrict__ w1l,
                                       float tt, bool tcol,
                                       float* __restrict__ hT,
                                       float* __restrict__ hTp,
                                       float* __restrict__ yT,
                                       float* __restrict__ yTp,
                                       float* __restrict__ ka,
                                       const float* __restrict__ b3s,
                                       float dt) {
    const int warp = threadIdx.x >> 5;
    const int lane = threadIdx.x & 31;
    const int gid = lane >> 2, tig = lane & 3;
    float c00 = 0.f, c01 = 0.f, c02 = 0.f, c03 = 0.f;  // r0/r1 x (mc, mc+1)
    float c10 = 0.f, c11 = 0.f, c12 = 0.f, c13 = 0.f;  // r0/r1 x (mc+8, mc+9)
    const float4* __restrict__ wp =
        reinterpret_cast<const float4*>(WF) + (warp * 32 * 32 + lane);
    const float* __restrict__ bq = Bp + tig * XSP + 2 * gid;
#pragma unroll 4
    for (int kt = 0; kt < 32; ++kt) {
        float4 af = wp[kt * 32];
        unsigned A0 = __float_as_uint(af.x), A1 = __float_as_uint(af.y);
        unsigned A2 = __float_as_uint(af.z), A3 = __float_as_uint(af.w);
        const float* __restrict__ b = bq + kt * 8 * XSP;
        float2 bl = *reinterpret_cast<const float2*>(b);            // k=tig
        float2 bh = *reinterpret_cast<const float2*>(b + 4 * XSP);  // k=tig+4
        MMA_TF32(c00, c01, c02, c03, A0, A1, A2, A3,
                 __float_as_uint(bl.x), __float_as_uint(bh.x));
        MMA_TF32(c10, c11, c12, c13, A0, A1, A2, A3,
                 __float_as_uint(bl.y), __float_as_uint(bh.y));
    }
    const int r0 = warp * 16 + gid, r1 = r0 + 8;
    const int mc = 2 * tig;
    if (EPI == 0) {
        float bb0 = bias[r0], bb1 = bias[r1];
        if (tcol) { bb0 += tt * w1l[r0]; bb1 += tt * w1l[r1]; }
        // packed words [2mc..2mc+3] of row r: (m=mc, m=mc+8, m=mc+1, m=mc+9)
        *reinterpret_cast<float2*>(&dstp[r0 * XSP + 2 * mc]) =
            make_float2(tf32f(tanha(bb0 + c00)), tf32f(tanha(bb0 + c10)));
        *reinterpret_cast<float2*>(&dstp[r0 * XSP + 2 * mc + 2]) =
            make_float2(tf32f(tanha(bb0 + c01)), tf32f(tanha(bb0 + c11)));
        *reinterpret_cast<float2*>(&dstp[r1 * XSP + 2 * mc]) =
            make_float2(tf32f(tanha(bb1 + c02)), tf32f(tanha(bb1 + c12)));
        *reinterpret_cast<float2*>(&dstp[r1 * XSP + 2 * mc + 2]) =
            make_float2(tf32f(tanha(bb1 + c03)), tf32f(tanha(bb1 + c13)));
    } else {
        float b0v = b3s[r0], b1v = b3s[r1];
        float f00 = b0v + c00, f01 = b0v + c01;    // r0: mc, mc+1
        float f10 = b0v + c10, f11 = b0v + c11;    // r0: mc+8, mc+9
        float f02 = b1v + c02, f03 = b1v + c03;    // r1: mc, mc+1
        float f12 = b1v + c12, f13 = b1v + c13;    // r1: mc+8, mc+9
        float2 h0a = *reinterpret_cast<float2*>(&hT[r0 * XSF + mc]);
        float2 h0b = *reinterpret_cast<float2*>(&hT[r0 * XSF + mc + 8]);
        float2 h1a = *reinterpret_cast<float2*>(&hT[r1 * XSF + mc]);
        float2 h1b = *reinterpret_cast<float2*>(&hT[r1 * XSF + mc + 8]);
        if (EPI == 1) {
            *reinterpret_cast<float2*>(&ka[r0 * XSF + mc])     = make_float2(f00, f01);
            *reinterpret_cast<float2*>(&ka[r0 * XSF + mc + 8]) = make_float2(f10, f11);
            *reinterpret_cast<float2*>(&ka[r1 * XSF + mc])     = make_float2(f02, f03);
            *reinterpret_cast<float2*>(&ka[r1 * XSF + mc + 8]) = make_float2(f12, f13);
        } else {
            float2 k0a = *reinterpret_cast<float2*>(&ka[r0 * XSF + mc]);
            float2 k0b = *reinterpret_cast<float2*>(&ka[r0 * XSF + mc + 8]);
            float2 k1a = *reinterpret_cast<float2*>(&ka[r1 * XSF + mc]);
            float2 k1b = *reinterpret_cast<float2*>(&ka[r1 * XSF + mc + 8]);
            if (EPI == 2 || EPI == 3) {
                *reinterpret_cast<float2*>(&ka[r0 * XSF + mc]) =
                    make_float2(k0a.x + 2.f * f00, k0a.y + 2.f * f01);
                *reinterpret_cast<float2*>(&ka[r0 * XSF + mc + 8]) =
                    make_float2(k0b.x + 2.f * f10, k0b.y + 2.f * f11);
                *reinterpret_cast<float2*>(&ka[r1 * XSF + mc]) =
                    make_float2(k1a.x + 2.f * f02, k1a.y + 2.f * f03);
                *reinterpret_cast<float2*>(&ka[r1 * XSF + mc + 8]) =
                    make_float2(k1b.x + 2.f * f12, k1b.y + 2.f * f13);
            } else {  // EPI == 4
                float c = dt * (1.0f / 6.0f);
                float n00 = h0a.x + c * (k0a.x + f00), n01 = h0a.y + c * (k0a.y + f01);
                float n10 = h0b.x + c * (k0b.x + f10), n11 = h0b.y + c * (k0b.y + f11);
                float n02 = h1a.x + c * (k1a.x + f02), n03 = h1a.y + c * (k1a.y + f03);
                float n12 = h1b.x + c * (k1b.x + f12), n13 = h1b.y + c * (k1b.y + f13);
                *reinterpret_cast<float2*>(&hT[r0 * XSF + mc])     = make_float2(n00, n01);
                *reinterpret_cast<float2*>(&hT[r0 * XSF + mc + 8]) = make_float2(n10, n11);
                *reinterpret_cast<float2*>(&hT[r1 * XSF + mc])     = make_float2(n02, n03);
                *reinterpret_cast<float2*>(&hT[r1 * XSF + mc + 8]) = make_float2(n12, n13);
                *reinterpret_cast<float2*>(&hTp[r0 * XSP + 2 * mc]) =
                    make_float2(tf32f(n00), tf32f(n10));
                *reinterpret_cast<float2*>(&hTp[r0 * XSP + 2 * mc + 2]) =
                    make_float2(tf32f(n01), tf32f(n11));
                *reinterpret_cast<float2*>(&hTp[r1 * XSP + 2 * mc]) =
                    make_float2(tf32f(n02), tf32f(n12));
                *reinterpret_cast<float2*>(&hTp[r1 * XSP + 2 * mc + 2]) =
                    make_float2(tf32f(n03), tf32f(n13));
                return;
            }
        }
        // EPI 1..3: y = h + c*f (c = dt/2 or dt), fp32 + packed mirror
        float c = (EPI == 3) ? dt : 0.5f * dt;
        float y00 = h0a.x + c * f00, y01 = h0a.y + c * f01;
        float y10 = h0b.x + c * f10, y11 = h0b.y + c * f11;
        float y02 = h1a.x + c * f02, y03 = h1a.y + c * f03;
        float y12 = h1b.x + c * f12, y13 = h1b.y + c * f13;
        *reinterpret_cast<float2*>(&yT[r0 * XSF + mc])     = make_float2(y00, y01);
        *reinterpret_cast<float2*>(&yT[r0 * XSF + mc + 8]) = make_float2(y10, y11);
        *reinterpret_cast<float2*>(&yT[r1 * XSF + mc])     = make_float2(y02, y03);
        *reinterpret_cast<float2*>(&yT[r1 * XSF + mc + 8]) = make_float2(y12, y13);
        *reinterpret_cast<float2*>(&yTp[r0 * XSP + 2 * mc]) =
            make_float2(tf32f(y00), tf32f(y10));
        *reinterpret_cast<float2*>(&yTp[r0 * XSP + 2 * mc + 2]) =
            make_float2(tf32f(y01), tf32f(y11));
        *reinterpret_cast<float2*>(&yTp[r1 * XSP + 2 * mc]) =
            make_float2(tf32f(y02), tf32f(y12));
        *reinterpret_cast<float2*>(&yTp[r1 * XSP + 2 * mc + 2]) =
            make_float2(tf32f(y03), tf32f(y13));
    }
}

// GRU GEMM, fp32 FFMA2, 8 m per thread (mh = m-half), xs row stride XSF.
template<int K>
__device__ __forceinline__ void gru_mm(const float* __restrict__ WT4,
                                       const float* __restrict__ bias,
                                       const float* __restrict__ xs,
                                       float* __restrict__ ys, int N) {
    const int n0 = threadIdx.x & 255;
    const int mh = threadIdx.x >> 8;
    const float* __restrict__ xb = xs + mh * 8;
    for (int n = n0; n < N; n += 256) {
        float a0 = bias[n];
        ull acc0 = 0ULL, acc1 = 0ULL, acc2 = 0ULL, acc3 = 0ULL;
        const float4* __restrict__ wp = reinterpret_cast<const float4*>(WT4) + n;
#pragma unroll 2
        for (int k4 = 0; k4 < K / 4; ++k4) {
            float4 w = wp[(size_t)k4 * N];
            const float* __restrict__ xr = xb + (k4 * 4) * XSF;
#pragma unroll
            for (int kk = 0; kk < 4; ++kk) {
                float wv = (kk == 0 ? w.x : kk == 1 ? w.y : kk == 2 ? w.z : w.w);
                ull wd = pk2(wv, wv);
                float4 xa = *reinterpret_cast<const float4*>(xr + kk * XSF);
                float4 xbv = *reinterpret_cast<const float4*>(xr + kk * XSF + 4);
                acc0 = ffma2(wd, pk2(xa.x, xa.y), acc0);
                acc1 = ffma2(wd, pk2(xa.z, xa.w), acc1);
                acc2 = ffma2(wd, pk2(xbv.x, xbv.y), acc2);
                acc3 = ffma2(wd, pk2(xbv.z, xbv.w), acc3);
            }
        }
        float2 p0 = *reinterpret_cast<float2*>(&acc0);
        float2 p1 = *reinterpret_cast<float2*>(&acc1);
        float2 p2 = *reinterpret_cast<float2*>(&acc2);
        float2 p3 = *reinterpret_cast<float2*>(&acc3);
        float* yp = ys + n * 16 + mh * 8;
        *reinterpret_cast<float4*>(yp) =
            make_float4(a0 + p0.x, a0 + p0.y, a0 + p1.x, a0 + p1.y);
        *reinterpret_cast<float4*>(yp + 4) =
            make_float4(a0 + p2.x, a0 + p2.y, a0 + p3.x, a0 + p3.y);
    }
}

__global__ void __launch_bounds__(NT, 1)
odernn_kernel(const float* __restrict__ x,
              const float* __restrict__ t,
              const float* __restrict__ mask,
              const float* __restrict__ b_ih,
              const float* __restrict__ b_hh,
              const float* __restrict__ b1,
              const float* __restrict__ b2,
              const float* __restrict__ b3,
              float* __restrict__ out) {
    extern __shared__ float sm[];
    float* xT  = sm;               // 64*20  = 1280
    float* hT  = sm + 1280;        // 256*20 = 5120
    float* hTp = sm + 6400;        // 256*18 = 4608
    float* U   = sm + 11008;       // union region: 24576 floats
    float* gi  = U;                // 768*16 = 12288 (GRU phase)
    float* gh  = U + 12288;        // 12288
    float* yT  = U;                // 5120 (RK4 phase)
    float* ka  = U + 5120;         // 5120
    float* a1p = U + 10240;        // 4608
    float* a2p = U + 14848;        // 4608
    float* yTp = U + 19456;        // 4608 (total 24064 <= 24576)
    float* bihs = sm + 35584;      // 768
    float* bhhs = bihs + 768;      // 768
    float* b1s  = bhhs + 768;      // 256
    float* b2s  = b1s + 256;       // 256
    float* b3s  = b2s + 256;       // 256
    float* w1ls = b3s + 256;       // 256
    // total 38144 floats = 152576 bytes

    const int tid = threadIdx.x;
    const int m0 = blockIdx.x * MBR;

    for (int idx = tid; idx < 768; idx += NT) { bihs[idx] = b_ih[idx]; bhhs[idx] = b_hh[idx]; }
    for (int idx = tid; idx < 256; idx += NT) {
        b1s[idx] = b1[idx]; b2s[idx] = b2[idx]; b3s[idx] = b3[idx];
        w1ls[idx] = g_W1last[idx];
    }
    for (int idx = tid; idx < 256 * XSF; idx += NT) hT[idx] = 0.0f;
    for (int idx = tid; idx < 256 * XSP; idx += NT) hTp[idx] = 0.0f;
    __syncthreads();

    for (int i = 0; i < T_LEN; ++i) {
        for (int idx = tid; idx < 64 * MBR; idx += NT) {
            int k = idx & 63, m = idx >> 6;
            xT[k * XSF + m] = x[((size_t)(m0 + m) * T_LEN + i) * 64 + k];
        }
        __syncthreads();

        gru_mm<64>(g_WihT, bihs, xT, gi, 768);
        gru_mm<256>(g_WhhT, bhhs, hT, gh, 768);
        __syncthreads();

        // gate pointwise: m = tid&15, n = (tid>>4) + 32j; writes hT + hTp
        {
            const int pm = tid & 15;
            const int pn0 = tid >> 4;
            const int pidx = 2 * (pm & 7) + (pm >> 3);
#pragma unroll
            for (int j = 0; j < 8; ++j) {
                int n = pn0 + j * 32;
                float ir = gi[n * 16 + pm];
                float iz = gi[(256 + n) * 16 + pm];
                float in_ = gi[(512 + n) * 16 + pm];
                float hr = gh[n * 16 + pm];
                float hz = gh[(256 + n) * 16 + pm];
                float hn = gh[(512 + n) * 16 + pm];
                float h = hT[n * XSF + pm];
                float r = sigm(ir + hr);
                float z = sigm(iz + hz);
                float nn = tanhf(in_ + r * hn);
                float hnew = (1.0f - z) * nn + z * h;
                float mk = mask[(size_t)(m0 + pm) * T_LEN + i];
                float hobs = mk * hnew + (1.0f - mk) * h;
                hT[n * XSF + pm] = hobs;
                hTp[n * XSP + pidx] = tf32f(hobs);
                out[((size_t)(m0 + pm) * T_LEN + i) * 256 + n] = hobs;
            }
        }
        __syncthreads();

        if (i == T_LEN - 1) break;

        float t0v = t[i], t1v = t[i + 1];
        float dt = (t1v - t0v) * 0.25f;
        float tt = t0v;
        for (int sub = 0; sub < 4; ++sub) {
            // stage 1: f(tt, h)
            gemm16<0>(g_W1F, hTp, a1p, b1s, w1ls, tt, true, 0, 0, 0, 0, 0, 0, 0.f); __syncthreads();
            gemm16<0>(g_W2F, a1p, a2p, b2s, 0, 0.f, false, 0, 0, 0, 0, 0, 0, 0.f); __syncthreads();
            gemm16<1>(g_W3F, a2p, 0, 0, 0, 0.f, false, hT, hTp, yT, yTp, ka, b3s, dt); __syncthreads();
            // stage 2: f(tt+dt/2, y)
            gemm16<0>(g_W1F, yTp, a1p, b1s, w1ls, tt + 0.5f * dt, true, 0, 0, 0, 0, 0, 0, 0.f); __syncthreads();
            gemm16<0>(g_W2F, a1p, a2p, b2s, 0, 0.f, false, 0, 0, 0, 0, 0, 0, 0.f); __syncthreads();
            gemm16<2>(g_W3F, a2p, 0, 0, 0, 0.f, false, hT, hTp, yT, yTp, ka, b3s, dt); __syncthreads();
            // stage 3: f(tt+dt/2, y)
            gemm16<0>(g_W1F, yTp, a1p, b1s, w1ls, tt + 0.5f * dt, true, 0, 0, 0, 0, 0, 0, 0.f); __syncthreads();
            gemm16<0>(g_W2F, a1p, a2p, b2s, 0, 0.f, false, 0, 0, 0, 0, 0, 0, 0.f); __syncthreads();
            gemm16<3>(g_W3F, a2p, 0, 0, 0, 0.f, false, hT, hTp, yT, yTp, ka, b3s, dt); __syncthreads();
            // stage 4: f(tt+dt, y)
            gemm16<0>(g_W1F, yTp, a1p, b1s, w1ls, tt + dt, true, 0, 0, 0, 0, 0, 0, 0.f); __syncthreads();
            gemm16<0>(g_W2F, a1p, a2p, b2s, 0, 0.f, false, 0, 0, 0, 0, 0, 0, 0.f); __syncthreads();
            gemm16<4>(g_W3F, a2p, 0, 0, 0, 0.f, false, hT, hTp, yT, yTp, ka, b3s, dt); __syncthreads();
            tt += dt;
        }
    }
}

extern "C" void kernel_launch(void* const* d_in, const int* in_sizes, int n_in,
                              void* d_out, int out_size) {
    const float* x    = (const float*)d_in[0];
    const float* t    = (const float*)d_in[1];
    const float* mask = (const float*)d_in[2];
    const float* W_ih = (const float*)d_in[3];
    const float* W_hh = (const float*)d_in[4];
    const float* b_ih = (const float*)d_in[5];
    const float* b_hh = (const float*)d_in[6];
    const float* W1   = (const float*)d_in[7];
    const float* b1   = (const float*)d_in[8];
    const float* W2   = (const float*)d_in[9];
    const float* b2   = (const float*)d_in[10];
    const float* W3   = (const float*)d_in[11];
    const float* b3   = (const float*)d_in[12];
    float* out = (float*)d_out;

    prep_kernel<<<256, 256>>>(W_ih, W_hh, W1, W2, W3);

    const int smem_bytes = 38144 * sizeof(float);  // 152576
    cudaFuncSetAttribute(odernn_kernel,
                         cudaFuncAttributeMaxDynamicSharedMemorySize, smem_bytes);
    odernn_kernel<<<NCTA, NT, smem_bytes>>>(x, t, mask, b_ih, b_hh,
                                            b1, b2, b3, out);
}

// round 9
// speedup vs baseline: 1.6259x; 1.6259x over previous
#include <cuda_runtime.h>
#include <math.h>

// ODE-RNN persistent kernel, round 9 (base = round 6 micro-structure):
//  - MB=8 rows/CTA, grid=128 CTAs -> 128/148 SMs active (was 64).
//  - MLP inner loop per kt: 1 LDG.128 (A-frag) + 2 LDS.32 (B, stride-8
//    conflict-free) + 2 CVT + 1 MMA (m16n8k8 tf32; batch m == n8 exactly).
//  - GRU exact fp32 FFMA2, activations [k][8].

#define NT 512
#define MBR 8
#define NCTA 128
#define T_LEN 200

typedef unsigned long long ull;

__device__ float g_WihT[16 * 768 * 4];
__device__ float g_WhhT[64 * 768 * 4];
// MLP tf32 fragment-packed weights: [nt(16)][kt(32)][lane(32)][a0..a3]
__device__ unsigned g_W1F[16 * 32 * 32 * 4];
__device__ unsigned g_W2F[16 * 32 * 32 * 4];
__device__ unsigned g_W3F[16 * 32 * 32 * 4];
__device__ float g_W1last[256];

__device__ __forceinline__ unsigned tf32r(float f) {
    unsigned u;
    asm("cvt.rna.tf32.f32 %0, %1;" : "=r"(u) : "f"(f));
    return u;
}

__global__ void prep_kernel(const float* __restrict__ W_ih,
                            const float* __restrict__ W_hh,
                            const float* __restrict__ W1,
                            const float* __restrict__ W2,
                            const float* __restrict__ W3) {
    int idx = blockIdx.x * blockDim.x + threadIdx.x;
    int stride = gridDim.x * blockDim.x;
    for (int t = idx; t < 16 * 768 * 4; t += stride) {
        int j = t & 3, nk = t >> 2;
        int n = nk % 768, k4 = nk / 768;
        g_WihT[t] = W_ih[n * 64 + k4 * 4 + j];
    }
    for (int t = idx; t < 64 * 768 * 4; t += stride) {
        int j = t & 3, nk = t >> 2;
        int n = nk % 768, k4 = nk / 768;
        g_WhhT[t] = W_hh[n * 256 + k4 * 4 + j];
    }
    for (int tI = idx; tI < 16 * 32 * 32; tI += stride) {
        int l = tI & 31, kt = (tI >> 5) & 31, nt = tI >> 10;
        int gid = l >> 2, tig = l & 3;
        int r0 = nt * 16 + gid, r1 = r0 + 8;
        int c0 = kt * 8 + tig, c1 = c0 + 4;
        g_W1F[tI * 4 + 0] = tf32r(W1[r0 * 257 + c0]);
        g_W1F[tI * 4 + 1] = tf32r(W1[r1 * 257 + c0]);
        g_W1F[tI * 4 + 2] = tf32r(W1[r0 * 257 + c1]);
        g_W1F[tI * 4 + 3] = tf32r(W1[r1 * 257 + c1]);
        g_W2F[tI * 4 + 0] = tf32r(W2[r0 * 256 + c0]);
        g_W2F[tI * 4 + 1] = tf32r(W2[r1 * 256 + c0]);
        g_W2F[tI * 4 + 2] = tf32r(W2[r0 * 256 + c1]);
        g_W2F[tI * 4 + 3] = tf32r(W2[r1 * 256 + c1]);
        g_W3F[tI * 4 + 0] = tf32r(W3[r0 * 256 + c0]);
        g_W3F[tI * 4 + 1] = tf32r(W3[r1 * 256 + c0]);
        g_W3F[tI * 4 + 2] = tf32r(W3[r0 * 256 + c1]);
        g_W3F[tI * 4 + 3] = tf32r(W3[r1 * 256 + c1]);
    }
    for (int n = idx; n < 256; n += stride) g_W1last[n] = W1[n * 257 + 256];
}

__device__ __forceinline__ float sigm(float v) {
    return 1.0f / (1.0f + __expf(-v));
}
__device__ __forceinline__ float tanha(float v) {
    float r;
    asm("tanh.approx.f32 %0, %1;" : "=f"(r) : "f"(v));
    return r;
}
__device__ __forceinline__ ull pk2(float a, float b) {
    ull r;
    asm("mov.b64 %0, {%1, %2};" : "=l"(r) : "f"(a), "f"(b));
    return r;
}
__device__ __forceinline__ ull ffma2(ull a, ull b, ull c) {
    ull d;
    asm("fma.rn.f32x2 %0, %1, %2, %3;" : "=l"(d) : "l"(a), "l"(b), "l"(c));
    return d;
}

#define MMA_TF32(c0, c1, c2, c3, A0, A1, A2, A3, B0, B1)                      \
    asm volatile(                                                             \
        "mma.sync.aligned.m16n8k8.row.col.f32.tf32.tf32.f32 "                 \
        "{%0,%1,%2,%3}, {%4,%5,%6,%7}, {%8,%9}, {%0,%1,%2,%3};"               \
        : "+f"(c0), "+f"(c1), "+f"(c2), "+f"(c3)                              \
        : "r"(A0), "r"(A1), "r"(A2), "r"(A3), "r"(B0), "r"(B1))

// One MLP GEMM: D[256][8] = W @ xs. Warp w owns n-rows [16w,16w+16), full K.
// xs layout [k][8] (fp32). EPI 0: bias(+tt*w1l)+tanh -> dst.
// EPI 1..4: RK4 stage update fused.
template<int EPI>
__device__ __forceinline__ void gemm8(const unsigned* __restrict__ WF,
                                      const float* __restrict__ xs,
                                      float* __restrict__ dst,
                                      const float* __restrict__ bias,
                                      const float* __restrict__ w1l,
                                      float tt, bool tcol,
                                      float* __restrict__ hT,
                                      float* __restrict__ yT,
                                      float* __restrict__ ka,
                                      const float* __restrict__ b3s,
                                      float dt) {
    const int warp = threadIdx.x >> 5;
    const int lane = threadIdx.x & 31;
    const int gid = lane >> 2, tig = lane & 3;
    float c0 = 0.f, c1 = 0.f, c2 = 0.f, c3 = 0.f;
    const float4* __restrict__ wp =
        reinterpret_cast<const float4*>(WF) + (warp * 32 * 32 + lane);
    const float* __restrict__ bq = xs + tig * 8 + gid;
#pragma unroll 4
    for (int kt = 0; kt < 32; ++kt) {
        float4 af = wp[kt * 32];
        unsigned A0 = __float_as_uint(af.x), A1 = __float_as_uint(af.y);
        unsigned A2 = __float_as_uint(af.z), A3 = __float_as_uint(af.w);
        unsigned B0 = tf32r(bq[kt * 64]);        // k = kt*8+tig,   m = gid
        unsigned B1 = tf32r(bq[kt * 64 + 32]);   // k = kt*8+tig+4, m = gid
        MMA_TF32(c0, c1, c2, c3, A0, A1, A2, A3, B0, B1);
    }
    const int r0 = warp * 16 + gid, r1 = r0 + 8;
    const int mc = 2 * tig;
    if (EPI == 0) {
        float bb0 = bias[r0], bb1 = bias[r1];
        if (tcol) { bb0 += tt * w1l[r0]; bb1 += tt * w1l[r1]; }
        *reinterpret_cast<float2*>(&dst[r0 * 8 + mc]) =
            make_float2(tanha(bb0 + c0), tanha(bb0 + c1));
        *reinterpret_cast<float2*>(&dst[r1 * 8 + mc]) =
            make_float2(tanha(bb1 + c2), tanha(bb1 + c3));
    } else {
        float b0 = b3s[r0], b1 = b3s[r1];
        float f0 = b0 + c0, f1 = b0 + c1;   // r0: mc, mc+1
        float f2 = b1 + c2, f3 = b1 + c3;   // r1: mc, mc+1
        float2 h0 = *reinterpret_cast<float2*>(&hT[r0 * 8 + mc]);
        float2 h1 = *reinterpret_cast<float2*>(&hT[r1 * 8 + mc]);
        if (EPI == 1) {
            *reinterpret_cast<float2*>(&ka[r0 * 8 + mc]) = make_float2(f0, f1);
            *reinterpret_cast<float2*>(&ka[r1 * 8 + mc]) = make_float2(f2, f3);
            float c = 0.5f * dt;
            *reinterpret_cast<float2*>(&yT[r0 * 8 + mc]) =
                make_float2(h0.x + c * f0, h0.y + c * f1);
            *reinterpret_cast<float2*>(&yT[r1 * 8 + mc]) =
                make_float2(h1.x + c * f2, h1.y + c * f3);
        } else if (EPI == 2 || EPI == 3) {
            float2 k0 = *reinterpret_cast<float2*>(&ka[r0 * 8 + mc]);
            float2 k1 = *reinterpret_cast<float2*>(&ka[r1 * 8 + mc]);
            *reinterpret_cast<float2*>(&ka[r0 * 8 + mc]) =
                make_float2(k0.x + 2.f * f0, k0.y + 2.f * f1);
            *reinterpret_cast<float2*>(&ka[r1 * 8 + mc]) =
                make_float2(k1.x + 2.f * f2, k1.y + 2.f * f3);
            float c = (EPI == 2) ? 0.5f * dt : dt;
            *reinterpret_cast<float2*>(&yT[r0 * 8 + mc]) =
                make_float2(h0.x + c * f0, h0.y + c * f1);
            *reinterpret_cast<float2*>(&yT[r1 * 8 + mc]) =
                make_float2(h1.x + c * f2, h1.y + c * f3);
        } else {  // EPI == 4
            float2 k0 = *reinterpret_cast<float2*>(&ka[r0 * 8 + mc]);
            float2 k1 = *reinterpret_cast<float2*>(&ka[r1 * 8 + mc]);
            float c = dt * (1.0f / 6.0f);
            *reinterpret_cast<float2*>(&hT[r0 * 8 + mc]) =
                make_float2(h0.x + c * (k0.x + f0), h0.y + c * (k0.y + f1));
            *reinterpret_cast<float2*>(&hT[r1 * 8 + mc]) =
                make_float2(h1.x + c * (k1.x + f2), h1.y + c * (k1.y + f3));
        }
    }
}

// GRU GEMM, fp32 FFMA2. 512 threads: n = tid&255 (+256 strides), mh = tid>>8
// handles m 0-3 / 4-7. xs layout [k][8].
template<int K>
__device__ __forceinline__ void gru_mm(const float* __restrict__ WT4,
                                       const float* __restrict__ bias,
                                       const float* __restrict__ xs,
                                       float* __restrict__ ys, int N) {
    const int n0 = threadIdx.x & 255;
    const int mh = threadIdx.x >> 8;
    const float* __restrict__ xb = xs + mh * 4;
    for (int n = n0; n < N; n += 256) {
        float a0 = bias[n];
        ull acc0 = 0ULL, acc1 = 0ULL;
        const float4* __restrict__ wp = reinterpret_cast<const float4*>(WT4) + n;
#pragma unroll 4
        for (int k4 = 0; k4 < K / 4; ++k4) {
            float4 w = wp[(size_t)k4 * N];
            const float* __restrict__ xr = xb + (k4 * 4) * 8;
#pragma unroll
            for (int kk = 0; kk < 4; ++kk) {
                float wv = (kk == 0 ? w.x : kk == 1 ? w.y : kk == 2 ? w.z : w.w);
                ull wd = pk2(wv, wv);
                float4 xa = *reinterpret_cast<const float4*>(xr + kk * 8);
                acc0 = ffma2(wd, pk2(xa.x, xa.y), acc0);
                acc1 = ffma2(wd, pk2(xa.z, xa.w), acc1);
            }
        }
        float2 p0 = *reinterpret_cast<float2*>(&acc0);
        float2 p1 = *reinterpret_cast<float2*>(&acc1);
        *reinterpret_cast<float4*>(ys + n * 8 + mh * 4) =
            make_float4(a0 + p0.x, a0 + p0.y, a0 + p1.x, a0 + p1.y);
    }
}

__global__ void __launch_bounds__(NT, 1)
odernn_kernel(const float* __restrict__ x,
              const float* __restrict__ t,
              const float* __restrict__ mask,
              const float* __restrict__ b_ih,
              const float* __restrict__ b_hh,
              const float* __restrict__ b1,
              const float* __restrict__ b2,
              const float* __restrict__ b3,
              float* __restrict__ out) {
    extern __shared__ float sm[];
    float* xT  = sm;               // 64*8  = 512
    float* hT  = sm + 512;         // 256*8 = 2048
    float* U   = sm + 2560;        // union: 12288 floats
    float* gi  = U;                // 768*8 = 6144 (GRU phase)
    float* gh  = U + 6144;         // 6144
    float* yT  = U;                // 2048 (RK4 phase)
    float* a1  = U + 2048;         // 2048
    float* a2  = U + 4096;         // 2048
    float* ka  = U + 6144;         // 2048
    float* bihs = sm + 14848;      // 768
    float* bhhs = bihs + 768;      // 768
    float* b1s  = bhhs + 768;      // 256
    float* b2s  = b1s + 256;       // 256
    float* b3s  = b2s + 256;       // 256
    float* w1ls = b3s + 256;       // 256
    // total 17408 floats = 69632 bytes

    const int tid = threadIdx.x;
    const int m0 = blockIdx.x * MBR;

    for (int idx = tid; idx < 768; idx += NT) { bihs[idx] = b_ih[idx]; bhhs[idx] = b_hh[idx]; }
    for (int idx = tid; idx < 256; idx += NT) {
        b1s[idx] = b1[idx]; b2s[idx] = b2[idx]; b3s[idx] = b3[idx];
        w1ls[idx] = g_W1last[idx];
    }
    for (int idx = tid; idx < 256 * 8; idx += NT) hT[idx] = 0.0f;
    __syncthreads();

    for (int i = 0; i < T_LEN; ++i) {
        for (int idx = tid; idx < 64 * MBR; idx += NT) {
            int k = idx >> 3, m = idx & 7;
            xT[k * 8 + m] = x[((size_t)(m0 + m) * T_LEN + i) * 64 + k];
        }
        __syncthreads();

        gru_mm<64>(g_WihT, bihs, xT, gi, 768);
        gru_mm<256>(g_WhhT, bhhs, hT, gh, 768);
        __syncthreads();

        // gate pointwise: m = tid&7, n = (tid>>3) + 64j
        {
            const int pm = tid & 7;
            const int pn0 = tid >> 3;
#pragma unroll
            for (int j = 0; j < 4; ++j) {
                int n = pn0 + j * 64;
                float ir = gi[n * 8 + pm];
                float iz = gi[(256 + n) * 8 + pm];
                float in_ = gi[(512 + n) * 8 + pm];
                float hr = gh[n * 8 + pm];
                float hz = gh[(256 + n) * 8 + pm];
                float hn = gh[(512 + n) * 8 + pm];
                float h = hT[n * 8 + pm];
                float r = sigm(ir + hr);
                float z = sigm(iz + hz);
                float nn = tanhf(in_ + r * hn);
                float hnew = (1.0f - z) * nn + z * h;
                float mk = mask[(size_t)(m0 + pm) * T_LEN + i];
                float hobs = mk * hnew + (1.0f - mk) * h;
                hT[n * 8 + pm] = hobs;
                out[((size_t)(m0 + pm) * T_LEN + i) * 256 + n] = hobs;
            }
        }
        __syncthreads();

        if (i == T_LEN - 1) break;

        float t0v = t[i], t1v = t[i + 1];
        float dt = (t1v - t0v) * 0.25f;
        float tt = t0v;
        for (int sub = 0; sub < 4; ++sub) {
            // stage 1: f(tt, h)
            gemm8<0>(g_W1F, hT, a1, b1s, w1ls, tt, true, 0, 0, 0, 0, 0.f); __syncthreads();
            gemm8<0>(g_W2F, a1, a2, b2s, 0, 0.f, false, 0, 0, 0, 0, 0.f); __syncthreads();
            gemm8<1>(g_W3F, a2, 0, 0, 0, 0.f, false, hT, yT, ka, b3s, dt); __syncthreads();
            // stage 2: f(tt+dt/2, y)
            gemm8<0>(g_W1F, yT, a1, b1s, w1ls, tt + 0.5f * dt, true, 0, 0, 0, 0, 0.f); __syncthreads();
            gemm8<0>(g_W2F, a1, a2, b2s, 0, 0.f, false, 0, 0, 0, 0, 0.f); __syncthreads();
            gemm8<2>(g_W3F, a2, 0, 0, 0, 0.f, false, hT, yT, ka, b3s, dt); __syncthreads();
            // stage 3: f(tt+dt/2, y)
            gemm8<0>(g_W1F, yT, a1, b1s, w1ls, tt + 0.5f * dt, true, 0, 0, 0, 0, 0.f); __syncthreads();
            gemm8<0>(g_W2F, a1, a2, b2s, 0, 0.f, false, 0, 0, 0, 0, 0.f); __syncthreads();
            gemm8<3>(g_W3F, a2, 0, 0, 0, 0.f, false, hT, yT, ka, b3s, dt); __syncthreads();
            // stage 4: f(tt+dt, y)
            gemm8<0>(g_W1F, yT, a1, b1s, w1ls, tt + dt, true, 0, 0, 0, 0, 0.f); __syncthreads();
            gemm8<0>(g_W2F, a1, a2, b2s, 0, 0.f, false, 0, 0, 0, 0, 0.f); __syncthreads();
            gemm8<4>(g_W3F, a2, 0, 0, 0, 0.f, false, hT, yT, ka, b3s, dt); __syncthreads();
            tt += dt;
        }
    }
}

extern "C" void kernel_launch(void* const* d_in, const int* in_sizes, int n_in,
                              void* d_out, int out_size) {
    const float* x    = (const float*)d_in[0];
    const float* t    = (const float*)d_in[1];
    const float* mask = (const float*)d_in[2];
    const float* W_ih = (const float*)d_in[3];
    const float* W_hh = (const float*)d_in[4];
    const float* b_ih = (const float*)d_in[5];
    const float* b_hh = (const float*)d_in[6];
    const float* W1   = (const float*)d_in[7];
    const float* b1   = (const float*)d_in[8];
    const float* W2   = (const float*)d_in[9];
    const float* b2   = (const float*)d_in[10];
    const float* W3   = (const float*)d_in[11];
    const float* b3   = (const float*)d_in[12];
    float* out = (float*)d_out;

    prep_kernel<<<256, 256>>>(W_ih, W_hh, W1, W2, W3);

    const int smem_bytes = 17408 * sizeof(float);  // 69632
    cudaFuncSetAttribute(odernn_kernel,
                         cudaFuncAttributeMaxDynamicSharedMemorySize, smem_bytes);
    odernn_kernel<<<NCTA, NT, smem_bytes>>>(x, t, mask, b_ih, b_hh,
                                            b1, b2, b3, out);
}

// round 10
// speedup vs baseline: 2.4885x; 1.5306x over previous
#include <cuda_runtime.h>
#include <cuda_fp16.h>
#include <math.h>

// ODE-RNN persistent kernel, round 10 (base = round 9, 26.7ms):
//  - MLP weights/activations in fp16 (same 11-bit mantissa as tf32, fp32
//    accumulate): mma.m16n8k16 halves both weight bytes (L1-bound stream)
//    and inner-loop length (16 kt vs 32).
//  - Activation k-index permutation sigma (per 16-block: physical 2q+h <->
//    logical q+8h) lets epilogue threads (owning rows r, r+8) write whole
//    half2 words; inverse baked into pre-packed weight columns.
//  - GRU exact fp32 FFMA2 unchanged. Grid 128 CTAs x 512 thr, MB=8.

#define NT 512
#define MBR 8
#define NCTA 128
#define T_LEN 200

typedef unsigned long long ull;

__device__ float g_WihT[16 * 768 * 4];
__device__ float g_WhhT[64 * 768 * 4];
// MLP fp16 fragment-packed weights: [nt(16)][kt(16)][lane(32)][a0..a3 (u32=half2)]
__device__ unsigned g_W1F[16 * 16 * 32 * 4];
__device__ unsigned g_W2F[16 * 16 * 32 * 4];
__device__ unsigned g_W3F[16 * 16 * 32 * 4];
__device__ float g_W1last[256];

// logical column for physical k-index (sigma^-1), per 16-block
__device__ __forceinline__ int permL(int c) {
    return (c & ~15) + ((c & 15) >> 1) + ((c & 1) << 3);
}
__device__ __forceinline__ unsigned h2pack(float a, float b) {
    __half2 h = __floats2half2_rn(a, b);
    return *reinterpret_cast<unsigned*>(&h);
}

__global__ void prep_kernel(const float* __restrict__ W_ih,
                            const float* __restrict__ W_hh,
                            const float* __restrict__ W1,
                            const float* __restrict__ W2,
                            const float* __restrict__ W3) {
    int idx = blockIdx.x * blockDim.x + threadIdx.x;
    int stride = gridDim.x * blockDim.x;
    for (int t = idx; t < 16 * 768 * 4; t += stride) {
        int j = t & 3, nk = t >> 2;
        int n = nk % 768, k4 = nk / 768;
        g_WihT[t] = W_ih[n * 64 + k4 * 4 + j];
    }
    for (int t = idx; t < 64 * 768 * 4; t += stride) {
        int j = t & 3, nk = t >> 2;
        int n = nk % 768, k4 = nk / 768;
        g_WhhT[t] = W_hh[n * 256 + k4 * 4 + j];
    }
    // fp16 fragment packs for m16n8k16 (A row-major), physical cols c with
    // logical source permL(c):
    //  a0=(W[r0][L(c0)],W[r0][L(c0+1)])  a1=(r1, same cols)
    //  a2=(W[r0][L(c0+8)],W[r0][L(c0+9)]) a3=(r1, same cols)
    for (int tI = idx; tI < 16 * 16 * 32; tI += stride) {
        int l = tI & 31, kt = (tI >> 5) & 15, nt = tI >> 9;
        int gid = l >> 2, tig = l & 3;
        int r0 = nt * 16 + gid, r1 = r0 + 8;
        int c0 = kt * 16 + 2 * tig;
        int la = permL(c0), lb = permL(c0 + 1), lc = permL(c0 + 8), ld = permL(c0 + 9);
        g_W1F[tI * 4 + 0] = h2pack(W1[r0 * 257 + la], W1[r0 * 257 + lb]);
        g_W1F[tI * 4 + 1] = h2pack(W1[r1 * 257 + la], W1[r1 * 257 + lb]);
        g_W1F[tI * 4 + 2] = h2pack(W1[r0 * 257 + lc], W1[r0 * 257 + ld]);
        g_W1F[tI * 4 + 3] = h2pack(W1[r1 * 257 + lc], W1[r1 * 257 + ld]);
        g_W2F[tI * 4 + 0] = h2pack(W2[r0 * 256 + la], W2[r0 * 256 + lb]);
        g_W2F[tI * 4 + 1] = h2pack(W2[r1 * 256 + la], W2[r1 * 256 + lb]);
        g_W2F[tI * 4 + 2] = h2pack(W2[r0 * 256 + lc], W2[r0 * 256 + ld]);
        g_W2F[tI * 4 + 3] = h2pack(W2[r1 * 256 + lc], W2[r1 * 256 + ld]);
        g_W3F[tI * 4 + 0] = h2pack(W3[r0 * 256 + la], W3[r0 * 256 + lb]);
        g_W3F[tI * 4 + 1] = h2pack(W3[r1 * 256 + la], W3[r1 * 256 + lb]);
        g_W3F[tI * 4 + 2] = h2pack(W3[r0 * 256 + lc], W3[r0 * 256 + ld]);
        g_W3F[tI * 4 + 3] = h2pack(W3[r1 * 256 + lc], W3[r1 * 256 + ld]);
    }
    for (int n = idx; n < 256; n += stride) g_W1last[n] = W1[n * 257 + 256];
}

__device__ __forceinline__ float sigm(float v) {
    return 1.0f / (1.0f + __expf(-v));
}
__device__ __forceinline__ float tanha(float v) {
    float r;
    asm("tanh.approx.f32 %0, %1;" : "=f"(r) : "f"(v));
    return r;
}
__device__ __forceinline__ ull pk2(float a, float b) {
    ull r;
    asm("mov.b64 %0, {%1, %2};" : "=l"(r) : "f"(a), "f"(b));
    return r;
}
__device__ __forceinline__ ull ffma2(ull a, ull b, ull c) {
    ull d;
    asm("fma.rn.f32x2 %0, %1, %2, %3;" : "=l"(d) : "l"(a), "l"(b), "l"(c));
    return d;
}

#define MMA_F16(c0, c1, c2, c3, A0, A1, A2, A3, B0, B1)                       \
    asm volatile(                                                             \
        "mma.sync.aligned.m16n8k16.row.col.f32.f16.f16.f32 "                  \
        "{%0,%1,%2,%3}, {%4,%5,%6,%7}, {%8,%9}, {%0,%1,%2,%3};"               \
        : "+f"(c0), "+f"(c1), "+f"(c2), "+f"(c3)                              \
        : "r"(A0), "r"(A1), "r"(A2), "r"(A3), "r"(B0), "r"(B1))

// One MLP GEMM: D[256][8] = W @ B. Warp w owns n-rows [16w,16w+16), full K.
// Bp: half2 words, word (p2*8+m) = (act[physical 2*p2][m], act[2*p2+1][m]).
// EPI 0: bias(+tt*w1l)+tanh -> dstp (half2). EPI 1..4: RK4 stage fused,
// fp32 state + half2 mirror.
template<int EPI>
__device__ __forceinline__ void gemm8(const unsigned* __restrict__ WF,
                                      const unsigned* __restrict__ Bp,
                                      unsigned* __restrict__ dstp,
                                      const float* __restrict__ bias,
                                      const float* __restrict__ w1l,
                                      float tt, bool tcol,
                                      float* __restrict__ hT,
                                      unsigned* __restrict__ hTp,
                                      float* __restrict__ yT,
                                      unsigned* __restrict__ yTp,
                                      float* __restrict__ ka,
                                      const float* __restrict__ b3s,
                                      float dt) {
    const int warp = threadIdx.x >> 5;
    const int lane = threadIdx.x & 31;
    const int gid = lane >> 2, tig = lane & 3;
    float c0 = 0.f, c1 = 0.f, c2 = 0.f, c3 = 0.f;
    const float4* __restrict__ wp =
        reinterpret_cast<const float4*>(WF) + (warp * 16 * 32 + lane);
    const unsigned* __restrict__ bq = Bp + tig * 8 + gid;
#pragma unroll 4
    for (int kt = 0; kt < 16; ++kt) {
        float4 af = wp[kt * 32];
        unsigned A0 = __float_as_uint(af.x), A1 = __float_as_uint(af.y);
        unsigned A2 = __float_as_uint(af.z), A3 = __float_as_uint(af.w);
        unsigned B0 = bq[kt * 64];        // phys k pair (kt*16+2tig, +1), m=gid
        unsigned B1 = bq[kt * 64 + 32];   // phys k pair (kt*16+2tig+8, +9)
        MMA_F16(c0, c1, c2, c3, A0, A1, A2, A3, B0, B1);
    }
    const int r0 = warp * 16 + gid, r1 = r0 + 8;
    const int mc = 2 * tig;
    const int wB = (warp * 8 + gid) * 8;  // half2 word base for rows (r0,r1)
    if (EPI == 0) {
        float bb0 = bias[r0], bb1 = bias[r1];
        if (tcol) { bb0 += tt * w1l[r0]; bb1 += tt * w1l[r1]; }
        dstp[wB + mc]     = h2pack(tanha(bb0 + c0), tanha(bb1 + c2));
        dstp[wB + mc + 1] = h2pack(tanha(bb0 + c1), tanha(bb1 + c3));
    } else {
        float b0 = b3s[r0], b1 = b3s[r1];
        float f0 = b0 + c0, f1 = b0 + c1;   // r0: mc, mc+1
        float f2 = b1 + c2, f3 = b1 + c3;   // r1: mc, mc+1
        float2 h0 = *reinterpret_cast<float2*>(&hT[r0 * 8 + mc]);
        float2 h1 = *reinterpret_cast<float2*>(&hT[r1 * 8 + mc]);
        if (EPI == 1) {
            *reinterpret_cast<float2*>(&ka[r0 * 8 + mc]) = make_float2(f0, f1);
            *reinterpret_cast<float2*>(&ka[r1 * 8 + mc]) = make_float2(f2, f3);
            float c = 0.5f * dt;
            float y0 = h0.x + c * f0, y1 = h0.y + c * f1;
            float y2 = h1.x + c * f2, y3 = h1.y + c * f3;
            *reinterpret_cast<float2*>(&yT[r0 * 8 + mc]) = make_float2(y0, y1);
            *reinterpret_cast<float2*>(&yT[r1 * 8 + mc]) = make_float2(y2, y3);
            yTp[wB + mc]     = h2pack(y0, y2);
            yTp[wB + mc + 1] = h2pack(y1, y3);
        } else if (EPI == 2 || EPI == 3) {
            float2 k0 = *reinterpret_cast<float2*>(&ka[r0 * 8 + mc]);
            float2 k1 = *reinterpret_cast<float2*>(&ka[r1 * 8 + mc]);
            *reinterpret_cast<float2*>(&ka[r0 * 8 + mc]) =
                make_float2(k0.x + 2.f * f0, k0.y + 2.f * f1);
            *reinterpret_cast<float2*>(&ka[r1 * 8 + mc]) =
                make_float2(k1.x + 2.f * f2, k1.y + 2.f * f3);
            float c = (EPI == 2) ? 0.5f * dt : dt;
            float y0 = h0.x + c * f0, y1 = h0.y + c * f1;
            float y2 = h1.x + c * f2, y3 = h1.y + c * f3;
            *reinterpret_cast<float2*>(&yT[r0 * 8 + mc]) = make_float2(y0, y1);
            *reinterpret_cast<float2*>(&yT[r1 * 8 + mc]) = make_float2(y2, y3);
            yTp[wB + mc]     = h2pack(y0, y2);
            yTp[wB + mc + 1] = h2pack(y1, y3);
        } else {  // EPI == 4
            float2 k0 = *reinterpret_cast<float2*>(&ka[r0 * 8 + mc]);
            float2 k1 = *reinterpret_cast<float2*>(&ka[r1 * 8 + mc]);
            float c = dt * (1.0f / 6.0f);
            float n0 = h0.x + c * (k0.x + f0), n1 = h0.y + c * (k0.y + f1);
            float n2 = h1.x + c * (k1.x + f2), n3 = h1.y + c * (k1.y + f3);
            *reinterpret_cast<float2*>(&hT[r0 * 8 + mc]) = make_float2(n0, n1);
            *reinterpret_cast<float2*>(&hT[r1 * 8 + mc]) = make_float2(n2, n3);
            hTp[wB + mc]     = h2pack(n0, n2);
            hTp[wB + mc + 1] = h2pack(n1, n3);
        }
    }
}

// GRU GEMM, fp32 FFMA2, xs layout [k][8].
template<int K>
__device__ __forceinline__ void gru_mm(const float* __restrict__ WT4,
                                       const float* __restrict__ bias,
                                       const float* __restrict__ xs,
                                       float* __restrict__ ys, int N) {
    const int n0 = threadIdx.x & 255;
    const int mh = threadIdx.x >> 8;
    const float* __restrict__ xb = xs + mh * 4;
    for (int n = n0; n < N; n += 256) {
        float a0 = bias[n];
        ull acc0 = 0ULL, acc1 = 0ULL;
        const float4* __restrict__ wp = reinterpret_cast<const float4*>(WT4) + n;
#pragma unroll 4
        for (int k4 = 0; k4 < K / 4; ++k4) {
            float4 w = wp[(size_t)k4 * N];
            const float* __restrict__ xr = xb + (k4 * 4) * 8;
#pragma unroll
            for (int kk = 0; kk < 4; ++kk) {
                float wv = (kk == 0 ? w.x : kk == 1 ? w.y : kk == 2 ? w.z : w.w);
                ull wd = pk2(wv, wv);
                float4 xa = *reinterpret_cast<const float4*>(xr + kk * 8);
                acc0 = ffma2(wd, pk2(xa.x, xa.y), acc0);
                acc1 = ffma2(wd, pk2(xa.z, xa.w), acc1);
            }
        }
        float2 p0 = *reinterpret_cast<float2*>(&acc0);
        float2 p1 = *reinterpret_cast<float2*>(&acc1);
        *reinterpret_cast<float4*>(ys + n * 8 + mh * 4) =
            make_float4(a0 + p0.x, a0 + p0.y, a0 + p1.x, a0 + p1.y);
    }
}

__global__ void __launch_bounds__(NT, 1)
odernn_kernel(const float* __restrict__ x,
              const float* __restrict__ t,
              const float* __restrict__ mask,
              const float* __restrict__ b_ih,
              const float* __restrict__ b_hh,
              const float* __restrict__ b1,
              const float* __restrict__ b2,
              const float* __restrict__ b3,
              float* __restrict__ out) {
    extern __shared__ float sm[];
    float* xT  = sm;                 // 64*8  = 512
    float* hT  = sm + 512;           // 256*8 = 2048
    unsigned* hTp = reinterpret_cast<unsigned*>(sm + 2560);  // 128*8 = 1024
    float* U   = sm + 3584;          // union: 12288 floats
    float* gi  = U;                  // 6144 (GRU phase)
    float* gh  = U + 6144;           // 6144
    float* yT  = U;                  // 2048 (RK4 phase)
    float* ka  = U + 2048;           // 2048
    unsigned* a1p = reinterpret_cast<unsigned*>(U + 4096);   // 1024
    unsigned* a2p = reinterpret_cast<unsigned*>(U + 5120);   // 1024
    unsigned* yTp = reinterpret_cast<unsigned*>(U + 6144);   // 1024
    float* bihs = sm + 15872;        // 768
    float* bhhs = bihs + 768;        // 768
    float* b1s  = bhhs + 768;        // 256
    float* b2s  = b1s + 256;         // 256
    float* b3s  = b2s + 256;         // 256
    float* w1ls = b3s + 256;         // 256
    // total 18432 floats = 73728 bytes

    const int tid = threadIdx.x;
    const int m0 = blockIdx.x * MBR;

    for (int idx = tid; idx < 768; idx += NT) { bihs[idx] = b_ih[idx]; bhhs[idx] = b_hh[idx]; }
    for (int idx = tid; idx < 256; idx += NT) {
        b1s[idx] = b1[idx]; b2s[idx] = b2[idx]; b3s[idx] = b3[idx];
        w1ls[idx] = g_W1last[idx];
    }
    for (int idx = tid; idx < 256 * 8; idx += NT) hT[idx] = 0.0f;
    for (int idx = tid; idx < 128 * 8; idx += NT) hTp[idx] = 0u;
    __syncthreads();

    for (int i = 0; i < T_LEN; ++i) {
        for (int idx = tid; idx < 64 * MBR; idx += NT) {
            int k = idx >> 3, m = idx & 7;
            xT[k * 8 + m] = x[((size_t)(m0 + m) * T_LEN + i) * 64 + k];
        }
        __syncthreads();

        gru_mm<64>(g_WihT, bihs, xT, gi, 768);
        gru_mm<256>(g_WhhT, bhhs, hT, gh, 768);
        __syncthreads();

        // gate pointwise on row pairs (n, n+8) so hTp half2 words are whole:
        // pm = tid&7, pid = tid>>3: q = pid&7, blk = (pid>>3) + 8j
        {
            const int pm = tid & 7;
            const int pid = tid >> 3;
            const int q = pid & 7;
            const int bblk = pid >> 3;
            const float mk = mask[(size_t)(m0 + pm) * T_LEN + i];
#pragma unroll
            for (int j = 0; j < 2; ++j) {
                int blk = bblk + 8 * j;
                float hobs2[2];
#pragma unroll
                for (int hh = 0; hh < 2; ++hh) {
                    int n = blk * 16 + q + 8 * hh;
                    float ir = gi[n * 8 + pm];
                    float iz = gi[(256 + n) * 8 + pm];
                    float in_ = gi[(512 + n) * 8 + pm];
                    float hr = gh[n * 8 + pm];
                    float hz = gh[(256 + n) * 8 + pm];
                    float hn = gh[(512 + n) * 8 + pm];
                    float h = hT[n * 8 + pm];
                    float r = sigm(ir + hr);
                    float z = sigm(iz + hz);
                    float nn = tanhf(in_ + r * hn);
                    float hnew = (1.0f - z) * nn + z * h;
                    float hobs = mk * hnew + (1.0f - mk) * h;
                    hT[n * 8 + pm] = hobs;
                    out[((size_t)(m0 + pm) * T_LEN + i) * 256 + n] = hobs;
                    hobs2[hh] = hobs;
                }
                hTp[(blk * 8 + q) * 8 + pm] = h2pack(hobs2[0], hobs2[1]);
            }
        }
        __syncthreads();

        if (i == T_LEN - 1) break;

        float t0v = t[i], t1v = t[i + 1];
        float dt = (t1v - t0v) * 0.25f;
        float tt = t0v;
        for (int sub = 0; sub < 4; ++sub) {
            // stage 1: f(tt, h)
            gemm8<0>(g_W1F, hTp, a1p, b1s, w1ls, tt, true, 0, 0, 0, 0, 0, 0, 0.f); __syncthreads();
            gemm8<0>(g_W2F, a1p, a2p, b2s, 0, 0.f, false, 0, 0, 0, 0, 0, 0, 0.f); __syncthreads();
            gemm8<1>(g_W3F, a2p, 0, 0, 0, 0.f, false, hT, hTp, yT, yTp, ka, b3s, dt); __syncthreads();
            // stage 2: f(tt+dt/2, y)
            gemm8<0>(g_W1F, yTp, a1p, b1s, w1ls, tt + 0.5f * dt, true, 0, 0, 0, 0, 0, 0, 0.f); __syncthreads();
            gemm8<0>(g_W2F, a1p, a2p, b2s, 0, 0.f, false, 0, 0, 0, 0, 0, 0, 0.f); __syncthreads();
            gemm8<2>(g_W3F, a2p, 0, 0, 0, 0.f, false, hT, hTp, yT, yTp, ka, b3s, dt); __syncthreads();
            // stage 3: f(tt+dt/2, y)
            gemm8<0>(g_W1F, yTp, a1p, b1s, w1ls, tt + 0.5f * dt, true, 0, 0, 0, 0, 0, 0, 0.f); __syncthreads();
            gemm8<0>(g_W2F, a1p, a2p, b2s, 0, 0.f, false, 0, 0, 0, 0, 0, 0, 0.f); __syncthreads();
            gemm8<3>(g_W3F, a2p, 0, 0, 0, 0.f, false, hT, hTp, yT, yTp, ka, b3s, dt); __syncthreads();
            // stage 4: f(tt+dt, y)
            gemm8<0>(g_W1F, yTp, a1p, b1s, w1ls, tt + dt, true, 0, 0, 0, 0, 0, 0, 0.f); __syncthreads();
            gemm8<0>(g_W2F, a1p, a2p, b2s, 0, 0.f, false, 0, 0, 0, 0, 0, 0, 0.f); __syncthreads();
            gemm8<4>(g_W3F, a2p, 0, 0, 0, 0.f, false, hT, hTp, yT, yTp, ka, b3s, dt); __syncthreads();
            tt += dt;
        }
    }
}

extern "C" void kernel_launch(void* const* d_in, const int* in_sizes, int n_in,
                              void* d_out, int out_size) {
    const float* x    = (const float*)d_in[0];
    const float* t    = (const float*)d_in[1];
    const float* mask = (const float*)d_in[2];
    const float* W_ih = (const float*)d_in[3];
    const float* W_hh = (const float*)d_in[4];
    const float* b_ih = (const float*)d_in[5];
    const float* b_hh = (const float*)d_in[6];
    const float* W1   = (const float*)d_in[7];
    const float* b1   = (const float*)d_in[8];
    const float* W2   = (const float*)d_in[9];
    const float* b2   = (const float*)d_in[10];
    const float* W3   = (const float*)d_in[11];
    const float* b3   = (const float*)d_in[12];
    float* out = (float*)d_out;

    prep_kernel<<<256, 256>>>(W_ih, W_hh, W1, W2, W3);

    const int smem_bytes = 18432 * sizeof(float);  // 73728
    cudaFuncSetAttribute(odernn_kernel,
                         cudaFuncAttributeMaxDynamicSharedMemorySize, smem_bytes);
    odernn_kernel<<<NCTA, NT, smem_bytes>>>(x, t, mask, b_ih, b_hh,
                                            b1, b2, b3, out);
}

// round 11
// speedup vs baseline: 2.6197x; 1.0527x over previous
#include <cuda_runtime.h>
#include <cuda_fp16.h>
#include <math.h>

// ODE-RNN persistent kernel, round 11 (base = round 10, 17.45ms):
//  - W3 fragment weights cached in SMEM (128KB, loaded once): removes 29%
//    of the per-step L2 weight stream (we measured ~12 TB/s = LTS ceiling).
//  - W1/W2 weight LDGs register-pipelined depth 8 to cover ~250cyc L2 hits.
//  - Otherwise identical to round 10 (fp16 m16n8k16 MLP, fp32 FFMA2 GRU).

#define NT 512
#define MBR 8
#define NCTA 128
#define T_LEN 200

typedef unsigned long long ull;

__device__ float g_WihT[16 * 768 * 4];
__device__ float g_WhhT[64 * 768 * 4];
// MLP fp16 fragment-packed weights: [nt(16)][kt(16)][lane(32)][a0..a3 (u32=half2)]
__device__ unsigned g_W1F[16 * 16 * 32 * 4];
__device__ unsigned g_W2F[16 * 16 * 32 * 4];
__device__ unsigned g_W3F[16 * 16 * 32 * 4];
__device__ float g_W1last[256];

// logical column for physical k-index (sigma^-1), per 16-block
__device__ __forceinline__ int permL(int c) {
    return (c & ~15) + ((c & 15) >> 1) + ((c & 1) << 3);
}
__device__ __forceinline__ unsigned h2pack(float a, float b) {
    __half2 h = __floats2half2_rn(a, b);
    return *reinterpret_cast<unsigned*>(&h);
}

__global__ void prep_kernel(const float* __restrict__ W_ih,
                            const float* __restrict__ W_hh,
                            const float* __restrict__ W1,
                            const float* __restrict__ W2,
                            const float* __restrict__ W3) {
    int idx = blockIdx.x * blockDim.x + threadIdx.x;
    int stride = gridDim.x * blockDim.x;
    for (int t = idx; t < 16 * 768 * 4; t += stride) {
        int j = t & 3, nk = t >> 2;
        int n = nk % 768, k4 = nk / 768;
        g_WihT[t] = W_ih[n * 64 + k4 * 4 + j];
    }
    for (int t = idx; t < 64 * 768 * 4; t += stride) {
        int j = t & 3, nk = t >> 2;
        int n = nk % 768, k4 = nk / 768;
        g_WhhT[t] = W_hh[n * 256 + k4 * 4 + j];
    }
    for (int tI = idx; tI < 16 * 16 * 32; tI += stride) {
        int l = tI & 31, kt = (tI >> 5) & 15, nt = tI >> 9;
        int gid = l >> 2, tig = l & 3;
        int r0 = nt * 16 + gid, r1 = r0 + 8;
        int c0 = kt * 16 + 2 * tig;
        int la = permL(c0), lb = permL(c0 + 1), lc = permL(c0 + 8), ld = permL(c0 + 9);
        g_W1F[tI * 4 + 0] = h2pack(W1[r0 * 257 + la], W1[r0 * 257 + lb]);
        g_W1F[tI * 4 + 1] = h2pack(W1[r1 * 257 + la], W1[r1 * 257 + lb]);
        g_W1F[tI * 4 + 2] = h2pack(W1[r0 * 257 + lc], W1[r0 * 257 + ld]);
        g_W1F[tI * 4 + 3] = h2pack(W1[r1 * 257 + lc], W1[r1 * 257 + ld]);
        g_W2F[tI * 4 + 0] = h2pack(W2[r0 * 256 + la], W2[r0 * 256 + lb]);
        g_W2F[tI * 4 + 1] = h2pack(W2[r1 * 256 + la], W2[r1 * 256 + lb]);
        g_W2F[tI * 4 + 2] = h2pack(W2[r0 * 256 + lc], W2[r0 * 256 + ld]);
        g_W2F[tI * 4 + 3] = h2pack(W2[r1 * 256 + lc], W2[r1 * 256 + ld]);
        g_W3F[tI * 4 + 0] = h2pack(W3[r0 * 256 + la], W3[r0 * 256 + lb]);
        g_W3F[tI * 4 + 1] = h2pack(W3[r1 * 256 + la], W3[r1 * 256 + lb]);
        g_W3F[tI * 4 + 2] = h2pack(W3[r0 * 256 + lc], W3[r0 * 256 + ld]);
        g_W3F[tI * 4 + 3] = h2pack(W3[r1 * 256 + lc], W3[r1 * 256 + ld]);
    }
    for (int n = idx; n < 256; n += stride) g_W1last[n] = W1[n * 257 + 256];
}

__device__ __forceinline__ float sigm(float v) {
    return 1.0f / (1.0f + __expf(-v));
}
__device__ __forceinline__ float tanha(float v) {
    float r;
    asm("tanh.approx.f32 %0, %1;" : "=f"(r) : "f"(v));
    return r;
}
__device__ __forceinline__ ull pk2(float a, float b) {
    ull r;
    asm("mov.b64 %0, {%1, %2};" : "=l"(r) : "f"(a), "f"(b));
    return r;
}
__device__ __forceinline__ ull ffma2(ull a, ull b, ull c) {
    ull d;
    asm("fma.rn.f32x2 %0, %1, %2, %3;" : "=l"(d) : "l"(a), "l"(b), "l"(c));
    return d;
}

#define MMA_F16(c0, c1, c2, c3, A0, A1, A2, A3, B0, B1)                       \
    asm volatile(                                                             \
        "mma.sync.aligned.m16n8k16.row.col.f32.f16.f16.f32 "                  \
        "{%0,%1,%2,%3}, {%4,%5,%6,%7}, {%8,%9}, {%0,%1,%2,%3};"               \
        : "+f"(c0), "+f"(c1), "+f"(c2), "+f"(c3)                              \
        : "r"(A0), "r"(A1), "r"(A2), "r"(A3), "r"(B0), "r"(B1))

// One MLP GEMM: D[256][8] = W @ B. Warp w owns n-rows [16w,16w+16), full K.
// SMW=false: WF in global, register-pipelined depth 8.
// SMW=true:  WF in shared (W3 cache), plain loop.
// EPI 0: bias(+tt*w1l)+tanh -> dstp. EPI 1..4: RK4 stage fused.
template<int EPI, bool SMW>
__device__ __forceinline__ void gemm8(const unsigned* __restrict__ WF,
                                      const unsigned* __restrict__ Bp,
                                      unsigned* __restrict__ dstp,
                                      const float* __restrict__ bias,
                                      const float* __restrict__ w1l,
                                      float tt, bool tcol,
                                      float* __restrict__ hT,
                                      unsigned* __restrict__ hTp,
                                      float* __restrict__ yT,
                                      unsigned* __restrict__ yTp,
                                      float* __restrict__ ka,
                                      const float* __restrict__ b3s,
                                      float dt) {
    const int warp = threadIdx.x >> 5;
    const int lane = threadIdx.x & 31;
    const int gid = lane >> 2, tig = lane & 3;
    float c0 = 0.f, c1 = 0.f, c2 = 0.f, c3 = 0.f;
    const float4* __restrict__ wp =
        reinterpret_cast<const float4*>(WF) + (warp * 16 * 32 + lane);
    const unsigned* __restrict__ bq = Bp + tig * 8 + gid;
    if (SMW) {
#pragma unroll 4
        for (int kt = 0; kt < 16; ++kt) {
            float4 af = wp[kt * 32];
            unsigned A0 = __float_as_uint(af.x), A1 = __float_as_uint(af.y);
            unsigned A2 = __float_as_uint(af.z), A3 = __float_as_uint(af.w);
            unsigned B0 = bq[kt * 64];
            unsigned B1 = bq[kt * 64 + 32];
            MMA_F16(c0, c1, c2, c3, A0, A1, A2, A3, B0, B1);
        }
    } else {
        float4 a0[8];
#pragma unroll
        for (int p = 0; p < 8; ++p) a0[p] = wp[p * 32];
#pragma unroll
        for (int kt = 0; kt < 8; ++kt) {
            float4 af = a0[kt];
            a0[kt] = wp[(kt + 8) * 32];  // prefetch second half
            unsigned A0 = __float_as_uint(af.x), A1 = __float_as_uint(af.y);
            unsigned A2 = __float_as_uint(af.z), A3 = __float_as_uint(af.w);
            unsigned B0 = bq[kt * 64];
            unsigned B1 = bq[kt * 64 + 32];
            MMA_F16(c0, c1, c2, c3, A0, A1, A2, A3, B0, B1);
        }
#pragma unroll
        for (int kt = 8; kt < 16; ++kt) {
            float4 af = a0[kt - 8];
            unsigned A0 = __float_as_uint(af.x), A1 = __float_as_uint(af.y);
            unsigned A2 = __float_as_uint(af.z), A3 = __float_as_uint(af.w);
            unsigned B0 = bq[kt * 64];
            unsigned B1 = bq[kt * 64 + 32];
            MMA_F16(c0, c1, c2, c3, A0, A1, A2, A3, B0, B1);
        }
    }
    const int r0 = warp * 16 + gid, r1 = r0 + 8;
    const int mc = 2 * tig;
    const int wB = (warp * 8 + gid) * 8;  // half2 word base for rows (r0,r1)
    if (EPI == 0) {
        float bb0 = bias[r0], bb1 = bias[r1];
        if (tcol) { bb0 += tt * w1l[r0]; bb1 += tt * w1l[r1]; }
        dstp[wB + mc]     = h2pack(tanha(bb0 + c0), tanha(bb1 + c2));
        dstp[wB + mc + 1] = h2pack(tanha(bb0 + c1), tanha(bb1 + c3));
    } else {
        float b0 = b3s[r0], b1 = b3s[r1];
        float f0 = b0 + c0, f1 = b0 + c1;   // r0: mc, mc+1
        float f2 = b1 + c2, f3 = b1 + c3;   // r1: mc, mc+1
        float2 h0 = *reinterpret_cast<float2*>(&hT[r0 * 8 + mc]);
        float2 h1 = *reinterpret_cast<float2*>(&hT[r1 * 8 + mc]);
        if (EPI == 1) {
            *reinterpret_cast<float2*>(&ka[r0 * 8 + mc]) = make_float2(f0, f1);
            *reinterpret_cast<float2*>(&ka[r1 * 8 + mc]) = make_float2(f2, f3);
            float c = 0.5f * dt;
            float y0 = h0.x + c * f0, y1 = h0.y + c * f1;
            float y2 = h1.x + c * f2, y3 = h1.y + c * f3;
            *reinterpret_cast<float2*>(&yT[r0 * 8 + mc]) = make_float2(y0, y1);
            *reinterpret_cast<float2*>(&yT[r1 * 8 + mc]) = make_float2(y2, y3);
            yTp[wB + mc]     = h2pack(y0, y2);
            yTp[wB + mc + 1] = h2pack(y1, y3);
        } else if (EPI == 2 || EPI == 3) {
            float2 k0 = *reinterpret_cast<float2*>(&ka[r0 * 8 + mc]);
            float2 k1 = *reinterpret_cast<float2*>(&ka[r1 * 8 + mc]);
            *reinterpret_cast<float2*>(&ka[r0 * 8 + mc]) =
                make_float2(k0.x + 2.f * f0, k0.y + 2.f * f1);
            *reinterpret_cast<float2*>(&ka[r1 * 8 + mc]) =
                make_float2(k1.x + 2.f * f2, k1.y + 2.f * f3);
            float c = (EPI == 2) ? 0.5f * dt : dt;
            float y0 = h0.x + c * f0, y1 = h0.y + c * f1;
            float y2 = h1.x + c * f2, y3 = h1.y + c * f3;
            *reinterpret_cast<float2*>(&yT[r0 * 8 + mc]) = make_float2(y0, y1);
            *reinterpret_cast<float2*>(&yT[r1 * 8 + mc]) = make_float2(y2, y3);
            yTp[wB + mc]     = h2pack(y0, y2);
            yTp[wB + mc + 1] = h2pack(y1, y3);
        } else {  // EPI == 4
            float2 k0 = *reinterpret_cast<float2*>(&ka[r0 * 8 + mc]);
            float2 k1 = *reinterpret_cast<float2*>(&ka[r1 * 8 + mc]);
            float c = dt * (1.0f / 6.0f);
            float n0 = h0.x + c * (k0.x + f0), n1 = h0.y + c * (k0.y + f1);
            float n2 = h1.x + c * (k1.x + f2), n3 = h1.y + c * (k1.y + f3);
            *reinterpret_cast<float2*>(&hT[r0 * 8 + mc]) = make_float2(n0, n1);
            *reinterpret_cast<float2*>(&hT[r1 * 8 + mc]) = make_float2(n2, n3);
            hTp[wB + mc]     = h2pack(n0, n2);
            hTp[wB + mc + 1] = h2pack(n1, n3);
        }
    }
}

// GRU GEMM, fp32 FFMA2, xs layout [k][8].
template<int K>
__device__ __forceinline__ void gru_mm(const float* __restrict__ WT4,
                                       const float* __restrict__ bias,
                                       const float* __restrict__ xs,
                                       float* __restrict__ ys, int N) {
    const int n0 = threadIdx.x & 255;
    const int mh = threadIdx.x >> 8;
    const float* __restrict__ xb = xs + mh * 4;
    for (int n = n0; n < N; n += 256) {
        float a0 = bias[n];
        ull acc0 = 0ULL, acc1 = 0ULL;
        const float4* __restrict__ wp = reinterpret_cast<const float4*>(WT4) + n;
#pragma unroll 4
        for (int k4 = 0; k4 < K / 4; ++k4) {
            float4 w = wp[(size_t)k4 * N];
            const float* __restrict__ xr = xb + (k4 * 4) * 8;
#pragma unroll
            for (int kk = 0; kk < 4; ++kk) {
                float wv = (kk == 0 ? w.x : kk == 1 ? w.y : kk == 2 ? w.z : w.w);
                ull wd = pk2(wv, wv);
                float4 xa = *reinterpret_cast<const float4*>(xr + kk * 8);
                acc0 = ffma2(wd, pk2(xa.x, xa.y), acc0);
                acc1 = ffma2(wd, pk2(xa.z, xa.w), acc1);
            }
        }
        float2 p0 = *reinterpret_cast<float2*>(&acc0);
        float2 p1 = *reinterpret_cast<float2*>(&acc1);
        *reinterpret_cast<float4*>(ys + n * 8 + mh * 4) =
            make_float4(a0 + p0.x, a0 + p0.y, a0 + p1.x, a0 + p1.y);
    }
}

__global__ void __launch_bounds__(NT, 1)
odernn_kernel(const float* __restrict__ x,
              const float* __restrict__ t,
              const float* __restrict__ mask,
              const float* __restrict__ b_ih,
              const float* __restrict__ b_hh,
              const float* __restrict__ b1,
              const float* __restrict__ b2,
              const float* __restrict__ b3,
              float* __restrict__ out) {
    extern __shared__ float sm[];
    unsigned* w3s = reinterpret_cast<unsigned*>(sm);         // 32768 u32 (128KB)
    float* xT  = sm + 32768;         // 512
    float* hT  = sm + 33280;         // 2048
    unsigned* hTp = reinterpret_cast<unsigned*>(sm + 35328); // 1024
    float* U   = sm + 36352;         // union: 12288 floats
    float* gi  = U;                  // 6144 (GRU phase)
    float* gh  = U + 6144;           // 6144
    float* yT  = U;                  // 2048 (RK4 phase)
    float* ka  = U + 2048;           // 2048
    unsigned* a1p = reinterpret_cast<unsigned*>(U + 4096);   // 1024
    unsigned* a2p = reinterpret_cast<unsigned*>(U + 5120);   // 1024
    unsigned* yTp = reinterpret_cast<unsigned*>(U + 6144);   // 1024
    float* bihs = sm + 48640;        // 768
    float* bhhs = bihs + 768;        // 768
    float* b1s  = bhhs + 768;        // 256
    float* b2s  = b1s + 256;         // 256
    float* b3s  = b2s + 256;         // 256
    float* w1ls = b3s + 256;         // 256
    // total 51200 floats = 204800 bytes

    const int tid = threadIdx.x;
    const int m0 = blockIdx.x * MBR;

    // stage W3 fragments into smem (once per launch)
    {
        float4* d = reinterpret_cast<float4*>(w3s);
        const float4* s = reinterpret_cast<const float4*>(g_W3F);
        for (int idx = tid; idx < 16 * 16 * 32; idx += NT) d[idx] = s[idx];
    }
    for (int idx = tid; idx < 768; idx += NT) { bihs[idx] = b_ih[idx]; bhhs[idx] = b_hh[idx]; }
    for (int idx = tid; idx < 256; idx += NT) {
        b1s[idx] = b1[idx]; b2s[idx] = b2[idx]; b3s[idx] = b3[idx];
        w1ls[idx] = g_W1last[idx];
    }
    for (int idx = tid; idx < 256 * 8; idx += NT) hT[idx] = 0.0f;
    for (int idx = tid; idx < 128 * 8; idx += NT) hTp[idx] = 0u;
    __syncthreads();

    for (int i = 0; i < T_LEN; ++i) {
        for (int idx = tid; idx < 64 * MBR; idx += NT) {
            int k = idx >> 3, m = idx & 7;
            xT[k * 8 + m] = x[((size_t)(m0 + m) * T_LEN + i) * 64 + k];
        }
        __syncthreads();

        gru_mm<64>(g_WihT, bihs, xT, gi, 768);
        gru_mm<256>(g_WhhT, bhhs, hT, gh, 768);
        __syncthreads();

        // gate pointwise on row pairs (n, n+8) so hTp half2 words are whole
        {
            const int pm = tid & 7;
            const int pid = tid >> 3;
            const int q = pid & 7;
            const int bblk = pid >> 3;
            const float mk = mask[(size_t)(m0 + pm) * T_LEN + i];
#pragma unroll
            for (int j = 0; j < 2; ++j) {
                int blk = bblk + 8 * j;
                float hobs2[2];
#pragma unroll
                for (int hh = 0; hh < 2; ++hh) {
                    int n = blk * 16 + q + 8 * hh;
                    float ir = gi[n * 8 + pm];
                    float iz = gi[(256 + n) * 8 + pm];
                    float in_ = gi[(512 + n) * 8 + pm];
                    float hr = gh[n * 8 + pm];
                    float hz = gh[(256 + n) * 8 + pm];
                    float hn = gh[(512 + n) * 8 + pm];
                    float h = hT[n * 8 + pm];
                    float r = sigm(ir + hr);
                    float z = sigm(iz + hz);
                    float nn = tanhf(in_ + r * hn);
                    float hnew = (1.0f - z) * nn + z * h;
                    float hobs = mk * hnew + (1.0f - mk) * h;
                    hT[n * 8 + pm] = hobs;
                    out[((size_t)(m0 + pm) * T_LEN + i) * 256 + n] = hobs;
                    hobs2[hh] = hobs;
                }
                hTp[(blk * 8 + q) * 8 + pm] = h2pack(hobs2[0], hobs2[1]);
            }
        }
        __syncthreads();

        if (i == T_LEN - 1) break;

        float t0v = t[i], t1v = t[i + 1];
        float dt = (t1v - t0v) * 0.25f;
        float tt = t0v;
        for (int sub = 0; sub < 4; ++sub) {
            // stage 1: f(tt, h)
            gemm8<0, false>(g_W1F, hTp, a1p, b1s, w1ls, tt, true, 0, 0, 0, 0, 0, 0, 0.f); __syncthreads();
            gemm8<0, false>(g_W2F, a1p, a2p, b2s, 0, 0.f, false, 0, 0, 0, 0, 0, 0, 0.f); __syncthreads();
            gemm8<1, true>(w3s, a2p, 0, 0, 0, 0.f, false, hT, hTp, yT, yTp, ka, b3s, dt); __syncthreads();
            // stage 2: f(tt+dt/2, y)
            gemm8<0, false>(g_W1F, yTp, a1p, b1s, w1ls, tt + 0.5f * dt, true, 0, 0, 0, 0, 0, 0, 0.f); __syncthreads();
            gemm8<0, false>(g_W2F, a1p, a2p, b2s, 0, 0.f, false, 0, 0, 0, 0, 0, 0, 0.f); __syncthreads();
            gemm8<2, true>(w3s, a2p, 0, 0, 0, 0.f, false, hT, hTp, yT, yTp, ka, b3s, dt); __syncthreads();
            // stage 3: f(tt+dt/2, y)
            gemm8<0, false>(g_W1F, yTp, a1p, b1s, w1ls, tt + 0.5f * dt, true, 0, 0, 0, 0, 0, 0, 0.f); __syncthreads();
            gemm8<0, false>(g_W2F, a1p, a2p, b2s, 0, 0.f, false, 0, 0, 0, 0, 0, 0, 0.f); __syncthreads();
            gemm8<3, true>(w3s, a2p, 0, 0, 0, 0.f, false, hT, hTp, yT, yTp, ka, b3s, dt); __syncthreads();
            // stage 4: f(tt+dt, y)
            gemm8<0, false>(g_W1F, yTp, a1p, b1s, w1ls, tt + dt, true, 0, 0, 0, 0, 0, 0, 0.f); __syncthreads();
            gemm8<0, false>(g_W2F, a1p, a2p, b2s, 0, 0.f, false, 0, 0, 0, 0, 0, 0, 0.f); __syncthreads();
            gemm8<4, true>(w3s, a2p, 0, 0, 0, 0.f, false, hT, hTp, yT, yTp, ka, b3s, dt); __syncthreads();
            tt += dt;
        }
    }
}

extern "C" void kernel_launch(void* const* d_in, const int* in_sizes, int n_in,
                              void* d_out, int out_size) {
    const float* x    = (const float*)d_in[0];
    const float* t    = (const float*)d_in[1];
    const float* mask = (const float*)d_in[2];
    const float* W_ih = (const float*)d_in[3];
    const float* W_hh = (const float*)d_in[4];
    const float* b_ih = (const float*)d_in[5];
    const float* b_hh = (const float*)d_in[6];
    const float* W1   = (const float*)d_in[7];
    const float* b1   = (const float*)d_in[8];
    const float* W2   = (const float*)d_in[9];
    const float* b2   = (const float*)d_in[10];
    const float* W3   = (const float*)d_in[11];
    const float* b3   = (const float*)d_in[12];
    float* out = (float*)d_out;

    prep_kernel<<<256, 256>>>(W_ih, W_hh, W1, W2, W3);

    const int smem_bytes = 51200 * sizeof(float);  // 204800
    cudaFuncSetAttribute(odernn_kernel,
                         cudaFuncAttributeMaxDynamicSharedMemorySize, smem_bytes);
    odernn_kernel<<<NCTA, NT, smem_bytes>>>(x, t, mask, b_ih, b_hh,
                                            b1, b2, b3, out);
}

// round 12
// speedup vs baseline: 3.8801x; 1.4811x over previous
#include <cuda_runtime.h>
#include <cuda_fp16.h>
#include <math.h>

// ODE-RNN persistent kernel, round 12 (base = round 11, 16.57ms):
//  - GRU GEMMs also on fp16 m16n8k16 tensor cores: 32 fused (W_ih@x + W_hh@h)
//    r/z-gate tiles + 16 inn tiles + 16 hn tiles (n-gate needs inn + r*hn
//    separately). Kills the GRU's broadcast-LDS l1tex hog (~25K cyc/step)
//    and halves GRU weight bytes.
//  - MLP path unchanged from R11 (W3 in smem, W1/W2 register-pipelined).

#define NT 512
#define MBR 8
#define NCTA 128
#define T_LEN 200

// MLP fp16 fragment-packed weights: [nt(16)][kt(16)][lane(32)][a0..a3]
__device__ unsigned g_W1F[16 * 16 * 32 * 4];
__device__ unsigned g_W2F[16 * 16 * 32 * 4];
__device__ unsigned g_W3F[16 * 16 * 32 * 4];
__device__ float g_W1last[256];
// GRU fp16 fragment-packed weights: W_ih 48 tiles x 4 kt, W_hh 48 tiles x 16 kt
__device__ unsigned g_WihF[48 * 4 * 32 * 4];
__device__ unsigned g_WhhF[48 * 16 * 32 * 4];

// logical column for physical k-index (sigma^-1), per 16-block
__device__ __forceinline__ int permL(int c) {
    return (c & ~15) + ((c & 15) >> 1) + ((c & 1) << 3);
}
__device__ __forceinline__ unsigned h2pack(float a, float b) {
    __half2 h = __floats2half2_rn(a, b);
    return *reinterpret_cast<unsigned*>(&h);
}

__global__ void prep_kernel(const float* __restrict__ W_ih,
                            const float* __restrict__ W_hh,
                            const float* __restrict__ W1,
                            const float* __restrict__ W2,
                            const float* __restrict__ W3) {
    int idx = blockIdx.x * blockDim.x + threadIdx.x;
    int stride = gridDim.x * blockDim.x;
    // MLP fragments (N=256: 16 tiles, K=256: 16 kt)
    for (int tI = idx; tI < 16 * 16 * 32; tI += stride) {
        int l = tI & 31, kt = (tI >> 5) & 15, nt = tI >> 9;
        int gid = l >> 2, tig = l & 3;
        int r0 = nt * 16 + gid, r1 = r0 + 8;
        int c0 = kt * 16 + 2 * tig;
        int la = permL(c0), lb = permL(c0 + 1), lc = permL(c0 + 8), ld = permL(c0 + 9);
        g_W1F[tI * 4 + 0] = h2pack(W1[r0 * 257 + la], W1[r0 * 257 + lb]);
        g_W1F[tI * 4 + 1] = h2pack(W1[r1 * 257 + la], W1[r1 * 257 + lb]);
        g_W1F[tI * 4 + 2] = h2pack(W1[r0 * 257 + lc], W1[r0 * 257 + ld]);
        g_W1F[tI * 4 + 3] = h2pack(W1[r1 * 257 + lc], W1[r1 * 257 + ld]);
        g_W2F[tI * 4 + 0] = h2pack(W2[r0 * 256 + la], W2[r0 * 256 + lb]);
        g_W2F[tI * 4 + 1] = h2pack(W2[r1 * 256 + la], W2[r1 * 256 + lb]);
        g_W2F[tI * 4 + 2] = h2pack(W2[r0 * 256 + lc], W2[r0 * 256 + ld]);
        g_W2F[tI * 4 + 3] = h2pack(W2[r1 * 256 + lc], W2[r1 * 256 + ld]);
        g_W3F[tI * 4 + 0] = h2pack(W3[r0 * 256 + la], W3[r0 * 256 + lb]);
        g_W3F[tI * 4 + 1] = h2pack(W3[r1 * 256 + la], W3[r1 * 256 + lb]);
        g_W3F[tI * 4 + 2] = h2pack(W3[r0 * 256 + lc], W3[r0 * 256 + ld]);
        g_W3F[tI * 4 + 3] = h2pack(W3[r1 * 256 + lc], W3[r1 * 256 + ld]);
    }
    for (int n = idx; n < 256; n += stride) g_W1last[n] = W1[n * 257 + 256];
    // GRU W_ih fragments (N=768: 48 tiles, K=64: 4 kt)
    for (int tI = idx; tI < 48 * 4 * 32; tI += stride) {
        int l = tI & 31, kt = (tI >> 5) & 3, nt = tI >> 7;
        int gid = l >> 2, tig = l & 3;
        int r0 = nt * 16 + gid, r1 = r0 + 8;
        int c0 = kt * 16 + 2 * tig;
        int la = permL(c0), lb = permL(c0 + 1), lc = permL(c0 + 8), ld = permL(c0 + 9);
        g_WihF[tI * 4 + 0] = h2pack(W_ih[r0 * 64 + la], W_ih[r0 * 64 + lb]);
        g_WihF[tI * 4 + 1] = h2pack(W_ih[r1 * 64 + la], W_ih[r1 * 64 + lb]);
        g_WihF[tI * 4 + 2] = h2pack(W_ih[r0 * 64 + lc], W_ih[r0 * 64 + ld]);
        g_WihF[tI * 4 + 3] = h2pack(W_ih[r1 * 64 + lc], W_ih[r1 * 64 + ld]);
    }
    // GRU W_hh fragments (N=768: 48 tiles, K=256: 16 kt)
    for (int tI = idx; tI < 48 * 16 * 32; tI += stride) {
        int l = tI & 31, kt = (tI >> 5) & 15, nt = tI >> 9;
        int gid = l >> 2, tig = l & 3;
        int r0 = nt * 16 + gid, r1 = r0 + 8;
        int c0 = kt * 16 + 2 * tig;
        int la = permL(c0), lb = permL(c0 + 1), lc = permL(c0 + 8), ld = permL(c0 + 9);
        g_WhhF[tI * 4 + 0] = h2pack(W_hh[r0 * 256 + la], W_hh[r0 * 256 + lb]);
        g_WhhF[tI * 4 + 1] = h2pack(W_hh[r1 * 256 + la], W_hh[r1 * 256 + lb]);
        g_WhhF[tI * 4 + 2] = h2pack(W_hh[r0 * 256 + lc], W_hh[r0 * 256 + ld]);
        g_WhhF[tI * 4 + 3] = h2pack(W_hh[r1 * 256 + lc], W_hh[r1 * 256 + ld]);
    }
}

__device__ __forceinline__ float sigm(float v) {
    return 1.0f / (1.0f + __expf(-v));
}
__device__ __forceinline__ float tanha(float v) {
    float r;
    asm("tanh.approx.f32 %0, %1;" : "=f"(r) : "f"(v));
    return r;
}

#define MMA_F16(c0, c1, c2, c3, A0, A1, A2, A3, B0, B1)                       \
    asm volatile(                                                             \
        "mma.sync.aligned.m16n8k16.row.col.f32.f16.f16.f32 "                  \
        "{%0,%1,%2,%3}, {%4,%5,%6,%7}, {%8,%9}, {%0,%1,%2,%3};"               \
        : "+f"(c0), "+f"(c1), "+f"(c2), "+f"(c3)                              \
        : "r"(A0), "r"(A1), "r"(A2), "r"(A3), "r"(B0), "r"(B1))

#define U32(f) __float_as_uint(f)

// GRU GEMMs on tensor cores. Each of 16 warps does 4 logical tiles:
//  tile 0,1: fused rows [nt*16, nt*16+16), nt = warp, warp+16 (r/z gates):
//            acc = W_ih@x + W_hh@h, bias b_ih+b_hh -> g
//  tile 2:   inn rows 512.. (W_ih tile warp+32, K=64)  -> gin (+b_ih)
//  tile 3:   hn  rows 512.. (W_hh tile warp+32, K=256) -> ghn (+b_hh)
__device__ __forceinline__ void gru_gemm(const unsigned* __restrict__ xTp,
                                         const unsigned* __restrict__ hTp,
                                         float* __restrict__ g,
                                         float* __restrict__ gin,
                                         float* __restrict__ ghn,
                                         const float* __restrict__ bihs,
                                         const float* __restrict__ bhhs) {
    const int warp = threadIdx.x >> 5;
    const int lane = threadIdx.x & 31;
    const int gid = lane >> 2, tig = lane & 3;
    const int mc = 2 * tig;
    const unsigned* __restrict__ bx = xTp + tig * 8 + gid;
    const unsigned* __restrict__ bh = hTp + tig * 8 + gid;
#pragma unroll
    for (int tile = 0; tile < 4; ++tile) {
        float c0 = 0.f, c1 = 0.f, c2 = 0.f, c3 = 0.f;
        if (tile < 2) {
            const int nt = warp + 16 * tile;   // 0..31
            const float4* __restrict__ wpx =
                reinterpret_cast<const float4*>(g_WihF) + (nt * 4 * 32 + lane);
#pragma unroll
            for (int kt = 0; kt < 4; ++kt) {
                float4 af = wpx[kt * 32];
                MMA_F16(c0, c1, c2, c3, U32(af.x), U32(af.y), U32(af.z), U32(af.w),
                        bx[kt * 64], bx[kt * 64 + 32]);
            }
            const float4* __restrict__ wph =
                reinterpret_cast<const float4*>(g_WhhF) + (nt * 16 * 32 + lane);
#pragma unroll 4
            for (int kt = 0; kt < 16; ++kt) {
                float4 af = wph[kt * 32];
                MMA_F16(c0, c1, c2, c3, U32(af.x), U32(af.y), U32(af.z), U32(af.w),
                        bh[kt * 64], bh[kt * 64 + 32]);
            }
            const int r0 = nt * 16 + gid, r1 = r0 + 8;
            float bb0 = bihs[r0] + bhhs[r0], bb1 = bihs[r1] + bhhs[r1];
            *reinterpret_cast<float2*>(&g[r0 * 8 + mc]) = make_float2(bb0 + c0, bb0 + c1);
            *reinterpret_cast<float2*>(&g[r1 * 8 + mc]) = make_float2(bb1 + c2, bb1 + c3);
        } else if (tile == 2) {
            const int nt = warp + 32;   // W_ih tiles 32..47 (rows 512..767)
            const float4* __restrict__ wpx =
                reinterpret_cast<const float4*>(g_WihF) + (nt * 4 * 32 + lane);
#pragma unroll
            for (int kt = 0; kt < 4; ++kt) {
                float4 af = wpx[kt * 32];
                MMA_F16(c0, c1, c2, c3, U32(af.x), U32(af.y), U32(af.z), U32(af.w),
                        bx[kt * 64], bx[kt * 64 + 32]);
            }
            const int lr0 = warp * 16 + gid, lr1 = lr0 + 8;  // local rows 0..255
            float bb0 = bihs[512 + lr0], bb1 = bihs[512 + lr1];
            *reinterpret_cast<float2*>(&gin[lr0 * 8 + mc]) = make_float2(bb0 + c0, bb0 + c1);
            *reinterpret_cast<float2*>(&gin[lr1 * 8 + mc]) = make_float2(bb1 + c2, bb1 + c3);
        } else {
            const int nt = warp + 32;   // W_hh tiles 32..47 (rows 512..767)
            const float4* __restrict__ wph =
                reinterpret_cast<const float4*>(g_WhhF) + (nt * 16 * 32 + lane);
#pragma unroll 4
            for (int kt = 0; kt < 16; ++kt) {
                float4 af = wph[kt * 32];
                MMA_F16(c0, c1, c2, c3, U32(af.x), U32(af.y), U32(af.z), U32(af.w),
                        bh[kt * 64], bh[kt * 64 + 32]);
            }
            const int lr0 = warp * 16 + gid, lr1 = lr0 + 8;
            float bb0 = bhhs[512 + lr0], bb1 = bhhs[512 + lr1];
            *reinterpret_cast<float2*>(&ghn[lr0 * 8 + mc]) = make_float2(bb0 + c0, bb0 + c1);
            *reinterpret_cast<float2*>(&ghn[lr1 * 8 + mc]) = make_float2(bb1 + c2, bb1 + c3);
        }
    }
}

// One MLP GEMM: D[256][8] = W @ B. Warp w owns n-rows [16w,16w+16), full K.
// SMW=false: WF in global, register-pipelined depth 8. SMW=true: WF in shared.
// EPI 0: bias(+tt*w1l)+tanh -> dstp. EPI 1..4: RK4 stage fused.
template<int EPI, bool SMW>
__device__ __forceinline__ void gemm8(const unsigned* __restrict__ WF,
                                      const unsigned* __restrict__ Bp,
                                      unsigned* __restrict__ dstp,
                                      const float* __restrict__ bias,
                                      const float* __restrict__ w1l,
                                      float tt, bool tcol,
                                      float* __restrict__ hT,
                                      unsigned* __restrict__ hTp,
                                      float* __restrict__ yT,
                                      unsigned* __restrict__ yTp,
                                      float* __restrict__ ka,
                                      const float* __restrict__ b3s,
                                      float dt) {
    const int warp = threadIdx.x >> 5;
    const int lane = threadIdx.x & 31;
    const int gid = lane >> 2, tig = lane & 3;
    float c0 = 0.f, c1 = 0.f, c2 = 0.f, c3 = 0.f;
    const float4* __restrict__ wp =
        reinterpret_cast<const float4*>(WF) + (warp * 16 * 32 + lane);
    const unsigned* __restrict__ bq = Bp + tig * 8 + gid;
    if (SMW) {
#pragma unroll 4
        for (int kt = 0; kt < 16; ++kt) {
            float4 af = wp[kt * 32];
            MMA_F16(c0, c1, c2, c3, U32(af.x), U32(af.y), U32(af.z), U32(af.w),
                    bq[kt * 64], bq[kt * 64 + 32]);
        }
    } else {
        float4 a0[8];
#pragma unroll
        for (int p = 0; p < 8; ++p) a0[p] = wp[p * 32];
#pragma unroll
        for (int kt = 0; kt < 8; ++kt) {
            float4 af = a0[kt];
            a0[kt] = wp[(kt + 8) * 32];  // prefetch second half
            MMA_F16(c0, c1, c2, c3, U32(af.x), U32(af.y), U32(af.z), U32(af.w),
                    bq[kt * 64], bq[kt * 64 + 32]);
        }
#pragma unroll
        for (int kt = 8; kt < 16; ++kt) {
            float4 af = a0[kt - 8];
            MMA_F16(c0, c1, c2, c3, U32(af.x), U32(af.y), U32(af.z), U32(af.w),
                    bq[kt * 64], bq[kt * 64 + 32]);
        }
    }
    const int r0 = warp * 16 + gid, r1 = r0 + 8;
    const int mc = 2 * tig;
    const int wB = (warp * 8 + gid) * 8;  // half2 word base for rows (r0,r1)
    if (EPI == 0) {
        float bb0 = bias[r0], bb1 = bias[r1];
        if (tcol) { bb0 += tt * w1l[r0]; bb1 += tt * w1l[r1]; }
        dstp[wB + mc]     = h2pack(tanha(bb0 + c0), tanha(bb1 + c2));
        dstp[wB + mc + 1] = h2pack(tanha(bb0 + c1), tanha(bb1 + c3));
    } else {
        float b0 = b3s[r0], b1 = b3s[r1];
        float f0 = b0 + c0, f1 = b0 + c1;
        float f2 = b1 + c2, f3 = b1 + c3;
        float2 h0 = *reinterpret_cast<float2*>(&hT[r0 * 8 + mc]);
        float2 h1 = *reinterpret_cast<float2*>(&hT[r1 * 8 + mc]);
        if (EPI == 1) {
            *reinterpret_cast<float2*>(&ka[r0 * 8 + mc]) = make_float2(f0, f1);
            *reinterpret_cast<float2*>(&ka[r1 * 8 + mc]) = make_float2(f2, f3);
            float c = 0.5f * dt;
            float y0 = h0.x + c * f0, y1 = h0.y + c * f1;
            float y2 = h1.x + c * f2, y3 = h1.y + c * f3;
            *reinterpret_cast<float2*>(&yT[r0 * 8 + mc]) = make_float2(y0, y1);
            *reinterpret_cast<float2*>(&yT[r1 * 8 + mc]) = make_float2(y2, y3);
            yTp[wB + mc]     = h2pack(y0, y2);
            yTp[wB + mc + 1] = h2pack(y1, y3);
        } else if (EPI == 2 || EPI == 3) {
            float2 k0 = *reinterpret_cast<float2*>(&ka[r0 * 8 + mc]);
            float2 k1 = *reinterpret_cast<float2*>(&ka[r1 * 8 + mc]);
            *reinterpret_cast<float2*>(&ka[r0 * 8 + mc]) =
                make_float2(k0.x + 2.f * f0, k0.y + 2.f * f1);
            *reinterpret_cast<float2*>(&ka[r1 * 8 + mc]) =
                make_float2(k1.x + 2.f * f2, k1.y + 2.f * f3);
            float c = (EPI == 2) ? 0.5f * dt : dt;
            float y0 = h0.x + c * f0, y1 = h0.y + c * f1;
            float y2 = h1.x + c * f2, y3 = h1.y + c * f3;
            *reinterpret_cast<float2*>(&yT[r0 * 8 + mc]) = make_float2(y0, y1);
            *reinterpret_cast<float2*>(&yT[r1 * 8 + mc]) = make_float2(y2, y3);
            yTp[wB + mc]     = h2pack(y0, y2);
            yTp[wB + mc + 1] = h2pack(y1, y3);
        } else {  // EPI == 4
            float2 k0 = *reinterpret_cast<float2*>(&ka[r0 * 8 + mc]);
            float2 k1 = *reinterpret_cast<float2*>(&ka[r1 * 8 + mc]);
            float c = dt * (1.0f / 6.0f);
            float n0 = h0.x + c * (k0.x + f0), n1 = h0.y + c * (k0.y + f1);
            float n2 = h1.x + c * (k1.x + f2), n3 = h1.y + c * (k1.y + f3);
            *reinterpret_cast<float2*>(&hT[r0 * 8 + mc]) = make_float2(n0, n1);
            *reinterpret_cast<float2*>(&hT[r1 * 8 + mc]) = make_float2(n2, n3);
            hTp[wB + mc]     = h2pack(n0, n2);
            hTp[wB + mc + 1] = h2pack(n1, n3);
        }
    }
}

__global__ void __launch_bounds__(NT, 1)
odernn_kernel(const float* __restrict__ x,
              const float* __restrict__ t,
              const float* __restrict__ mask,
              const float* __restrict__ b_ih,
              const float* __restrict__ b_hh,
              const float* __restrict__ b1,
              const float* __restrict__ b2,
              const float* __restrict__ b3,
              float* __restrict__ out) {
    extern __shared__ float sm[];
    unsigned* w3s = reinterpret_cast<unsigned*>(sm);          // 32768 u32 (128KB)
    float* hT  = sm + 32768;          // 2048
    unsigned* hTp = reinterpret_cast<unsigned*>(sm + 34816);  // 1024
    unsigned* xTp = reinterpret_cast<unsigned*>(sm + 35840);  // 256
    float* U   = sm + 36096;          // union: 8192 floats
    float* g   = U;                   // 512*8 = 4096 (GRU phase: r/z gates)
    float* gin = U + 4096;            // 2048
    float* ghn = U + 6144;            // 2048
    float* yT  = U;                   // 2048 (RK4 phase)
    float* ka  = U + 2048;            // 2048
    unsigned* a1p = reinterpret_cast<unsigned*>(U + 4096);    // 1024
    unsigned* a2p = reinterpret_cast<unsigned*>(U + 5120);    // 1024
    unsigned* yTp = reinterpret_cast<unsigned*>(U + 6144);    // 1024
    float* bihs = sm + 44288;         // 768
    float* bhhs = bihs + 768;         // 768
    float* b1s  = bhhs + 768;         // 256
    float* b2s  = b1s + 256;          // 256
    float* b3s  = b2s + 256;          // 256
    float* w1ls = b3s + 256;          // 256
    // total 46848 floats = 187392 bytes

    const int tid = threadIdx.x;
    const int m0 = blockIdx.x * MBR;

    // stage W3 fragments into smem (once per launch)
    {
        float4* d = reinterpret_cast<float4*>(w3s);
        const float4* s = reinterpret_cast<const float4*>(g_W3F);
        for (int idx = tid; idx < 16 * 16 * 32; idx += NT) d[idx] = s[idx];
    }
    for (int idx = tid; idx < 768; idx += NT) { bihs[idx] = b_ih[idx]; bhhs[idx] = b_hh[idx]; }
    for (int idx = tid; idx < 256; idx += NT) {
        b1s[idx] = b1[idx]; b2s[idx] = b2[idx]; b3s[idx] = b3[idx];
        w1ls[idx] = g_W1last[idx];
    }
    for (int idx = tid; idx < 256 * 8; idx += NT) hT[idx] = 0.0f;
    for (int idx = tid; idx < 128 * 8; idx += NT) hTp[idx] = 0u;
    __syncthreads();

    for (int i = 0; i < T_LEN; ++i) {
        // pack x[:, i, :] into permuted half2 layout (32 k-pairs x 8 m)
        for (int idx = tid; idx < 32 * 8; idx += NT) {
            int m = idx & 7, w2 = idx >> 3;
            int blk = w2 >> 3, q = w2 & 7;
            const float* xr = x + ((size_t)(m0 + m) * T_LEN + i) * 64;
            xTp[idx] = h2pack(xr[blk * 16 + q], xr[blk * 16 + q + 8]);
        }
        __syncthreads();

        gru_gemm(xTp, hTp, g, gin, ghn, bihs, bhhs);
        __syncthreads();

        // gate pointwise on row pairs (n, n+8) so hTp half2 words are whole
        {
            const int pm = tid & 7;
            const int pid = tid >> 3;
            const int q = pid & 7;
            const int bblk = pid >> 3;
            const float mk = mask[(size_t)(m0 + pm) * T_LEN + i];
#pragma unroll
            for (int j = 0; j < 2; ++j) {
                int blk = bblk + 8 * j;
                float hobs2[2];
#pragma unroll
                for (int hh = 0; hh < 2; ++hh) {
                    int n = blk * 16 + q + 8 * hh;
                    float r = sigm(g[n * 8 + pm]);
                    float z = sigm(g[(256 + n) * 8 + pm]);
                    float h = hT[n * 8 + pm];
                    float nn = tanhf(gin[n * 8 + pm] + r * ghn[n * 8 + pm]);
                    float hnew = (1.0f - z) * nn + z * h;
                    float hobs = mk * hnew + (1.0f - mk) * h;
                    hT[n * 8 + pm] = hobs;
                    out[((size_t)(m0 + pm) * T_LEN + i) * 256 + n] = hobs;
                    hobs2[hh] = hobs;
                }
                hTp[(blk * 8 + q) * 8 + pm] = h2pack(hobs2[0], hobs2[1]);
            }
        }
        __syncthreads();

        if (i == T_LEN - 1) break;

        float t0v = t[i], t1v = t[i + 1];
        float dt = (t1v - t0v) * 0.25f;
        float tt = t0v;
        for (int sub = 0; sub < 4; ++sub) {
            // stage 1: f(tt, h)
            gemm8<0, false>(g_W1F, hTp, a1p, b1s, w1ls, tt, true, 0, 0, 0, 0, 0, 0, 0.f); __syncthreads();
            gemm8<0, false>(g_W2F, a1p, a2p, b2s, 0, 0.f, false, 0, 0, 0, 0, 0, 0, 0.f); __syncthreads();
            gemm8<1, true>(w3s, a2p, 0, 0, 0, 0.f, false, hT, hTp, yT, yTp, ka, b3s, dt); __syncthreads();
            // stage 2: f(tt+dt/2, y)
            gemm8<0, false>(g_W1F, yTp, a1p, b1s, w1ls, tt + 0.5f * dt, true, 0, 0, 0, 0, 0, 0, 0.f); __syncthreads();
            gemm8<0, false>(g_W2F, a1p, a2p, b2s, 0, 0.f, false, 0, 0, 0, 0, 0, 0, 0.f); __syncthreads();
            gemm8<2, true>(w3s, a2p, 0, 0, 0, 0.f, false, hT, hTp, yT, yTp, ka, b3s, dt); __syncthreads();
            // stage 3: f(tt+dt/2, y)
            gemm8<0, false>(g_W1F, yTp, a1p, b1s, w1ls, tt + 0.5f * dt, true, 0, 0, 0, 0, 0, 0, 0.f); __syncthreads();
            gemm8<0, false>(g_W2F, a1p, a2p, b2s, 0, 0.f, false, 0, 0, 0, 0, 0, 0, 0.f); __syncthreads();
            gemm8<3, true>(w3s, a2p, 0, 0, 0, 0.f, false, hT, hTp, yT, yTp, ka, b3s, dt); __syncthreads();
            // stage 4: f(tt+dt, y)
            gemm8<0, false>(g_W1F, yTp, a1p, b1s, w1ls, tt + dt, true, 0, 0, 0, 0, 0, 0, 0.f); __syncthreads();
            gemm8<0, false>(g_W2F, a1p, a2p, b2s, 0, 0.f, false, 0, 0, 0, 0, 0, 0, 0.f); __syncthreads();
            gemm8<4, true>(w3s, a2p, 0, 0, 0, 0.f, false, hT, hTp, yT, yTp, ka, b3s, dt); __syncthreads();
            tt += dt;
        }
    }
}

extern "C" void kernel_launch(void* const* d_in, const int* in_sizes, int n_in,
                              void* d_out, int out_size) {
    const float* x    = (const float*)d_in[0];
    const float* t    = (const float*)d_in[1];
    const float* mask = (const float*)d_in[2];
    const float* W_ih = (const float*)d_in[3];
    const float* W_hh = (const float*)d_in[4];
    const float* b_ih = (const float*)d_in[5];
    const float* b_hh = (const float*)d_in[6];
    const float* W1   = (const float*)d_in[7];
    const float* b1   = (const float*)d_in[8];
    const float* W2   = (const float*)d_in[9];
    const float* b2   = (const float*)d_in[10];
    const float* W3   = (const float*)d_in[11];
    const float* b3   = (const float*)d_in[12];
    float* out = (float*)d_out;

    prep_kernel<<<256, 256>>>(W_ih, W_hh, W1, W2, W3);

    const int smem_bytes = 46848 * sizeof(float);  // 187392
    cudaFuncSetAttribute(odernn_kernel,
                         cudaFuncAttributeMaxDynamicSharedMemorySize, smem_bytes);
    odernn_kernel<<<NCTA, NT, smem_bytes>>>(x, t, mask, b_ih, b_hh,
                                            b1, b2, b3, out);
}

// round 13
// speedup vs baseline: 3.9516x; 1.0184x over previous
#include <cuda_runtime.h>
#include <cuda_fp16.h>
#include <math.h>

// ODE-RNN persistent kernel, round 13 (base = round 12, 11.19ms):
//  - Cross-barrier weight prefetch: each global-weight MLP GEMM consumes 4
//    A-fragments preloaded BEFORE the preceding __syncthreads (weights are
//    barrier-independent), and prefetches the next global GEMM's first 4
//    fragments before its epilogue. Kills the post-barrier LDG cold-start
//    (~250cyc L2 latency) on all 32 global GEMMs per step.
//  - Chain: init=W1 -> G1(use W1, pre W2) -> G2(use W2, pre W1') -> G3(smem,
//    untouched) -> ... ; pre[] (16 regs) stays live across gates/GRU.
//  - Everything else identical to round 12.

#define NT 512
#define MBR 8
#define NCTA 128
#define T_LEN 200

// MLP fp16 fragment-packed weights: [nt(16)][kt(16)][lane(32)][a0..a3]
__device__ unsigned g_W1F[16 * 16 * 32 * 4];
__device__ unsigned g_W2F[16 * 16 * 32 * 4];
__device__ unsigned g_W3F[16 * 16 * 32 * 4];
__device__ float g_W1last[256];
// GRU fp16 fragment-packed weights: W_ih 48 tiles x 4 kt, W_hh 48 tiles x 16 kt
__device__ unsigned g_WihF[48 * 4 * 32 * 4];
__device__ unsigned g_WhhF[48 * 16 * 32 * 4];

// logical column for physical k-index (sigma^-1), per 16-block
__device__ __forceinline__ int permL(int c) {
    return (c & ~15) + ((c & 15) >> 1) + ((c & 1) << 3);
}
__device__ __forceinline__ unsigned h2pack(float a, float b) {
    __half2 h = __floats2half2_rn(a, b);
    return *reinterpret_cast<unsigned*>(&h);
}

__global__ void prep_kernel(const float* __restrict__ W_ih,
                            const float* __restrict__ W_hh,
                            const float* __restrict__ W1,
                            const float* __restrict__ W2,
                            const float* __restrict__ W3) {
    int idx = blockIdx.x * blockDim.x + threadIdx.x;
    int stride = gridDim.x * blockDim.x;
    for (int tI = idx; tI < 16 * 16 * 32; tI += stride) {
        int l = tI & 31, kt = (tI >> 5) & 15, nt = tI >> 9;
        int gid = l >> 2, tig = l & 3;
        int r0 = nt * 16 + gid, r1 = r0 + 8;
        int c0 = kt * 16 + 2 * tig;
        int la = permL(c0), lb = permL(c0 + 1), lc = permL(c0 + 8), ld = permL(c0 + 9);
        g_W1F[tI * 4 + 0] = h2pack(W1[r0 * 257 + la], W1[r0 * 257 + lb]);
        g_W1F[tI * 4 + 1] = h2pack(W1[r1 * 257 + la], W1[r1 * 257 + lb]);
        g_W1F[tI * 4 + 2] = h2pack(W1[r0 * 257 + lc], W1[r0 * 257 + ld]);
        g_W1F[tI * 4 + 3] = h2pack(W1[r1 * 257 + lc], W1[r1 * 257 + ld]);
        g_W2F[tI * 4 + 0] = h2pack(W2[r0 * 256 + la], W2[r0 * 256 + lb]);
        g_W2F[tI * 4 + 1] = h2pack(W2[r1 * 256 + la], W2[r1 * 256 + lb]);
        g_W2F[tI * 4 + 2] = h2pack(W2[r0 * 256 + lc], W2[r0 * 256 + ld]);
        g_W2F[tI * 4 + 3] = h2pack(W2[r1 * 256 + lc], W2[r1 * 256 + ld]);
        g_W3F[tI * 4 + 0] = h2pack(W3[r0 * 256 + la], W3[r0 * 256 + lb]);
        g_W3F[tI * 4 + 1] = h2pack(W3[r1 * 256 + la], W3[r1 * 256 + lb]);
        g_W3F[tI * 4 + 2] = h2pack(W3[r0 * 256 + lc], W3[r0 * 256 + ld]);
        g_W3F[tI * 4 + 3] = h2pack(W3[r1 * 256 + lc], W3[r1 * 256 + ld]);
    }
    for (int n = idx; n < 256; n += stride) g_W1last[n] = W1[n * 257 + 256];
    for (int tI = idx; tI < 48 * 4 * 32; tI += stride) {
        int l = tI & 31, kt = (tI >> 5) & 3, nt = tI >> 7;
        int gid = l >> 2, tig = l & 3;
        int r0 = nt * 16 + gid, r1 = r0 + 8;
        int c0 = kt * 16 + 2 * tig;
        int la = permL(c0), lb = permL(c0 + 1), lc = permL(c0 + 8), ld = permL(c0 + 9);
        g_WihF[tI * 4 + 0] = h2pack(W_ih[r0 * 64 + la], W_ih[r0 * 64 + lb]);
        g_WihF[tI * 4 + 1] = h2pack(W_ih[r1 * 64 + la], W_ih[r1 * 64 + lb]);
        g_WihF[tI * 4 + 2] = h2pack(W_ih[r0 * 64 + lc], W_ih[r0 * 64 + ld]);
        g_WihF[tI * 4 + 3] = h2pack(W_ih[r1 * 64 + lc], W_ih[r1 * 64 + ld]);
    }
    for (int tI = idx; tI < 48 * 16 * 32; tI += stride) {
        int l = tI & 31, kt = (tI >> 5) & 15, nt = tI >> 9;
        int gid = l >> 2, tig = l & 3;
        int r0 = nt * 16 + gid, r1 = r0 + 8;
        int c0 = kt * 16 + 2 * tig;
        int la = permL(c0), lb = permL(c0 + 1), lc = permL(c0 + 8), ld = permL(c0 + 9);
        g_WhhF[tI * 4 + 0] = h2pack(W_hh[r0 * 256 + la], W_hh[r0 * 256 + lb]);
        g_WhhF[tI * 4 + 1] = h2pack(W_hh[r1 * 256 + la], W_hh[r1 * 256 + lb]);
        g_WhhF[tI * 4 + 2] = h2pack(W_hh[r0 * 256 + lc], W_hh[r0 * 256 + ld]);
        g_WhhF[tI * 4 + 3] = h2pack(W_hh[r1 * 256 + lc], W_hh[r1 * 256 + ld]);
    }
}

__device__ __forceinline__ float sigm(float v) {
    return 1.0f / (1.0f + __expf(-v));
}
__device__ __forceinline__ float tanha(float v) {
    float r;
    asm("tanh.approx.f32 %0, %1;" : "=f"(r) : "f"(v));
    return r;
}

#define MMA_F16(c0, c1, c2, c3, A0, A1, A2, A3, B0, B1)                       \
    asm volatile(                                                             \
        "mma.sync.aligned.m16n8k16.row.col.f32.f16.f16.f32 "                  \
        "{%0,%1,%2,%3}, {%4,%5,%6,%7}, {%8,%9}, {%0,%1,%2,%3};"               \
        : "+f"(c0), "+f"(c1), "+f"(c2), "+f"(c3)                              \
        : "r"(A0), "r"(A1), "r"(A2), "r"(A3), "r"(B0), "r"(B1))

#define U32(f) __float_as_uint(f)

// GRU GEMMs on tensor cores (unchanged from R12).
__device__ __forceinline__ void gru_gemm(const unsigned* __restrict__ xTp,
                                         const unsigned* __restrict__ hTp,
                                         float* __restrict__ g,
                                         float* __restrict__ gin,
                                         float* __restrict__ ghn,
                                         const float* __restrict__ bihs,
                                         const float* __restrict__ bhhs) {
    const int warp = threadIdx.x >> 5;
    const int lane = threadIdx.x & 31;
    const int gid = lane >> 2, tig = lane & 3;
    const int mc = 2 * tig;
    const unsigned* __restrict__ bx = xTp + tig * 8 + gid;
    const unsigned* __restrict__ bh = hTp + tig * 8 + gid;
#pragma unroll
    for (int tile = 0; tile < 4; ++tile) {
        float c0 = 0.f, c1 = 0.f, c2 = 0.f, c3 = 0.f;
        if (tile < 2) {
            const int nt = warp + 16 * tile;
            const float4* __restrict__ wpx =
                reinterpret_cast<const float4*>(g_WihF) + (nt * 4 * 32 + lane);
#pragma unroll
            for (int kt = 0; kt < 4; ++kt) {
                float4 af = wpx[kt * 32];
                MMA_F16(c0, c1, c2, c3, U32(af.x), U32(af.y), U32(af.z), U32(af.w),
                        bx[kt * 64], bx[kt * 64 + 32]);
            }
            const float4* __restrict__ wph =
                reinterpret_cast<const float4*>(g_WhhF) + (nt * 16 * 32 + lane);
#pragma unroll 4
            for (int kt = 0; kt < 16; ++kt) {
                float4 af = wph[kt * 32];
                MMA_F16(c0, c1, c2, c3, U32(af.x), U32(af.y), U32(af.z), U32(af.w),
                        bh[kt * 64], bh[kt * 64 + 32]);
            }
            const int r0 = nt * 16 + gid, r1 = r0 + 8;
            float bb0 = bihs[r0] + bhhs[r0], bb1 = bihs[r1] + bhhs[r1];
            *reinterpret_cast<float2*>(&g[r0 * 8 + mc]) = make_float2(bb0 + c0, bb0 + c1);
            *reinterpret_cast<float2*>(&g[r1 * 8 + mc]) = make_float2(bb1 + c2, bb1 + c3);
        } else if (tile == 2) {
            const int nt = warp + 32;
            const float4* __restrict__ wpx =
                reinterpret_cast<const float4*>(g_WihF) + (nt * 4 * 32 + lane);
#pragma unroll
            for (int kt = 0; kt < 4; ++kt) {
                float4 af = wpx[kt * 32];
                MMA_F16(c0, c1, c2, c3, U32(af.x), U32(af.y), U32(af.z), U32(af.w),
                        bx[kt * 64], bx[kt * 64 + 32]);
            }
            const int lr0 = warp * 16 + gid, lr1 = lr0 + 8;
            float bb0 = bihs[512 + lr0], bb1 = bihs[512 + lr1];
            *reinterpret_cast<float2*>(&gin[lr0 * 8 + mc]) = make_float2(bb0 + c0, bb0 + c1);
            *reinterpret_cast<float2*>(&gin[lr1 * 8 + mc]) = make_float2(bb1 + c2, bb1 + c3);
        } else {
            const int nt = warp + 32;
            const float4* __restrict__ wph =
                reinterpret_cast<const float4*>(g_WhhF) + (nt * 16 * 32 + lane);
#pragma unroll 4
            for (int kt = 0; kt < 16; ++kt) {
                float4 af = wph[kt * 32];
                MMA_F16(c0, c1, c2, c3, U32(af.x), U32(af.y), U32(af.z), U32(af.w),
                        bh[kt * 64], bh[kt * 64 + 32]);
            }
            const int lr0 = warp * 16 + gid, lr1 = lr0 + 8;
            float bb0 = bhhs[512 + lr0], bb1 = bhhs[512 + lr1];
            *reinterpret_cast<float2*>(&ghn[lr0 * 8 + mc]) = make_float2(bb0 + c0, bb0 + c1);
            *reinterpret_cast<float2*>(&ghn[lr1 * 8 + mc]) = make_float2(bb1 + c2, bb1 + c3);
        }
    }
}

// One MLP GEMM: D[256][8] = W @ B. Warp w owns n-rows [16w,16w+16), full K.
// SMW=true: WF in shared (W3), plain loop, pre untouched.
// SMW=false (PIN): kt0..3 come from pre[] (loaded before the preceding
// barrier); kt4..15 pipelined from global; then prefetch NextWF's kt0..3
// into pre[] for the next global GEMM.
// EPI 0: bias(+tt*w1l)+tanh -> dstp. EPI 1..4: RK4 stage fused.
template<int EPI, bool SMW>
__device__ __forceinline__ void gemm8(const unsigned* __restrict__ WF,
                                      const unsigned* __restrict__ NextWF,
                                      float4* __restrict__ pre,
                                      const unsigned* __restrict__ Bp,
                                      unsigned* __restrict__ dstp,
                                      const float* __restrict__ bias,
                                      const float* __restrict__ w1l,
                                      float tt, bool tcol,
                                      float* __restrict__ hT,
                                      unsigned* __restrict__ hTp,
                                      float* __restrict__ yT,
                                      unsigned* __restrict__ yTp,
                                      float* __restrict__ ka,
                                      const float* __restrict__ b3s,
                                      float dt) {
    const int warp = threadIdx.x >> 5;
    const int lane = threadIdx.x & 31;
    const int gid = lane >> 2, tig = lane & 3;
    float c0 = 0.f, c1 = 0.f, c2 = 0.f, c3 = 0.f;
    const unsigned* __restrict__ bq = Bp + tig * 8 + gid;
    if (SMW) {
        const float4* __restrict__ wp =
            reinterpret_cast<const float4*>(WF) + (warp * 16 * 32 + lane);
#pragma unroll 4
        for (int kt = 0; kt < 16; ++kt) {
            float4 af = wp[kt * 32];
            MMA_F16(c0, c1, c2, c3, U32(af.x), U32(af.y), U32(af.z), U32(af.w),
                    bq[kt * 64], bq[kt * 64 + 32]);
        }
    } else {
        const float4* __restrict__ wp =
            reinterpret_cast<const float4*>(WF) + (warp * 16 * 32 + lane);
        float4 a0[8];
#pragma unroll
        for (int p = 0; p < 8; ++p) a0[p] = wp[(p + 4) * 32];  // kt 4..11
        // kt 0..3 from cross-barrier preloads
#pragma unroll
        for (int kt = 0; kt < 4; ++kt) {
            float4 af = pre[kt];
            MMA_F16(c0, c1, c2, c3, U32(af.x), U32(af.y), U32(af.z), U32(af.w),
                    bq[kt * 64], bq[kt * 64 + 32]);
        }
#pragma unroll
        for (int kt = 4; kt < 12; ++kt) {
            float4 af = a0[kt - 4];
            if (kt < 8) a0[kt - 4] = wp[(kt + 8) * 32];  // kt 12..15
            MMA_F16(c0, c1, c2, c3, U32(af.x), U32(af.y), U32(af.z), U32(af.w),
                    bq[kt * 64], bq[kt * 64 + 32]);
        }
#pragma unroll
        for (int kt = 12; kt < 16; ++kt) {
            float4 af = a0[kt - 12];
            MMA_F16(c0, c1, c2, c3, U32(af.x), U32(af.y), U32(af.z), U32(af.w),
                    bq[kt * 64], bq[kt * 64 + 32]);
        }
        // prefetch next global GEMM's kt0..3 (crosses the upcoming barriers)
        const float4* __restrict__ np =
            reinterpret_cast<const float4*>(NextWF) + (warp * 16 * 32 + lane);
#pragma unroll
        for (int p = 0; p < 4; ++p) pre[p] = np[p * 32];
    }
    const int r0 = warp * 16 + gid, r1 = r0 + 8;
    const int mc = 2 * tig;
    const int wB = (warp * 8 + gid) * 8;
    if (EPI == 0) {
        float bb0 = bias[r0], bb1 = bias[r1];
        if (tcol) { bb0 += tt * w1l[r0]; bb1 += tt * w1l[r1]; }
        dstp[wB + mc]     = h2pack(tanha(bb0 + c0), tanha(bb1 + c2));
        dstp[wB + mc + 1] = h2pack(tanha(bb0 + c1), tanha(bb1 + c3));
    } else {
        float b0 = b3s[r0], b1 = b3s[r1];
        float f0 = b0 + c0, f1 = b0 + c1;
        float f2 = b1 + c2, f3 = b1 + c3;
        float2 h0 = *reinterpret_cast<float2*>(&hT[r0 * 8 + mc]);
        float2 h1 = *reinterpret_cast<float2*>(&hT[r1 * 8 + mc]);
        if (EPI == 1) {
            *reinterpret_cast<float2*>(&ka[r0 * 8 + mc]) = make_float2(f0, f1);
            *reinterpret_cast<float2*>(&ka[r1 * 8 + mc]) = make_float2(f2, f3);
            float c = 0.5f * dt;
            float y0 = h0.x + c * f0, y1 = h0.y + c * f1;
            float y2 = h1.x + c * f2, y3 = h1.y + c * f3;
            *reinterpret_cast<float2*>(&yT[r0 * 8 + mc]) = make_float2(y0, y1);
            *reinterpret_cast<float2*>(&yT[r1 * 8 + mc]) = make_float2(y2, y3);
            yTp[wB + mc]     = h2pack(y0, y2);
            yTp[wB + mc + 1] = h2pack(y1, y3);
        } else if (EPI == 2 || EPI == 3) {
            float2 k0 = *reinterpret_cast<float2*>(&ka[r0 * 8 + mc]);
            float2 k1 = *reinterpret_cast<float2*>(&ka[r1 * 8 + mc]);
            *reinterpret_cast<float2*>(&ka[r0 * 8 + mc]) =
                make_float2(k0.x + 2.f * f0, k0.y + 2.f * f1);
            *reinterpret_cast<float2*>(&ka[r1 * 8 + mc]) =
                make_float2(k1.x + 2.f * f2, k1.y + 2.f * f3);
            float c = (EPI == 2) ? 0.5f * dt : dt;
            float y0 = h0.x + c * f0, y1 = h0.y + c * f1;
            float y2 = h1.x + c * f2, y3 = h1.y + c * f3;
            *reinterpret_cast<float2*>(&yT[r0 * 8 + mc]) = make_float2(y0, y1);
            *reinterpret_cast<float2*>(&yT[r1 * 8 + mc]) = make_float2(y2, y3);
            yTp[wB + mc]     = h2pack(y0, y2);
            yTp[wB + mc + 1] = h2pack(y1, y3);
        } else {  // EPI == 4
            float2 k0 = *reinterpret_cast<float2*>(&ka[r0 * 8 + mc]);
            float2 k1 = *reinterpret_cast<float2*>(&ka[r1 * 8 + mc]);
            float c = dt * (1.0f / 6.0f);
            float n0 = h0.x + c * (k0.x + f0), n1 = h0.y + c * (k0.y + f1);
            float n2 = h1.x + c * (k1.x + f2), n3 = h1.y + c * (k1.y + f3);
            *reinterpret_cast<float2*>(&hT[r0 * 8 + mc]) = make_float2(n0, n1);
            *reinterpret_cast<float2*>(&hT[r1 * 8 + mc]) = make_float2(n2, n3);
            hTp[wB + mc]     = h2pack(n0, n2);
            hTp[wB + mc + 1] = h2pack(n1, n3);
        }
    }
}

__global__ void __launch_bounds__(NT, 1)
odernn_kernel(const float* __restrict__ x,
              const float* __restrict__ t,
              const float* __restrict__ mask,
              const float* __restrict__ b_ih,
              const float* __restrict__ b_hh,
              const float* __restrict__ b1,
              const float* __restrict__ b2,
              const float* __restrict__ b3,
              float* __restrict__ out) {
    extern __shared__ float sm[];
    unsigned* w3s = reinterpret_cast<unsigned*>(sm);          // 32768 u32 (128KB)
    float* hT  = sm + 32768;          // 2048
    unsigned* hTp = reinterpret_cast<unsigned*>(sm + 34816);  // 1024
    unsigned* xTp = reinterpret_cast<unsigned*>(sm + 35840);  // 256
    float* U   = sm + 36096;          // union: 8192 floats
    float* g   = U;                   // 4096 (GRU phase)
    float* gin = U + 4096;            // 2048
    float* ghn = U + 6144;            // 2048
    float* yT  = U;                   // 2048 (RK4 phase)
    float* ka  = U + 2048;            // 2048
    unsigned* a1p = reinterpret_cast<unsigned*>(U + 4096);    // 1024
    unsigned* a2p = reinterpret_cast<unsigned*>(U + 5120);    // 1024
    unsigned* yTp = reinterpret_cast<unsigned*>(U + 6144);    // 1024
    float* bihs = sm + 44288;         // 768
    float* bhhs = bihs + 768;         // 768
    float* b1s  = bhhs + 768;         // 256
    float* b2s  = b1s + 256;          // 256
    float* b3s  = b2s + 256;          // 256
    float* w1ls = b3s + 256;          // 256
    // total 46848 floats = 187392 bytes

    const int tid = threadIdx.x;
    const int m0 = blockIdx.x * MBR;

    {
        float4* d = reinterpret_cast<float4*>(w3s);
        const float4* s = reinterpret_cast<const float4*>(g_W3F);
        for (int idx = tid; idx < 16 * 16 * 32; idx += NT) d[idx] = s[idx];
    }
    for (int idx = tid; idx < 768; idx += NT) { bihs[idx] = b_ih[idx]; bhhs[idx] = b_hh[idx]; }
    for (int idx = tid; idx < 256; idx += NT) {
        b1s[idx] = b1[idx]; b2s[idx] = b2[idx]; b3s[idx] = b3[idx];
        w1ls[idx] = g_W1last[idx];
    }
    for (int idx = tid; idx < 256 * 8; idx += NT) hT[idx] = 0.0f;
    for (int idx = tid; idx < 128 * 8; idx += NT) hTp[idx] = 0u;
    __syncthreads();

    // initial cross-barrier preload: W1 fragments kt0..3 for the first G1
    float4 pre[4];
    {
        const float4* wpre = reinterpret_cast<const float4*>(g_W1F) +
                             ((tid >> 5) * 16 * 32 + (tid & 31));
#pragma unroll
        for (int p = 0; p < 4; ++p) pre[p] = wpre[p * 32];
    }

    for (int i = 0; i < T_LEN; ++i) {
        for (int idx = tid; idx < 32 * 8; idx += NT) {
            int m = idx & 7, w2 = idx >> 3;
            int blk = w2 >> 3, q = w2 & 7;
            const float* xr = x + ((size_t)(m0 + m) * T_LEN + i) * 64;
            xTp[idx] = h2pack(xr[blk * 16 + q], xr[blk * 16 + q + 8]);
        }
        __syncthreads();

        gru_gemm(xTp, hTp, g, gin, ghn, bihs, bhhs);
        __syncthreads();

        // gate pointwise on row pairs (n, n+8)
        {
            const int pm = tid & 7;
            const int pid = tid >> 3;
            const int q = pid & 7;
            const int bblk = pid >> 3;
            const float mk = mask[(size_t)(m0 + pm) * T_LEN + i];
#pragma unroll
            for (int j = 0; j < 2; ++j) {
                int blk = bblk + 8 * j;
                float hobs2[2];
#pragma unroll
                for (int hh = 0; hh < 2; ++hh) {
                    int n = blk * 16 + q + 8 * hh;
                    float r = sigm(g[n * 8 + pm]);
                    float z = sigm(g[(256 + n) * 8 + pm]);
                    float h = hT[n * 8 + pm];
                    float nn = tanhf(gin[n * 8 + pm] + r * ghn[n * 8 + pm]);
                    float hnew = (1.0f - z) * nn + z * h;
                    float hobs = mk * hnew + (1.0f - mk) * h;
                    hT[n * 8 + pm] = hobs;
                    out[((size_t)(m0 + pm) * T_LEN + i) * 256 + n] = hobs;
                    hobs2[hh] = hobs;
                }
                hTp[(blk * 8 + q) * 8 + pm] = h2pack(hobs2[0], hobs2[1]);
            }
        }
        __syncthreads();

        if (i == T_LEN - 1) break;

        float t0v = t[i], t1v = t[i + 1];
        float dt = (t1v - t0v) * 0.25f;
        float tt = t0v;
        for (int sub = 0; sub < 4; ++sub) {
            // stage 1: f(tt, h)
            gemm8<0, false>(g_W1F, g_W2F, pre, hTp, a1p, b1s, w1ls, tt, true, 0, 0, 0, 0, 0, 0, 0.f); __syncthreads();
            gemm8<0, false>(g_W2F, g_W1F, pre, a1p, a2p, b2s, 0, 0.f, false, 0, 0, 0, 0, 0, 0, 0.f); __syncthreads();
            gemm8<1, true>(w3s, 0, pre, a2p, 0, 0, 0, 0.f, false, hT, hTp, yT, yTp, ka, b3s, dt); __syncthreads();
            // stage 2: f(tt+dt/2, y)
            gemm8<0, false>(g_W1F, g_W2F, pre, yTp, a1p, b1s, w1ls, tt + 0.5f * dt, true, 0, 0, 0, 0, 0, 0, 0.f); __syncthreads();
            gemm8<0, false>(g_W2F, g_W1F, pre, a1p, a2p, b2s, 0, 0.f, false, 0, 0, 0, 0, 0, 0, 0.f); __syncthreads();
            gemm8<2, true>(w3s, 0, pre, a2p, 0, 0, 0, 0.f, false, hT, hTp, yT, yTp, ka, b3s, dt); __syncthreads();
            // stage 3: f(tt+dt/2, y)
            gemm8<0, false>(g_W1F, g_W2F, pre, yTp, a1p, b1s, w1ls, tt + 0.5f * dt, true, 0, 0, 0, 0, 0, 0, 0.f); __syncthreads();
            gemm8<0, false>(g_W2F, g_W1F, pre, a1p, a2p, b2s, 0, 0.f, false, 0, 0, 0, 0, 0, 0, 0.f); __syncthreads();
            gemm8<3, true>(w3s, 0, pre, a2p, 0, 0, 0, 0.f, false, hT, hTp, yT, yTp, ka, b3s, dt); __syncthreads();
            // stage 4: f(tt+dt, y)
            gemm8<0, false>(g_W1F, g_W2F, pre, yTp, a1p, b1s, w1ls, tt + dt, true, 0, 0, 0, 0, 0, 0, 0.f); __syncthreads();
            gemm8<0, false>(g_W2F, g_W1F, pre, a1p, a2p, b2s, 0, 0.f, false, 0, 0, 0, 0, 0, 0, 0.f); __syncthreads();
            gemm8<4, true>(w3s, 0, pre, a2p, 0, 0, 0, 0.f, false, hT, hTp, yT, yTp, ka, b3s, dt); __syncthreads();
            tt += dt;
        }
    }
}

extern "C" void kernel_launch(void* const* d_in, const int* in_sizes, int n_in,
                              void* d_out, int out_size) {
    const float* x    = (const float*)d_in[0];
    const float* t    = (const float*)d_in[1];
    const float* mask = (const float*)d_in[2];
    const float* W_ih = (const float*)d_in[3];
    const float* W_hh = (const float*)d_in[4];
    const float* b_ih = (const float*)d_in[5];
    const float* b_hh = (const float*)d_in[6];
    const float* W1   = (const float*)d_in[7];
    const float* b1   = (const float*)d_in[8];
    const float* W2   = (const float*)d_in[9];
    const float* b2   = (const float*)d_in[10];
    const float* W3   = (const float*)d_in[11];
    const float* b3   = (const float*)d_in[12];
    float* out = (float*)d_out;

    prep_kernel<<<256, 256>>>(W_ih, W_hh, W1, W2, W3);

    const int smem_bytes = 46848 * sizeof(float);  // 187392
    cudaFuncSetAttribute(odernn_kernel,
                         cudaFuncAttributeMaxDynamicSharedMemorySize, smem_bytes);
    odernn_kernel<<<NCTA, NT, smem_bytes>>>(x, t, mask, b_ih, b_hh,
                                            b1, b2, b3, out);
}

// round 14
// speedup vs baseline: 3.9633x; 1.0030x over previous
#include <cuda_runtime.h>
#include <cuda_fp16.h>
#include <math.h>

// ODE-RNN persistent kernel, round 14 (base = round 13, 10.99ms):
//  - Dual accumulator sets (even/odd kt) in every mma loop: halves the
//    HMMA dependent-issue chain per GEMM per warp (~400 -> ~200cyc),
//    which 4 warps/SMSP could not cover. Summed once pre-epilogue.
//  - Everything else identical to round 13.

#define NT 512
#define MBR 8
#define NCTA 128
#define T_LEN 200

// MLP fp16 fragment-packed weights: [nt(16)][kt(16)][lane(32)][a0..a3]
__device__ unsigned g_W1F[16 * 16 * 32 * 4];
__device__ unsigned g_W2F[16 * 16 * 32 * 4];
__device__ unsigned g_W3F[16 * 16 * 32 * 4];
__device__ float g_W1last[256];
// GRU fp16 fragment-packed weights: W_ih 48 tiles x 4 kt, W_hh 48 tiles x 16 kt
__device__ unsigned g_WihF[48 * 4 * 32 * 4];
__device__ unsigned g_WhhF[48 * 16 * 32 * 4];

__device__ __forceinline__ int permL(int c) {
    return (c & ~15) + ((c & 15) >> 1) + ((c & 1) << 3);
}
__device__ __forceinline__ unsigned h2pack(float a, float b) {
    __half2 h = __floats2half2_rn(a, b);
    return *reinterpret_cast<unsigned*>(&h);
}

__global__ void prep_kernel(const float* __restrict__ W_ih,
                            const float* __restrict__ W_hh,
                            const float* __restrict__ W1,
                            const float* __restrict__ W2,
                            const float* __restrict__ W3) {
    int idx = blockIdx.x * blockDim.x + threadIdx.x;
    int stride = gridDim.x * blockDim.x;
    for (int tI = idx; tI < 16 * 16 * 32; tI += stride) {
        int l = tI & 31, kt = (tI >> 5) & 15, nt = tI >> 9;
        int gid = l >> 2, tig = l & 3;
        int r0 = nt * 16 + gid, r1 = r0 + 8;
        int c0 = kt * 16 + 2 * tig;
        int la = permL(c0), lb = permL(c0 + 1), lc = permL(c0 + 8), ld = permL(c0 + 9);
        g_W1F[tI * 4 + 0] = h2pack(W1[r0 * 257 + la], W1[r0 * 257 + lb]);
        g_W1F[tI * 4 + 1] = h2pack(W1[r1 * 257 + la], W1[r1 * 257 + lb]);
        g_W1F[tI * 4 + 2] = h2pack(W1[r0 * 257 + lc], W1[r0 * 257 + ld]);
        g_W1F[tI * 4 + 3] = h2pack(W1[r1 * 257 + lc], W1[r1 * 257 + ld]);
        g_W2F[tI * 4 + 0] = h2pack(W2[r0 * 256 + la], W2[r0 * 256 + lb]);
        g_W2F[tI * 4 + 1] = h2pack(W2[r1 * 256 + la], W2[r1 * 256 + lb]);
        g_W2F[tI * 4 + 2] = h2pack(W2[r0 * 256 + lc], W2[r0 * 256 + ld]);
        g_W2F[tI * 4 + 3] = h2pack(W2[r1 * 256 + lc], W2[r1 * 256 + ld]);
        g_W3F[tI * 4 + 0] = h2pack(W3[r0 * 256 + la], W3[r0 * 256 + lb]);
        g_W3F[tI * 4 + 1] = h2pack(W3[r1 * 256 + la], W3[r1 * 256 + lb]);
        g_W3F[tI * 4 + 2] = h2pack(W3[r0 * 256 + lc], W3[r0 * 256 + ld]);
        g_W3F[tI * 4 + 3] = h2pack(W3[r1 * 256 + lc], W3[r1 * 256 + ld]);
    }
    for (int n = idx; n < 256; n += stride) g_W1last[n] = W1[n * 257 + 256];
    for (int tI = idx; tI < 48 * 4 * 32; tI += stride) {
        int l = tI & 31, kt = (tI >> 5) & 3, nt = tI >> 7;
        int gid = l >> 2, tig = l & 3;
        int r0 = nt * 16 + gid, r1 = r0 + 8;
        int c0 = kt * 16 + 2 * tig;
        int la = permL(c0), lb = permL(c0 + 1), lc = permL(c0 + 8), ld = permL(c0 + 9);
        g_WihF[tI * 4 + 0] = h2pack(W_ih[r0 * 64 + la], W_ih[r0 * 64 + lb]);
        g_WihF[tI * 4 + 1] = h2pack(W_ih[r1 * 64 + la], W_ih[r1 * 64 + lb]);
        g_WihF[tI * 4 + 2] = h2pack(W_ih[r0 * 64 + lc], W_ih[r0 * 64 + ld]);
        g_WihF[tI * 4 + 3] = h2pack(W_ih[r1 * 64 + lc], W_ih[r1 * 64 + ld]);
    }
    for (int tI = idx; tI < 48 * 16 * 32; tI += stride) {
        int l = tI & 31, kt = (tI >> 5) & 15, nt = tI >> 9;
        int gid = l >> 2, tig = l & 3;
        int r0 = nt * 16 + gid, r1 = r0 + 8;
        int c0 = kt * 16 + 2 * tig;
        int la = permL(c0), lb = permL(c0 + 1), lc = permL(c0 + 8), ld = permL(c0 + 9);
        g_WhhF[tI * 4 + 0] = h2pack(W_hh[r0 * 256 + la], W_hh[r0 * 256 + lb]);
        g_WhhF[tI * 4 + 1] = h2pack(W_hh[r1 * 256 + la], W_hh[r1 * 256 + lb]);
        g_WhhF[tI * 4 + 2] = h2pack(W_hh[r0 * 256 + lc], W_hh[r0 * 256 + ld]);
        g_WhhF[tI * 4 + 3] = h2pack(W_hh[r1 * 256 + lc], W_hh[r1 * 256 + ld]);
    }
}

__device__ __forceinline__ float sigm(float v) {
    return 1.0f / (1.0f + __expf(-v));
}
__device__ __forceinline__ float tanha(float v) {
    float r;
    asm("tanh.approx.f32 %0, %1;" : "=f"(r) : "f"(v));
    return r;
}

#define MMA_F16(c0, c1, c2, c3, A0, A1, A2, A3, B0, B1)                       \
    asm volatile(                                                             \
        "mma.sync.aligned.m16n8k16.row.col.f32.f16.f16.f32 "                  \
        "{%0,%1,%2,%3}, {%4,%5,%6,%7}, {%8,%9}, {%0,%1,%2,%3};"               \
        : "+f"(c0), "+f"(c1), "+f"(c2), "+f"(c3)                              \
        : "r"(A0), "r"(A1), "r"(A2), "r"(A3), "r"(B0), "r"(B1))

#define U32(f) __float_as_uint(f)

// issue one mma into accumulator set (d0..d3) chosen by kt parity
#define MMA_DUAL(kt, af, B0, B1)                                              \
    do {                                                                      \
        if ((kt) & 1) {                                                       \
            MMA_F16(d0, d1, d2, d3, U32((af).x), U32((af).y), U32((af).z),    \
                    U32((af).w), (B0), (B1));                                 \
        } else {                                                              \
            MMA_F16(c0, c1, c2, c3, U32((af).x), U32((af).y), U32((af).z),    \
                    U32((af).w), (B0), (B1));                                 \
        }                                                                     \
    } while (0)

// GRU GEMMs on tensor cores, dual accumulators.
__device__ __forceinline__ void gru_gemm(const unsigned* __restrict__ xTp,
                                         const unsigned* __restrict__ hTp,
                                         float* __restrict__ g,
                                         float* __restrict__ gin,
                                         float* __restrict__ ghn,
                                         const float* __restrict__ bihs,
                                         const float* __restrict__ bhhs) {
    const int warp = threadIdx.x >> 5;
    const int lane = threadIdx.x & 31;
    const int gid = lane >> 2, tig = lane & 3;
    const int mc = 2 * tig;
    const unsigned* __restrict__ bx = xTp + tig * 8 + gid;
    const unsigned* __restrict__ bh = hTp + tig * 8 + gid;
#pragma unroll
    for (int tile = 0; tile < 4; ++tile) {
        float c0 = 0.f, c1 = 0.f, c2 = 0.f, c3 = 0.f;
        float d0 = 0.f, d1 = 0.f, d2 = 0.f, d3 = 0.f;
        if (tile < 2) {
            const int nt = warp + 16 * tile;
            const float4* __restrict__ wpx =
                reinterpret_cast<const float4*>(g_WihF) + (nt * 4 * 32 + lane);
#pragma unroll
            for (int kt = 0; kt < 4; ++kt) {
                float4 af = wpx[kt * 32];
                MMA_DUAL(kt, af, bx[kt * 64], bx[kt * 64 + 32]);
            }
            const float4* __restrict__ wph =
                reinterpret_cast<const float4*>(g_WhhF) + (nt * 16 * 32 + lane);
#pragma unroll 8
            for (int kt = 0; kt < 16; ++kt) {
                float4 af = wph[kt * 32];
                MMA_DUAL(kt, af, bh[kt * 64], bh[kt * 64 + 32]);
            }
            c0 += d0; c1 += d1; c2 += d2; c3 += d3;
            const int r0 = nt * 16 + gid, r1 = r0 + 8;
            float bb0 = bihs[r0] + bhhs[r0], bb1 = bihs[r1] + bhhs[r1];
            *reinterpret_cast<float2*>(&g[r0 * 8 + mc]) = make_float2(bb0 + c0, bb0 + c1);
            *reinterpret_cast<float2*>(&g[r1 * 8 + mc]) = make_float2(bb1 + c2, bb1 + c3);
        } else if (tile == 2) {
            const int nt = warp + 32;
            const float4* __restrict__ wpx =
                reinterpret_cast<const float4*>(g_WihF) + (nt * 4 * 32 + lane);
#pragma unroll
            for (int kt = 0; kt < 4; ++kt) {
                float4 af = wpx[kt * 32];
                MMA_DUAL(kt, af, bx[kt * 64], bx[kt * 64 + 32]);
            }
            c0 += d0; c1 += d1; c2 += d2; c3 += d3;
            const int lr0 = warp * 16 + gid, lr1 = lr0 + 8;
            float bb0 = bihs[512 + lr0], bb1 = bihs[512 + lr1];
            *reinterpret_cast<float2*>(&gin[lr0 * 8 + mc]) = make_float2(bb0 + c0, bb0 + c1);
            *reinterpret_cast<float2*>(&gin[lr1 * 8 + mc]) = make_float2(bb1 + c2, bb1 + c3);
        } else {
            const int nt = warp + 32;
            const float4* __restrict__ wph =
                reinterpret_cast<const float4*>(g_WhhF) + (nt * 16 * 32 + lane);
#pragma unroll 8
            for (int kt = 0; kt < 16; ++kt) {
                float4 af = wph[kt * 32];
                MMA_DUAL(kt, af, bh[kt * 64], bh[kt * 64 + 32]);
            }
            c0 += d0; c1 += d1; c2 += d2; c3 += d3;
            const int lr0 = warp * 16 + gid, lr1 = lr0 + 8;
            float bb0 = bhhs[512 + lr0], bb1 = bhhs[512 + lr1];
            *reinterpret_cast<float2*>(&ghn[lr0 * 8 + mc]) = make_float2(bb0 + c0, bb0 + c1);
            *reinterpret_cast<float2*>(&ghn[lr1 * 8 + mc]) = make_float2(bb1 + c2, bb1 + c3);
        }
    }
}

// One MLP GEMM: D[256][8] = W @ B, dual accumulators.
template<int EPI, bool SMW>
__device__ __forceinline__ void gemm8(const unsigned* __restrict__ WF,
                                      const unsigned* __restrict__ NextWF,
                                      float4* __restrict__ pre,
                                      const unsigned* __restrict__ Bp,
                                      unsigned* __restrict__ dstp,
                                      const float* __restrict__ bias,
                                      const float* __restrict__ w1l,
                                      float tt, bool tcol,
                                      float* __restrict__ hT,
                                      unsigned* __restrict__ hTp,
                                      float* __restrict__ yT,
                                      unsigned* __restrict__ yTp,
                                      float* __restrict__ ka,
                                      const float* __restrict__ b3s,
                                      float dt) {
    const int warp = threadIdx.x >> 5;
    const int lane = threadIdx.x & 31;
    const int gid = lane >> 2, tig = lane & 3;
    float c0 = 0.f, c1 = 0.f, c2 = 0.f, c3 = 0.f;
    float d0 = 0.f, d1 = 0.f, d2 = 0.f, d3 = 0.f;
    const unsigned* __restrict__ bq = Bp + tig * 8 + gid;
    if (SMW) {
        const float4* __restrict__ wp =
            reinterpret_cast<const float4*>(WF) + (warp * 16 * 32 + lane);
#pragma unroll 8
        for (int kt = 0; kt < 16; ++kt) {
            float4 af = wp[kt * 32];
            MMA_DUAL(kt, af, bq[kt * 64], bq[kt * 64 + 32]);
        }
    } else {
        const float4* __restrict__ wp =
            reinterpret_cast<const float4*>(WF) + (warp * 16 * 32 + lane);
        float4 a0[8];
#pragma unroll
        for (int p = 0; p < 8; ++p) a0[p] = wp[(p + 4) * 32];  // kt 4..11
#pragma unroll
        for (int kt = 0; kt < 4; ++kt) {
            float4 af = pre[kt];
            MMA_DUAL(kt, af, bq[kt * 64], bq[kt * 64 + 32]);
        }
#pragma unroll
        for (int kt = 4; kt < 12; ++kt) {
            float4 af = a0[kt - 4];
            if (kt < 8) a0[kt - 4] = wp[(kt + 8) * 32];  // kt 12..15
            MMA_DUAL(kt, af, bq[kt * 64], bq[kt * 64 + 32]);
        }
#pragma unroll
        for (int kt = 12; kt < 16; ++kt) {
            float4 af = a0[kt - 12];
            MMA_DUAL(kt, af, bq[kt * 64], bq[kt * 64 + 32]);
        }
        const float4* __restrict__ np =
            reinterpret_cast<const float4*>(NextWF) + (warp * 16 * 32 + lane);
#pragma unroll
        for (int p = 0; p < 4; ++p) pre[p] = np[p * 32];
    }
    c0 += d0; c1 += d1; c2 += d2; c3 += d3;
    const int r0 = warp * 16 + gid, r1 = r0 + 8;
    const int mc = 2 * tig;
    const int wB = (warp * 8 + gid) * 8;
    if (EPI == 0) {
        float bb0 = bias[r0], bb1 = bias[r1];
        if (tcol) { bb0 += tt * w1l[r0]; bb1 += tt * w1l[r1]; }
        dstp[wB + mc]     = h2pack(tanha(bb0 + c0), tanha(bb1 + c2));
        dstp[wB + mc + 1] = h2pack(tanha(bb0 + c1), tanha(bb1 + c3));
    } else {
        float b0 = b3s[r0], b1 = b3s[r1];
        float f0 = b0 + c0, f1 = b0 + c1;
        float f2 = b1 + c2, f3 = b1 + c3;
        float2 h0 = *reinterpret_cast<float2*>(&hT[r0 * 8 + mc]);
        float2 h1 = *reinterpret_cast<float2*>(&hT[r1 * 8 + mc]);
        if (EPI == 1) {
            *reinterpret_cast<float2*>(&ka[r0 * 8 + mc]) = make_float2(f0, f1);
            *reinterpret_cast<float2*>(&ka[r1 * 8 + mc]) = make_float2(f2, f3);
            float c = 0.5f * dt;
            float y0 = h0.x + c * f0, y1 = h0.y + c * f1;
            float y2 = h1.x + c * f2, y3 = h1.y + c * f3;
            *reinterpret_cast<float2*>(&yT[r0 * 8 + mc]) = make_float2(y0, y1);
            *reinterpret_cast<float2*>(&yT[r1 * 8 + mc]) = make_float2(y2, y3);
            yTp[wB + mc]     = h2pack(y0, y2);
            yTp[wB + mc + 1] = h2pack(y1, y3);
        } else if (EPI == 2 || EPI == 3) {
            float2 k0 = *reinterpret_cast<float2*>(&ka[r0 * 8 + mc]);
            float2 k1 = *reinterpret_cast<float2*>(&ka[r1 * 8 + mc]);
            *reinterpret_cast<float2*>(&ka[r0 * 8 + mc]) =
                make_float2(k0.x + 2.f * f0, k0.y + 2.f * f1);
            *reinterpret_cast<float2*>(&ka[r1 * 8 + mc]) =
                make_float2(k1.x + 2.f * f2, k1.y + 2.f * f3);
            float c = (EPI == 2) ? 0.5f * dt : dt;
            float y0 = h0.x + c * f0, y1 = h0.y + c * f1;
            float y2 = h1.x + c * f2, y3 = h1.y + c * f3;
            *reinterpret_cast<float2*>(&yT[r0 * 8 + mc]) = make_float2(y0, y1);
            *reinterpret_cast<float2*>(&yT[r1 * 8 + mc]) = make_float2(y2, y3);
            yTp[wB + mc]     = h2pack(y0, y2);
            yTp[wB + mc + 1] = h2pack(y1, y3);
        } else {  // EPI == 4
            float2 k0 = *reinterpret_cast<float2*>(&ka[r0 * 8 + mc]);
            float2 k1 = *reinterpret_cast<float2*>(&ka[r1 * 8 + mc]);
            float c = dt * (1.0f / 6.0f);
            float n0 = h0.x + c * (k0.x + f0), n1 = h0.y + c * (k0.y + f1);
            float n2 = h1.x + c * (k1.x + f2), n3 = h1.y + c * (k1.y + f3);
            *reinterpret_cast<float2*>(&hT[r0 * 8 + mc]) = make_float2(n0, n1);
            *reinterpret_cast<float2*>(&hT[r1 * 8 + mc]) = make_float2(n2, n3);
            hTp[wB + mc]     = h2pack(n0, n2);
            hTp[wB + mc + 1] = h2pack(n1, n3);
        }
    }
}

__global__ void __launch_bounds__(NT, 1)
odernn_kernel(const float* __restrict__ x,
              const float* __restrict__ t,
              const float* __restrict__ mask,
              const float* __restrict__ b_ih,
              const float* __restrict__ b_hh,
              const float* __restrict__ b1,
              const float* __restrict__ b2,
              const float* __restrict__ b3,
              float* __restrict__ out) {
    extern __shared__ float sm[];
    unsigned* w3s = reinterpret_cast<unsigned*>(sm);          // 32768 u32 (128KB)
    float* hT  = sm + 32768;          // 2048
    unsigned* hTp = reinterpret_cast<unsigned*>(sm + 34816);  // 1024
    unsigned* xTp = reinterpret_cast<unsigned*>(sm + 35840);  // 256
    float* U   = sm + 36096;          // union: 8192 floats
    float* g   = U;                   // 4096 (GRU phase)
    float* gin = U + 4096;            // 2048
    float* ghn = U + 6144;            // 2048
    float* yT  = U;                   // 2048 (RK4 phase)
    float* ka  = U + 2048;            // 2048
    unsigned* a1p = reinterpret_cast<unsigned*>(U + 4096);    // 1024
    unsigned* a2p = reinterpret_cast<unsigned*>(U + 5120);    // 1024
    unsigned* yTp = reinterpret_cast<unsigned*>(U + 6144);    // 1024
    float* bihs = sm + 44288;         // 768
    float* bhhs = bihs + 768;         // 768
    float* b1s  = bhhs + 768;         // 256
    float* b2s  = b1s + 256;          // 256
    float* b3s  = b2s + 256;          // 256
    float* w1ls = b3s + 256;          // 256
    // total 46848 floats = 187392 bytes

    const int tid = threadIdx.x;
    const int m0 = blockIdx.x * MBR;

    {
        float4* d = reinterpret_cast<float4*>(w3s);
        const float4* s = reinterpret_cast<const float4*>(g_W3F);
        for (int idx = tid; idx < 16 * 16 * 32; idx += NT) d[idx] = s[idx];
    }
    for (int idx = tid; idx < 768; idx += NT) { bihs[idx] = b_ih[idx]; bhhs[idx] = b_hh[idx]; }
    for (int idx = tid; idx < 256; idx += NT) {
        b1s[idx] = b1[idx]; b2s[idx] = b2[idx]; b3s[idx] = b3[idx];
        w1ls[idx] = g_W1last[idx];
    }
    for (int idx = tid; idx < 256 * 8; idx += NT) hT[idx] = 0.0f;
    for (int idx = tid; idx < 128 * 8; idx += NT) hTp[idx] = 0u;
    __syncthreads();

    // initial cross-barrier preload: W1 fragments kt0..3 for the first G1
    float4 pre[4];
    {
        const float4* wpre = reinterpret_cast<const float4*>(g_W1F) +
                             ((tid >> 5) * 16 * 32 + (tid & 31));
#pragma unroll
        for (int p = 0; p < 4; ++p) pre[p] = wpre[p * 32];
    }

    for (int i = 0; i < T_LEN; ++i) {
        for (int idx = tid; idx < 32 * 8; idx += NT) {
            int m = idx & 7, w2 = idx >> 3;
            int blk = w2 >> 3, q = w2 & 7;
            const float* xr = x + ((size_t)(m0 + m) * T_LEN + i) * 64;
            xTp[idx] = h2pack(xr[blk * 16 + q], xr[blk * 16 + q + 8]);
        }
        __syncthreads();

        gru_gemm(xTp, hTp, g, gin, ghn, bihs, bhhs);
        __syncthreads();

        // gate pointwise on row pairs (n, n+8)
        {
            const int pm = tid & 7;
            const int pid = tid >> 3;
            const int q = pid & 7;
            const int bblk = pid >> 3;
            const float mk = mask[(size_t)(m0 + pm) * T_LEN + i];
#pragma unroll
            for (int j = 0; j < 2; ++j) {
                int blk = bblk + 8 * j;
                float hobs2[2];
#pragma unroll
                for (int hh = 0; hh < 2; ++hh) {
                    int n = blk * 16 + q + 8 * hh;
                    float r = sigm(g[n * 8 + pm]);
                    float z = sigm(g[(256 + n) * 8 + pm]);
                    float h = hT[n * 8 + pm];
                    float nn = tanhf(gin[n * 8 + pm] + r * ghn[n * 8 + pm]);
                    float hnew = (1.0f - z) * nn + z * h;
                    float hobs = mk * hnew + (1.0f - mk) * h;
                    hT[n * 8 + pm] = hobs;
                    out[((size_t)(m0 + pm) * T_LEN + i) * 256 + n] = hobs;
                    hobs2[hh] = hobs;
                }
                hTp[(blk * 8 + q) * 8 + pm] = h2pack(hobs2[0], hobs2[1]);
            }
        }
        __syncthreads();

        if (i == T_LEN - 1) break;

        float t0v = t[i], t1v = t[i + 1];
        float dt = (t1v - t0v) * 0.25f;
        float tt = t0v;
        for (int sub = 0; sub < 4; ++sub) {
            // stage 1: f(tt, h)
            gemm8<0, false>(g_W1F, g_W2F, pre, hTp, a1p, b1s, w1ls, tt, true, 0, 0, 0, 0, 0, 0, 0.f); __syncthreads();
            gemm8<0, false>(g_W2F, g_W1F, pre, a1p, a2p, b2s, 0, 0.f, false, 0, 0, 0, 0, 0, 0, 0.f); __syncthreads();
            gemm8<1, true>(w3s, 0, pre, a2p, 0, 0, 0, 0.f, false, hT, hTp, yT, yTp, ka, b3s, dt); __syncthreads();
            // stage 2: f(tt+dt/2, y)
            gemm8<0, false>(g_W1F, g_W2F, pre, yTp, a1p, b1s, w1ls, tt + 0.5f * dt, true, 0, 0, 0, 0, 0, 0, 0.f); __syncthreads();
            gemm8<0, false>(g_W2F, g_W1F, pre, a1p, a2p, b2s, 0, 0.f, false, 0, 0, 0, 0, 0, 0, 0.f); __syncthreads();
            gemm8<2, true>(w3s, 0, pre, a2p, 0, 0, 0, 0.f, false, hT, hTp, yT, yTp, ka, b3s, dt); __syncthreads();
            // stage 3: f(tt+dt/2, y)
            gemm8<0, false>(g_W1F, g_W2F, pre, yTp, a1p, b1s, w1ls, tt + 0.5f * dt, true, 0, 0, 0, 0, 0, 0, 0.f); __syncthreads();
            gemm8<0, false>(g_W2F, g_W1F, pre, a1p, a2p, b2s, 0, 0.f, false, 0, 0, 0, 0, 0, 0, 0.f); __syncthreads();
            gemm8<3, true>(w3s, 0, pre, a2p, 0, 0, 0, 0.f, false, hT, hTp, yT, yTp, ka, b3s, dt); __syncthreads();
            // stage 4: f(tt+dt, y)
            gemm8<0, false>(g_W1F, g_W2F, pre, yTp, a1p, b1s, w1ls, tt + dt, true, 0, 0, 0, 0, 0, 0, 0.f); __syncthreads();
            gemm8<0, false>(g_W2F, g_W1F, pre, a1p, a2p, b2s, 0, 0.f, false, 0, 0, 0, 0, 0, 0, 0.f); __syncthreads();
            gemm8<4, true>(w3s, 0, pre, a2p, 0, 0, 0, 0.f, false, hT, hTp, yT, yTp, ka, b3s, dt); __syncthreads();
            tt += dt;
        }
    }
}

extern "C" void kernel_launch(void* const* d_in, const int* in_sizes, int n_in,
                              void* d_out, int out_size) {
    const float* x    = (const float*)d_in[0];
    const float* t    = (const float*)d_in[1];
    const float* mask = (const float*)d_in[2];
    const float* W_ih = (const float*)d_in[3];
    const float* W_hh = (const float*)d_in[4];
    const float* b_ih = (const float*)d_in[5];
    const float* b_hh = (const float*)d_in[6];
    const float* W1   = (const float*)d_in[7];
    const float* b1   = (const float*)d_in[8];
    const float* W2   = (const float*)d_in[9];
    const float* b2   = (const float*)d_in[10];
    const float* W3   = (const float*)d_in[11];
    const float* b3   = (const float*)d_in[12];
    float* out = (float*)d_out;

    prep_kernel<<<256, 256>>>(W_ih, W_hh, W1, W2, W3);

    const int smem_bytes = 46848 * sizeof(float);  // 187392
    cudaFuncSetAttribute(odernn_kernel,
                         cudaFuncAttributeMaxDynamicSharedMemorySize, smem_bytes);
    odernn_kernel<<<NCTA, NT, smem_bytes>>>(x, t, mask, b_ih, b_hh,
                                            b1, b2, b3, out);
}

// round 15
// speedup vs baseline: 4.0247x; 1.0155x over previous
#include <cuda_runtime.h>
#include <cuda_fp16.h>
#include <math.h>

// ODE-RNN persistent kernel, round 15 (base = round 13, 10.99ms; dual-acc
// reverted as proven-neutral):
//  - pre[] widened 4 -> 8 fragments: each global MLP GEMM consumes kt0..7
//    from registers loaded BEFORE the preceding barrier, so the post-barrier
//    LDG cold-start bubble (~250-350cyc) is fully covered by in-hand work.
//  - GRU W_hh 16-kt loops get a depth-4 rolling load buffer.
//  - Everything else identical to round 13.

#define NT 512
#define MBR 8
#define NCTA 128
#define T_LEN 200

// MLP fp16 fragment-packed weights: [nt(16)][kt(16)][lane(32)][a0..a3]
__device__ unsigned g_W1F[16 * 16 * 32 * 4];
__device__ unsigned g_W2F[16 * 16 * 32 * 4];
__device__ unsigned g_W3F[16 * 16 * 32 * 4];
__device__ float g_W1last[256];
// GRU fp16 fragment-packed weights: W_ih 48 tiles x 4 kt, W_hh 48 tiles x 16 kt
__device__ unsigned g_WihF[48 * 4 * 32 * 4];
__device__ unsigned g_WhhF[48 * 16 * 32 * 4];

__device__ __forceinline__ int permL(int c) {
    return (c & ~15) + ((c & 15) >> 1) + ((c & 1) << 3);
}
__device__ __forceinline__ unsigned h2pack(float a, float b) {
    __half2 h = __floats2half2_rn(a, b);
    return *reinterpret_cast<unsigned*>(&h);
}

__global__ void prep_kernel(const float* __restrict__ W_ih,
                            const float* __restrict__ W_hh,
                            const float* __restrict__ W1,
                            const float* __restrict__ W2,
                            const float* __restrict__ W3) {
    int idx = blockIdx.x * blockDim.x + threadIdx.x;
    int stride = gridDim.x * blockDim.x;
    for (int tI = idx; tI < 16 * 16 * 32; tI += stride) {
        int l = tI & 31, kt = (tI >> 5) & 15, nt = tI >> 9;
        int gid = l >> 2, tig = l & 3;
        int r0 = nt * 16 + gid, r1 = r0 + 8;
        int c0 = kt * 16 + 2 * tig;
        int la = permL(c0), lb = permL(c0 + 1), lc = permL(c0 + 8), ld = permL(c0 + 9);
        g_W1F[tI * 4 + 0] = h2pack(W1[r0 * 257 + la], W1[r0 * 257 + lb]);
        g_W1F[tI * 4 + 1] = h2pack(W1[r1 * 257 + la], W1[r1 * 257 + lb]);
        g_W1F[tI * 4 + 2] = h2pack(W1[r0 * 257 + lc], W1[r0 * 257 + ld]);
        g_W1F[tI * 4 + 3] = h2pack(W1[r1 * 257 + lc], W1[r1 * 257 + ld]);
        g_W2F[tI * 4 + 0] = h2pack(W2[r0 * 256 + la], W2[r0 * 256 + lb]);
        g_W2F[tI * 4 + 1] = h2pack(W2[r1 * 256 + la], W2[r1 * 256 + lb]);
        g_W2F[tI * 4 + 2] = h2pack(W2[r0 * 256 + lc], W2[r0 * 256 + ld]);
        g_W2F[tI * 4 + 3] = h2pack(W2[r1 * 256 + lc], W2[r1 * 256 + ld]);
        g_W3F[tI * 4 + 0] = h2pack(W3[r0 * 256 + la], W3[r0 * 256 + lb]);
        g_W3F[tI * 4 + 1] = h2pack(W3[r1 * 256 + la], W3[r1 * 256 + lb]);
        g_W3F[tI * 4 + 2] = h2pack(W3[r0 * 256 + lc], W3[r0 * 256 + ld]);
        g_W3F[tI * 4 + 3] = h2pack(W3[r1 * 256 + lc], W3[r1 * 256 + ld]);
    }
    for (int n = idx; n < 256; n += stride) g_W1last[n] = W1[n * 257 + 256];
    for (int tI = idx; tI < 48 * 4 * 32; tI += stride) {
        int l = tI & 31, kt = (tI >> 5) & 3, nt = tI >> 7;
        int gid = l >> 2, tig = l & 3;
        int r0 = nt * 16 + gid, r1 = r0 + 8;
        int c0 = kt * 16 + 2 * tig;
        int la = permL(c0), lb = permL(c0 + 1), lc = permL(c0 + 8), ld = permL(c0 + 9);
        g_WihF[tI * 4 + 0] = h2pack(W_ih[r0 * 64 + la], W_ih[r0 * 64 + lb]);
        g_WihF[tI * 4 + 1] = h2pack(W_ih[r1 * 64 + la], W_ih[r1 * 64 + lb]);
        g_WihF[tI * 4 + 2] = h2pack(W_ih[r0 * 64 + lc], W_ih[r0 * 64 + ld]);
        g_WihF[tI * 4 + 3] = h2pack(W_ih[r1 * 64 + lc], W_ih[r1 * 64 + ld]);
    }
    for (int tI = idx; tI < 48 * 16 * 32; tI += stride) {
        int l = tI & 31, kt = (tI >> 5) & 15, nt = tI >> 9;
        int gid = l >> 2, tig = l & 3;
        int r0 = nt * 16 + gid, r1 = r0 + 8;
        int c0 = kt * 16 + 2 * tig;
        int la = permL(c0), lb = permL(c0 + 1), lc = permL(c0 + 8), ld = permL(c0 + 9);
        g_WhhF[tI * 4 + 0] = h2pack(W_hh[r0 * 256 + la], W_hh[r0 * 256 + lb]);
        g_WhhF[tI * 4 + 1] = h2pack(W_hh[r1 * 256 + la], W_hh[r1 * 256 + lb]);
        g_WhhF[tI * 4 + 2] = h2pack(W_hh[r0 * 256 + lc], W_hh[r0 * 256 + ld]);
        g_WhhF[tI * 4 + 3] = h2pack(W_hh[r1 * 256 + lc], W_hh[r1 * 256 + ld]);
    }
}

__device__ __forceinline__ float sigm(float v) {
    return 1.0f / (1.0f + __expf(-v));
}
__device__ __forceinline__ float tanha(float v) {
    float r;
    asm("tanh.approx.f32 %0, %1;" : "=f"(r) : "f"(v));
    return r;
}

#define MMA_F16(c0, c1, c2, c3, A0, A1, A2, A3, B0, B1)                       \
    asm volatile(                                                             \
        "mma.sync.aligned.m16n8k16.row.col.f32.f16.f16.f32 "                  \
        "{%0,%1,%2,%3}, {%4,%5,%6,%7}, {%8,%9}, {%0,%1,%2,%3};"               \
        : "+f"(c0), "+f"(c1), "+f"(c2), "+f"(c3)                              \
        : "r"(A0), "r"(A1), "r"(A2), "r"(A3), "r"(B0), "r"(B1))

#define U32(f) __float_as_uint(f)
#define MMA_AF(af, B0, B1)                                                    \
    MMA_F16(c0, c1, c2, c3, U32((af).x), U32((af).y), U32((af).z),            \
            U32((af).w), (B0), (B1))

// GRU GEMMs on tensor cores; W_hh 16-kt loops use a depth-4 rolling buffer.
__device__ __forceinline__ void gru_gemm(const unsigned* __restrict__ xTp,
                                         const unsigned* __restrict__ hTp,
                                         float* __restrict__ g,
                                         float* __restrict__ gin,
                                         float* __restrict__ ghn,
                                         const float* __restrict__ bihs,
                                         const float* __restrict__ bhhs) {
    const int warp = threadIdx.x >> 5;
    const int lane = threadIdx.x & 31;
    const int gid = lane >> 2, tig = lane & 3;
    const int mc = 2 * tig;
    const unsigned* __restrict__ bx = xTp + tig * 8 + gid;
    const unsigned* __restrict__ bh = hTp + tig * 8 + gid;
#pragma unroll
    for (int tile = 0; tile < 4; ++tile) {
        float c0 = 0.f, c1 = 0.f, c2 = 0.f, c3 = 0.f;
        if (tile < 2) {
            const int nt = warp + 16 * tile;
            const float4* __restrict__ wpx =
                reinterpret_cast<const float4*>(g_WihF) + (nt * 4 * 32 + lane);
            const float4* __restrict__ wph =
                reinterpret_cast<const float4*>(g_WhhF) + (nt * 16 * 32 + lane);
            float4 b0[4];
#pragma unroll
            for (int p = 0; p < 4; ++p) b0[p] = wph[p * 32];
#pragma unroll
            for (int kt = 0; kt < 4; ++kt) {
                float4 af = wpx[kt * 32];
                MMA_AF(af, bx[kt * 64], bx[kt * 64 + 32]);
            }
#pragma unroll
            for (int kt = 0; kt < 16; ++kt) {
                float4 af = b0[kt & 3];
                if (kt < 12) b0[kt & 3] = wph[(kt + 4) * 32];
                MMA_AF(af, bh[kt * 64], bh[kt * 64 + 32]);
            }
            const int r0 = nt * 16 + gid, r1 = r0 + 8;
            float bb0 = bihs[r0] + bhhs[r0], bb1 = bihs[r1] + bhhs[r1];
            *reinterpret_cast<float2*>(&g[r0 * 8 + mc]) = make_float2(bb0 + c0, bb0 + c1);
            *reinterpret_cast<float2*>(&g[r1 * 8 + mc]) = make_float2(bb1 + c2, bb1 + c3);
        } else if (tile == 2) {
            const int nt = warp + 32;
            const float4* __restrict__ wpx =
                reinterpret_cast<const float4*>(g_WihF) + (nt * 4 * 32 + lane);
#pragma unroll
            for (int kt = 0; kt < 4; ++kt) {
                float4 af = wpx[kt * 32];
                MMA_AF(af, bx[kt * 64], bx[kt * 64 + 32]);
            }
            const int lr0 = warp * 16 + gid, lr1 = lr0 + 8;
            float bb0 = bihs[512 + lr0], bb1 = bihs[512 + lr1];
            *reinterpret_cast<float2*>(&gin[lr0 * 8 + mc]) = make_float2(bb0 + c0, bb0 + c1);
            *reinterpret_cast<float2*>(&gin[lr1 * 8 + mc]) = make_float2(bb1 + c2, bb1 + c3);
        } else {
            const int nt = warp + 32;
            const float4* __restrict__ wph =
                reinterpret_cast<const float4*>(g_WhhF) + (nt * 16 * 32 + lane);
            float4 b0[4];
#pragma unroll
            for (int p = 0; p < 4; ++p) b0[p] = wph[p * 32];
#pragma unroll
            for (int kt = 0; kt < 16; ++kt) {
                float4 af = b0[kt & 3];
                if (kt < 12) b0[kt & 3] = wph[(kt + 4) * 32];
                MMA_AF(af, bh[kt * 64], bh[kt * 64 + 32]);
            }
            const int lr0 = warp * 16 + gid, lr1 = lr0 + 8;
            float bb0 = bhhs[512 + lr0], bb1 = bhhs[512 + lr1];
            *reinterpret_cast<float2*>(&ghn[lr0 * 8 + mc]) = make_float2(bb0 + c0, bb0 + c1);
            *reinterpret_cast<float2*>(&ghn[lr1 * 8 + mc]) = make_float2(bb1 + c2, bb1 + c3);
        }
    }
}

// One MLP GEMM: D[256][8] = W @ B. Warp w owns n-rows [16w,16w+16), full K.
// SMW=true: WF in shared (W3), plain loop, pre untouched.
// SMW=false: kt0..7 from pre[8] (loaded before the preceding barriers);
// kt8..15 loaded post-barrier (covered by the 8 in-hand mmas); then
// prefetch NextWF's kt0..7 into pre[].
template<int EPI, bool SMW>
__device__ __forceinline__ void gemm8(const unsigned* __restrict__ WF,
                                      const unsigned* __restrict__ NextWF,
                                      float4* __restrict__ pre,
                                      const unsigned* __restrict__ Bp,
                                      unsigned* __restrict__ dstp,
                                      const float* __restrict__ bias,
                                      const float* __restrict__ w1l,
                                      float tt, bool tcol,
                                      float* __restrict__ hT,
                                      unsigned* __restrict__ hTp,
                                      float* __restrict__ yT,
                                      unsigned* __restrict__ yTp,
                                      float* __restrict__ ka,
                                      const float* __restrict__ b3s,
                                      float dt) {
    const int warp = threadIdx.x >> 5;
    const int lane = threadIdx.x & 31;
    const int gid = lane >> 2, tig = lane & 3;
    float c0 = 0.f, c1 = 0.f, c2 = 0.f, c3 = 0.f;
    const unsigned* __restrict__ bq = Bp + tig * 8 + gid;
    if (SMW) {
        const float4* __restrict__ wp =
            reinterpret_cast<const float4*>(WF) + (warp * 16 * 32 + lane);
#pragma unroll 4
        for (int kt = 0; kt < 16; ++kt) {
            float4 af = wp[kt * 32];
            MMA_AF(af, bq[kt * 64], bq[kt * 64 + 32]);
        }
    } else {
        const float4* __restrict__ wp =
            reinterpret_cast<const float4*>(WF) + (warp * 16 * 32 + lane);
        float4 a0[8];
#pragma unroll
        for (int p = 0; p < 8; ++p) a0[p] = wp[(p + 8) * 32];  // kt 8..15
        // kt 0..7 from cross-barrier preloads (in-hand work covers LDG latency)
#pragma unroll
        for (int kt = 0; kt < 8; ++kt) {
            float4 af = pre[kt];
            MMA_AF(af, bq[kt * 64], bq[kt * 64 + 32]);
        }
#pragma unroll
        for (int kt = 8; kt < 16; ++kt) {
            float4 af = a0[kt - 8];
            MMA_AF(af, bq[kt * 64], bq[kt * 64 + 32]);
        }
        // prefetch next global GEMM's kt0..7 (crosses the upcoming barriers)
        const float4* __restrict__ np =
            reinterpret_cast<const float4*>(NextWF) + (warp * 16 * 32 + lane);
#pragma unroll
        for (int p = 0; p < 8; ++p) pre[p] = np[p * 32];
    }
    const int r0 = warp * 16 + gid, r1 = r0 + 8;
    const int mc = 2 * tig;
    const int wB = (warp * 8 + gid) * 8;
    if (EPI == 0) {
        float bb0 = bias[r0], bb1 = bias[r1];
        if (tcol) { bb0 += tt * w1l[r0]; bb1 += tt * w1l[r1]; }
        dstp[wB + mc]     = h2pack(tanha(bb0 + c0), tanha(bb1 + c2));
        dstp[wB + mc + 1] = h2pack(tanha(bb0 + c1), tanha(bb1 + c3));
    } else {
        float b0 = b3s[r0], b1 = b3s[r1];
        float f0 = b0 + c0, f1 = b0 + c1;
        float f2 = b1 + c2, f3 = b1 + c3;
        float2 h0 = *reinterpret_cast<float2*>(&hT[r0 * 8 + mc]);
        float2 h1 = *reinterpret_cast<float2*>(&hT[r1 * 8 + mc]);
        if (EPI == 1) {
            *reinterpret_cast<float2*>(&ka[r0 * 8 + mc]) = make_float2(f0, f1);
            *reinterpret_cast<float2*>(&ka[r1 * 8 + mc]) = make_float2(f2, f3);
            float c = 0.5f * dt;
            float y0 = h0.x + c * f0, y1 = h0.y + c * f1;
            float y2 = h1.x + c * f2, y3 = h1.y + c * f3;
            *reinterpret_cast<float2*>(&yT[r0 * 8 + mc]) = make_float2(y0, y1);
            *reinterpret_cast<float2*>(&yT[r1 * 8 + mc]) = make_float2(y2, y3);
            yTp[wB + mc]     = h2pack(y0, y2);
            yTp[wB + mc + 1] = h2pack(y1, y3);
        } else if (EPI == 2 || EPI == 3) {
            float2 k0 = *reinterpret_cast<float2*>(&ka[r0 * 8 + mc]);
            float2 k1 = *reinterpret_cast<float2*>(&ka[r1 * 8 + mc]);
            *reinterpret_cast<float2*>(&ka[r0 * 8 + mc]) =
                make_float2(k0.x + 2.f * f0, k0.y + 2.f * f1);
            *reinterpret_cast<float2*>(&ka[r1 * 8 + mc]) =
                make_float2(k1.x + 2.f * f2, k1.y + 2.f * f3);
            float c = (EPI == 2) ? 0.5f * dt : dt;
            float y0 = h0.x + c * f0, y1 = h0.y + c * f1;
            float y2 = h1.x + c * f2, y3 = h1.y + c * f3;
            *reinterpret_cast<float2*>(&yT[r0 * 8 + mc]) = make_float2(y0, y1);
            *reinterpret_cast<float2*>(&yT[r1 * 8 + mc]) = make_float2(y2, y3);
            yTp[wB + mc]     = h2pack(y0, y2);
            yTp[wB + mc + 1] = h2pack(y1, y3);
        } else {  // EPI == 4
            float2 k0 = *reinterpret_cast<float2*>(&ka[r0 * 8 + mc]);
            float2 k1 = *reinterpret_cast<float2*>(&ka[r1 * 8 + mc]);
            float c = dt * (1.0f / 6.0f);
            float n0 = h0.x + c * (k0.x + f0), n1 = h0.y + c * (k0.y + f1);
            float n2 = h1.x + c * (k1.x + f2), n3 = h1.y + c * (k1.y + f3);
            *reinterpret_cast<float2*>(&hT[r0 * 8 + mc]) = make_float2(n0, n1);
            *reinterpret_cast<float2*>(&hT[r1 * 8 + mc]) = make_float2(n2, n3);
            hTp[wB + mc]     = h2pack(n0, n2);
            hTp[wB + mc + 1] = h2pack(n1, n3);
        }
    }
}

__global__ void __launch_bounds__(NT, 1)
odernn_kernel(const float* __restrict__ x,
              const float* __restrict__ t,
              const float* __restrict__ mask,
              const float* __restrict__ b_ih,
              const float* __restrict__ b_hh,
              const float* __restrict__ b1,
              const float* __restrict__ b2,
              const float* __restrict__ b3,
              float* __restrict__ out) {
    extern __shared__ float sm[];
    unsigned* w3s = reinterpret_cast<unsigned*>(sm);          // 32768 u32 (128KB)
    float* hT  = sm + 32768;          // 2048
    unsigned* hTp = reinterpret_cast<unsigned*>(sm + 34816);  // 1024
    unsigned* xTp = reinterpret_cast<unsigned*>(sm + 35840);  // 256
    float* U   = sm + 36096;          // union: 8192 floats
    float* g   = U;                   // 4096 (GRU phase)
    float* gin = U + 4096;            // 2048
    float* ghn = U + 6144;            // 2048
    float* yT  = U;                   // 2048 (RK4 phase)
    float* ka  = U + 2048;            // 2048
    unsigned* a1p = reinterpret_cast<unsigned*>(U + 4096);    // 1024
    unsigned* a2p = reinterpret_cast<unsigned*>(U + 5120);    // 1024
    unsigned* yTp = reinterpret_cast<unsigned*>(U + 6144);    // 1024
    float* bihs = sm + 44288;         // 768
    float* bhhs = bihs + 768;         // 768
    float* b1s  = bhhs + 768;         // 256
    float* b2s  = b1s + 256;          // 256
    float* b3s  = b2s + 256;          // 256
    float* w1ls = b3s + 256;          // 256
    // total 46848 floats = 187392 bytes

    const int tid = threadIdx.x;
    const int m0 = blockIdx.x * MBR;

    {
        float4* d = reinterpret_cast<float4*>(w3s);
        const float4* s = reinterpret_cast<const float4*>(g_W3F);
        for (int idx = tid; idx < 16 * 16 * 32; idx += NT) d[idx] = s[idx];
    }
    for (int idx = tid; idx < 768; idx += NT) { bihs[idx] = b_ih[idx]; bhhs[idx] = b_hh[idx]; }
    for (int idx = tid; idx < 256; idx += NT) {
        b1s[idx] = b1[idx]; b2s[idx] = b2[idx]; b3s[idx] = b3[idx];
        w1ls[idx] = g_W1last[idx];
    }
    for (int idx = tid; idx < 256 * 8; idx += NT) hT[idx] = 0.0f;
    for (int idx = tid; idx < 128 * 8; idx += NT) hTp[idx] = 0u;
    __syncthreads();

    // initial cross-barrier preload: W1 fragments kt0..7 for the first G1
    float4 pre[8];
    {
        const float4* wpre = reinterpret_cast<const float4*>(g_W1F) +
                             ((tid >> 5) * 16 * 32 + (tid & 31));
#pragma unroll
        for (int p = 0; p < 8; ++p) pre[p] = wpre[p * 32];
    }

    for (int i = 0; i < T_LEN; ++i) {
        for (int idx = tid; idx < 32 * 8; idx += NT) {
            int m = idx & 7, w2 = idx >> 3;
            int blk = w2 >> 3, q = w2 & 7;
            const float* xr = x + ((size_t)(m0 + m) * T_LEN + i) * 64;
            xTp[idx] = h2pack(xr[blk * 16 + q], xr[blk * 16 + q + 8]);
        }
        __syncthreads();

        gru_gemm(xTp, hTp, g, gin, ghn, bihs, bhhs);
        __syncthreads();

        // gate pointwise on row pairs (n, n+8)
        {
            const int pm = tid & 7;
            const int pid = tid >> 3;
            const int q = pid & 7;
            const int bblk = pid >> 3;
            const float mk = mask[(size_t)(m0 + pm) * T_LEN + i];
#pragma unroll
            for (int j = 0; j < 2; ++j) {
                int blk = bblk + 8 * j;
                float hobs2[2];
#pragma unroll
                for (int hh = 0; hh < 2; ++hh) {
                    int n = blk * 16 + q + 8 * hh;
                    float r = sigm(g[n * 8 + pm]);
                    float z = sigm(g[(256 + n) * 8 + pm]);
                    float h = hT[n * 8 + pm];
                    float nn = tanhf(gin[n * 8 + pm] + r * ghn[n * 8 + pm]);
                    float hnew = (1.0f - z) * nn + z * h;
                    float hobs = mk * hnew + (1.0f - mk) * h;
                    hT[n * 8 + pm] = hobs;
                    out[((size_t)(m0 + pm) * T_LEN + i) * 256 + n] = hobs;
                    hobs2[hh] = hobs;
                }
                hTp[(blk * 8 + q) * 8 + pm] = h2pack(hobs2[0], hobs2[1]);
            }
        }
        __syncthreads();

        if (i == T_LEN - 1) break;

        float t0v = t[i], t1v = t[i + 1];
        float dt = (t1v - t0v) * 0.25f;
        float tt = t0v;
        for (int sub = 0; sub < 4; ++sub) {
            // stage 1: f(tt, h)
            gemm8<0, false>(g_W1F, g_W2F, pre, hTp, a1p, b1s, w1ls, tt, true, 0, 0, 0, 0, 0, 0, 0.f); __syncthreads();
            gemm8<0, false>(g_W2F, g_W1F, pre, a1p, a2p, b2s, 0, 0.f, false, 0, 0, 0, 0, 0, 0, 0.f); __syncthreads();
            gemm8<1, true>(w3s, 0, pre, a2p, 0, 0, 0, 0.f, false, hT, hTp, yT, yTp, ka, b3s, dt); __syncthreads();
            // stage 2: f(tt+dt/2, y)
            gemm8<0, false>(g_W1F, g_W2F, pre, yTp, a1p, b1s, w1ls, tt + 0.5f * dt, true, 0, 0, 0, 0, 0, 0, 0.f); __syncthreads();
            gemm8<0, false>(g_W2F, g_W1F, pre, a1p, a2p, b2s, 0, 0.f, false, 0, 0, 0, 0, 0, 0, 0.f); __syncthreads();
            gemm8<2, true>(w3s, 0, pre, a2p, 0, 0, 0, 0.f, false, hT, hTp, yT, yTp, ka, b3s, dt); __syncthreads();
            // stage 3: f(tt+dt/2, y)
            gemm8<0, false>(g_W1F, g_W2F, pre, yTp, a1p, b1s, w1ls, tt + 0.5f * dt, true, 0, 0, 0, 0, 0, 0, 0.f); __syncthreads();
            gemm8<0, false>(g_W2F, g_W1F, pre, a1p, a2p, b2s, 0, 0.f, false, 0, 0, 0, 0, 0, 0, 0.f); __syncthreads();
            gemm8<3, true>(w3s, 0, pre, a2p, 0, 0, 0, 0.f, false, hT, hTp, yT, yTp, ka, b3s, dt); __syncthreads();
            // stage 4: f(tt+dt, y)
            gemm8<0, false>(g_W1F, g_W2F, pre, yTp, a1p, b1s, w1ls, tt + dt, true, 0, 0, 0, 0, 0, 0, 0.f); __syncthreads();
            gemm8<0, false>(g_W2F, g_W1F, pre, a1p, a2p, b2s, 0, 0.f, false, 0, 0, 0, 0, 0, 0, 0.f); __syncthreads();
            gemm8<4, true>(w3s, 0, pre, a2p, 0, 0, 0, 0.f, false, hT, hTp, yT, yTp, ka, b3s, dt); __syncthreads();
            tt += dt;
        }
    }
}

extern "C" void kernel_launch(void* const* d_in, const int* in_sizes, int n_in,
                              void* d_out, int out_size) {
    const float* x    = (const float*)d_in[0];
    const float* t    = (const float*)d_in[1];
    const float* mask = (const float*)d_in[2];
    const float* W_ih = (const float*)d_in[3];
    const float* W_hh = (const float*)d_in[4];
    const float* b_ih = (const float*)d_in[5];
    const float* b_hh = (const float*)d_in[6];
    const float* W1   = (const float*)d_in[7];
    const float* b1   = (const float*)d_in[8];
    const float* W2   = (const float*)d_in[9];
    const float* b2   = (const float*)d_in[10];
    const float* W3   = (const float*)d_in[11];
    const float* b3   = (const float*)d_in[12];
    float* out = (float*)d_out;

    prep_kernel<<<256, 256>>>(W_ih, W_hh, W1, W2, W3);

    const int smem_bytes = 46848 * sizeof(float);  // 187392
    cudaFuncSetAttribute(odernn_kernel,
                         cudaFuncAttributeMaxDynamicSharedMemorySize, smem_bytes);
    odernn_kernel<<<NCTA, NT, smem_bytes>>>(x, t, mask, b_ih, b_hh,
                                            b1, b2, b3, out);
}

// round 17
// speedup vs baseline: 4.0384x; 1.0034x over previous
#include <cuda_runtime.h>
#include <cuda_fp16.h>
#include <math.h>

// ODE-RNN persistent kernel, round 16 (base = round 15, 10.79ms):
//  - NT 512 -> 256: each warp owns TWO 16-row n-tiles per GEMM, so one
//    B-fragment LDS pair feeds 2 mmas. Halves the 16x cross-warp B-operand
//    smem re-read (512 -> 256 wf/GEMM), -13% l1tex wavefronts per CTA,
//    -30% instructions. Dual accumulator sets (one per tile) are
//    independent chains. GRU tiles likewise doubled per warp.
//  - Cross-barrier pre[] trimmed to kt0..1 per tile + depth-4 rolling
//    pipeline (register budget).

#define NT 256
#define MBR 8
#define NCTA 128
#define T_LEN 200

// MLP fp16 fragment-packed weights: [nt(16)][kt(16)][lane(32)][a0..a3]
__device__ unsigned g_W1F[16 * 16 * 32 * 4];
__device__ unsigned g_W2F[16 * 16 * 32 * 4];
__device__ unsigned g_W3F[16 * 16 * 32 * 4];
__device__ float g_W1last[256];
// GRU fp16 fragment-packed weights: W_ih 48 tiles x 4 kt, W_hh 48 tiles x 16 kt
__device__ unsigned g_WihF[48 * 4 * 32 * 4];
__device__ unsigned g_WhhF[48 * 16 * 32 * 4];

__device__ __forceinline__ int permL(int c) {
    return (c & ~15) + ((c & 15) >> 1) + ((c & 1) << 3);
}
__device__ __forceinline__ unsigned h2pack(float a, float b) {
    __half2 h = __floats2half2_rn(a, b);
    return *reinterpret_cast<unsigned*>(&h);
}

__global__ void prep_kernel(const float* __restrict__ W_ih,
                            const float* __restrict__ W_hh,
                            const float* __restrict__ W1,
                            const float* __restrict__ W2,
                            const float* __restrict__ W3) {
    int idx = blockIdx.x * blockDim.x + threadIdx.x;
    int stride = gridDim.x * blockDim.x;
    for (int tI = idx; tI < 16 * 16 * 32; tI += stride) {
        int l = tI & 31, kt = (tI >> 5) & 15, nt = tI >> 9;
        int gid = l >> 2, tig = l & 3;
        int r0 = nt * 16 + gid, r1 = r0 + 8;
        int c0 = kt * 16 + 2 * tig;
        int la = permL(c0), lb = permL(c0 + 1), lc = permL(c0 + 8), ld = permL(c0 + 9);
        g_W1F[tI * 4 + 0] = h2pack(W1[r0 * 257 + la], W1[r0 * 257 + lb]);
        g_W1F[tI * 4 + 1] = h2pack(W1[r1 * 257 + la], W1[r1 * 257 + lb]);
        g_W1F[tI * 4 + 2] = h2pack(W1[r0 * 257 + lc], W1[r0 * 257 + ld]);
        g_W1F[tI * 4 + 3] = h2pack(W1[r1 * 257 + lc], W1[r1 * 257 + ld]);
        g_W2F[tI * 4 + 0] = h2pack(W2[r0 * 256 + la], W2[r0 * 256 + lb]);
        g_W2F[tI * 4 + 1] = h2pack(W2[r1 * 256 + la], W2[r1 * 256 + lb]);
        g_W2F[tI * 4 + 2] = h2pack(W2[r0 * 256 + lc], W2[r0 * 256 + ld]);
        g_W2F[tI * 4 + 3] = h2pack(W2[r1 * 256 + lc], W2[r1 * 256 + ld]);
        g_W3F[tI * 4 + 0] = h2pack(W3[r0 * 256 + la], W3[r0 * 256 + lb]);
        g_W3F[tI * 4 + 1] = h2pack(W3[r1 * 256 + la], W3[r1 * 256 + lb]);
        g_W3F[tI * 4 + 2] = h2pack(W3[r0 * 256 + lc], W3[r0 * 256 + ld]);
        g_W3F[tI * 4 + 3] = h2pack(W3[r1 * 256 + lc], W3[r1 * 256 + ld]);
    }
    for (int n = idx; n < 256; n += stride) g_W1last[n] = W1[n * 257 + 256];
    for (int tI = idx; tI < 48 * 4 * 32; tI += stride) {
        int l = tI & 31, kt = (tI >> 5) & 3, nt = tI >> 7;
        int gid = l >> 2, tig = l & 3;
        int r0 = nt * 16 + gid, r1 = r0 + 8;
        int c0 = kt * 16 + 2 * tig;
        int la = permL(c0), lb = permL(c0 + 1), lc = permL(c0 + 8), ld = permL(c0 + 9);
        g_WihF[tI * 4 + 0] = h2pack(W_ih[r0 * 64 + la], W_ih[r0 * 64 + lb]);
        g_WihF[tI * 4 + 1] = h2pack(W_ih[r1 * 64 + la], W_ih[r1 * 64 + lb]);
        g_WihF[tI * 4 + 2] = h2pack(W_ih[r0 * 64 + lc], W_ih[r0 * 64 + ld]);
        g_WihF[tI * 4 + 3] = h2pack(W_ih[r1 * 64 + lc], W_ih[r1 * 64 + ld]);
    }
    for (int tI = idx; tI < 48 * 16 * 32; tI += stride) {
        int l = tI & 31, kt = (tI >> 5) & 15, nt = tI >> 9;
        int gid = l >> 2, tig = l & 3;
        int r0 = nt * 16 + gid, r1 = r0 + 8;
        int c0 = kt * 16 + 2 * tig;
        int la = permL(c0), lb = permL(c0 + 1), lc = permL(c0 + 8), ld = permL(c0 + 9);
        g_WhhF[tI * 4 + 0] = h2pack(W_hh[r0 * 256 + la], W_hh[r0 * 256 + lb]);
        g_WhhF[tI * 4 + 1] = h2pack(W_hh[r1 * 256 + la], W_hh[r1 * 256 + lb]);
        g_WhhF[tI * 4 + 2] = h2pack(W_hh[r0 * 256 + lc], W_hh[r0 * 256 + ld]);
        g_WhhF[tI * 4 + 3] = h2pack(W_hh[r1 * 256 + lc], W_hh[r1 * 256 + ld]);
    }
}

__device__ __forceinline__ float sigm(float v) {
    return 1.0f / (1.0f + __expf(-v));
}
__device__ __forceinline__ float tanha(float v) {
    float r;
    asm("tanh.approx.f32 %0, %1;" : "=f"(r) : "f"(v));
    return r;
}

#define MMA_F16(c0, c1, c2, c3, A0, A1, A2, A3, B0, B1)                       \
    asm volatile(                                                             \
        "mma.sync.aligned.m16n8k16.row.col.f32.f16.f16.f32 "                  \
        "{%0,%1,%2,%3}, {%4,%5,%6,%7}, {%8,%9}, {%0,%1,%2,%3};"               \
        : "+f"(c0), "+f"(c1), "+f"(c2), "+f"(c3)                              \
        : "r"(A0), "r"(A1), "r"(A2), "r"(A3), "r"(B0), "r"(B1))

#define U32(f) __float_as_uint(f)
#define MMA_C(af, B0, B1)                                                     \
    MMA_F16(c0, c1, c2, c3, U32((af).x), U32((af).y), U32((af).z),            \
            U32((af).w), (B0), (B1))
#define MMA_D(af, B0, B1)                                                     \
    MMA_F16(d0, d1, d2, d3, U32((af).x), U32((af).y), U32((af).z),            \
            U32((af).w), (B0), (B1))

// RK4-stage / tanh epilogue for one 16-row tile (rows r0=nt*16+gid, r1=r0+8).
template<int EPI>
__device__ __forceinline__ void epi_tile(int nt, int gid, int tig,
                                         float c0, float c1, float c2, float c3,
                                         unsigned* __restrict__ dstp,
                                         const float* __restrict__ bias,
                                         const float* __restrict__ w1l,
                                         float tt, bool tcol,
                                         float* __restrict__ hT,
                                         unsigned* __restrict__ hTp,
                                         float* __restrict__ yT,
                                         unsigned* __restrict__ yTp,
                                         float* __restrict__ ka,
                                         const float* __restrict__ b3s,
                                         float dt) {
    const int r0 = nt * 16 + gid, r1 = r0 + 8;
    const int mc = 2 * tig;
    const int wB = (nt * 8 + gid) * 8;
    if (EPI == 0) {
        float bb0 = bias[r0], bb1 = bias[r1];
        if (tcol) { bb0 += tt * w1l[r0]; bb1 += tt * w1l[r1]; }
        dstp[wB + mc]     = h2pack(tanha(bb0 + c0), tanha(bb1 + c2));
        dstp[wB + mc + 1] = h2pack(tanha(bb0 + c1), tanha(bb1 + c3));
    } else {
        float b0 = b3s[r0], b1 = b3s[r1];
        float f0 = b0 + c0, f1 = b0 + c1;
        float f2 = b1 + c2, f3 = b1 + c3;
        float2 h0 = *reinterpret_cast<float2*>(&hT[r0 * 8 + mc]);
        float2 h1 = *reinterpret_cast<float2*>(&hT[r1 * 8 + mc]);
        if (EPI == 1) {
            *reinterpret_cast<float2*>(&ka[r0 * 8 + mc]) = make_float2(f0, f1);
            *reinterpret_cast<float2*>(&ka[r1 * 8 + mc]) = make_float2(f2, f3);
            float c = 0.5f * dt;
            float y0 = h0.x + c * f0, y1 = h0.y + c * f1;
            float y2 = h1.x + c * f2, y3 = h1.y + c * f3;
            *reinterpret_cast<float2*>(&yT[r0 * 8 + mc]) = make_float2(y0, y1);
            *reinterpret_cast<float2*>(&yT[r1 * 8 + mc]) = make_float2(y2, y3);
            yTp[wB + mc]     = h2pack(y0, y2);
            yTp[wB + mc + 1] = h2pack(y1, y3);
        } else if (EPI == 2 || EPI == 3) {
            float2 k0 = *reinterpret_cast<float2*>(&ka[r0 * 8 + mc]);
            float2 k1 = *reinterpret_cast<float2*>(&ka[r1 * 8 + mc]);
            *reinterpret_cast<float2*>(&ka[r0 * 8 + mc]) =
                make_float2(k0.x + 2.f * f0, k0.y + 2.f * f1);
            *reinterpret_cast<float2*>(&ka[r1 * 8 + mc]) =
                make_float2(k1.x + 2.f * f2, k1.y + 2.f * f3);
            float c = (EPI == 2) ? 0.5f * dt : dt;
            float y0 = h0.x + c * f0, y1 = h0.y + c * f1;
            float y2 = h1.x + c * f2, y3 = h1.y + c * f3;
            *reinterpret_cast<float2*>(&yT[r0 * 8 + mc]) = make_float2(y0, y1);
            *reinterpret_cast<float2*>(&yT[r1 * 8 + mc]) = make_float2(y2, y3);
            yTp[wB + mc]     = h2pack(y0, y2);
            yTp[wB + mc + 1] = h2pack(y1, y3);
        } else {  // EPI == 4
            float2 k0 = *reinterpret_cast<float2*>(&ka[r0 * 8 + mc]);
            float2 k1 = *reinterpret_cast<float2*>(&ka[r1 * 8 + mc]);
            float c = dt * (1.0f / 6.0f);
            float n0 = h0.x + c * (k0.x + f0), n1 = h0.y + c * (k0.y + f1);
            float n2 = h1.x + c * (k1.x + f2), n3 = h1.y + c * (k1.y + f3);
            *reinterpret_cast<float2*>(&hT[r0 * 8 + mc]) = make_float2(n0, n1);
            *reinterpret_cast<float2*>(&hT[r1 * 8 + mc]) = make_float2(n2, n3);
            hTp[wB + mc]     = h2pack(n0, n2);
            hTp[wB + mc + 1] = h2pack(n1, n3);
        }
    }
}

// One MLP GEMM: D[256][8] = W @ B. Warp w owns tiles (2w, 2w+1) = 32 rows.
// One B-fragment pair per kt feeds both tiles' mmas.
// SMW=false: kt0..1 per tile from pre[4] (cross-barrier), depth-4 rolling
// pipeline for the rest; prefetch NextWF's kt0..1 into pre[].
template<int EPI, bool SMW>
__device__ __forceinline__ void gemm8(const unsigned* __restrict__ WF,
                                      const unsigned* __restrict__ NextWF,
                                      float4* __restrict__ pre,
                                      const unsigned* __restrict__ Bp,
                                      unsigned* __restrict__ dstp,
                                      const float* __restrict__ bias,
                                      const float* __restrict__ w1l,
                                      float tt, bool tcol,
                                      float* __restrict__ hT,
                                      unsigned* __restrict__ hTp,
                                      float* __restrict__ yT,
                                      unsigned* __restrict__ yTp,
                                      float* __restrict__ ka,
                                      const float* __restrict__ b3s,
                                      float dt) {
    const int warp = threadIdx.x >> 5;
    const int lane = threadIdx.x & 31;
    const int gid = lane >> 2, tig = lane & 3;
    const int nt0 = 2 * warp, nt1 = nt0 + 1;
    float c0 = 0.f, c1 = 0.f, c2 = 0.f, c3 = 0.f;   // tile0
    float d0 = 0.f, d1 = 0.f, d2 = 0.f, d3 = 0.f;   // tile1
    const unsigned* __restrict__ bq = Bp + tig * 8 + gid;
    const float4* __restrict__ wp0 =
        reinterpret_cast<const float4*>(WF) + (nt0 * 16 * 32 + lane);
    const float4* __restrict__ wp1 = wp0 + 16 * 32;
    if (SMW) {
#pragma unroll 4
        for (int kt = 0; kt < 16; ++kt) {
            float4 af0 = wp0[kt * 32];
            float4 af1 = wp1[kt * 32];
            unsigned B0 = bq[kt * 64], B1 = bq[kt * 64 + 32];
            MMA_C(af0, B0, B1);
            MMA_D(af1, B0, B1);
        }
    } else {
        float4 A0[4], A1[4];
#pragma unroll
        for (int p = 0; p < 4; ++p) {
            A0[p] = wp0[(p + 2) * 32];   // kt 2..5
            A1[p] = wp1[(p + 2) * 32];
        }
#pragma unroll
        for (int kt = 0; kt < 2; ++kt) {
            unsigned B0 = bq[kt * 64], B1 = bq[kt * 64 + 32];
            MMA_C(pre[kt], B0, B1);
            MMA_D(pre[2 + kt], B0, B1);
        }
#pragma unroll
        for (int kt = 2; kt < 16; ++kt) {
            int j = (kt - 2) & 3;
            float4 af0 = A0[j], af1 = A1[j];
            if (kt < 12) {
                A0[j] = wp0[(kt + 4) * 32];
                A1[j] = wp1[(kt + 4) * 32];
            }
            unsigned B0 = bq[kt * 64], B1 = bq[kt * 64 + 32];
            MMA_C(af0, B0, B1);
            MMA_D(af1, B0, B1);
        }
        // prefetch next global GEMM's kt0..1 per tile
        const float4* __restrict__ np0 =
            reinterpret_cast<const float4*>(NextWF) + (nt0 * 16 * 32 + lane);
        const float4* __restrict__ np1 = np0 + 16 * 32;
        pre[0] = np0[0]; pre[1] = np0[32];
        pre[2] = np1[0]; pre[3] = np1[32];
    }
    epi_tile<EPI>(nt0, gid, tig, c0, c1, c2, c3, dstp, bias, w1l, tt, tcol,
                  hT, hTp, yT, yTp, ka, b3s, dt);
    epi_tile<EPI>(nt1, gid, tig, d0, d1, d2, d3, dstp, bias, w1l, tt, tcol,
                  hT, hTp, yT, yTp, ka, b3s, dt);
}

// GRU GEMMs: 8 warps, each covers 2 tiles of every logical group.
__device__ __forceinline__ void gru_gemm(const unsigned* __restrict__ xTp,
                                         const unsigned* __restrict__ hTp,
                                         float* __restrict__ g,
                                         float* __restrict__ gin,
                                         float* __restrict__ ghn,
                                         const float* __restrict__ bihs,
                                         const float* __restrict__ bhhs) {
    const int warp = threadIdx.x >> 5;
    const int lane = threadIdx.x & 31;
    const int gid = lane >> 2, tig = lane & 3;
    const int mc = 2 * tig;
    const unsigned* __restrict__ bx = xTp + tig * 8 + gid;
    const unsigned* __restrict__ bh = hTp + tig * 8 + gid;
    // fused r/z tiles: nt = 2w+s and 2w+s+16 (dual per group via s loop)
#pragma unroll
    for (int grp = 0; grp < 2; ++grp) {
        const int ntA = 2 * warp + 16 * grp;       // tiles (ntA, ntA+1)
        float c0 = 0.f, c1 = 0.f, c2 = 0.f, c3 = 0.f;
        float d0 = 0.f, d1 = 0.f, d2 = 0.f, d3 = 0.f;
        const float4* __restrict__ wx0 =
            reinterpret_cast<const float4*>(g_WihF) + (ntA * 4 * 32 + lane);
        const float4* __restrict__ wx1 = wx0 + 4 * 32;
#pragma unroll
        for (int kt = 0; kt < 4; ++kt) {
            unsigned B0 = bx[kt * 64], B1 = bx[kt * 64 + 32];
            float4 a0 = wx0[kt * 32], a1 = wx1[kt * 32];
            MMA_C(a0, B0, B1);
            MMA_D(a1, B0, B1);
        }
        const float4* __restrict__ wh0 =
            reinterpret_cast<const float4*>(g_WhhF) + (ntA * 16 * 32 + lane);
        const float4* __restrict__ wh1 = wh0 + 16 * 32;
#pragma unroll 4
        for (int kt = 0; kt < 16; ++kt) {
            unsigned B0 = bh[kt * 64], B1 = bh[kt * 64 + 32];
            float4 a0 = wh0[kt * 32], a1 = wh1[kt * 32];
            MMA_C(a0, B0, B1);
            MMA_D(a1, B0, B1);
        }
#pragma unroll
        for (int s = 0; s < 2; ++s) {
            const int nt = ntA + s;
            const int r0 = nt * 16 + gid, r1 = r0 + 8;
            float bb0 = bihs[r0] + bhhs[r0], bb1 = bihs[r1] + bhhs[r1];
            float e0 = s ? d0 : c0, e1 = s ? d1 : c1;
            float e2 = s ? d2 : c2, e3 = s ? d3 : c3;
            *reinterpret_cast<float2*>(&g[r0 * 8 + mc]) = make_float2(bb0 + e0, bb0 + e1);
            *reinterpret_cast<float2*>(&g[r1 * 8 + mc]) = make_float2(bb1 + e2, bb1 + e3);
        }
    }
    // gin: W_ih tiles (2w+32, 2w+33)
    {
        const int ntA = 2 * warp + 32;
        float c0 = 0.f, c1 = 0.f, c2 = 0.f, c3 = 0.f;
        float d0 = 0.f, d1 = 0.f, d2 = 0.f, d3 = 0.f;
        const float4* __restrict__ wx0 =
            reinterpret_cast<const float4*>(g_WihF) + (ntA * 4 * 32 + lane);
        const float4* __restrict__ wx1 = wx0 + 4 * 32;
#pragma unroll
        for (int kt = 0; kt < 4; ++kt) {
            unsigned B0 = bx[kt * 64], B1 = bx[kt * 64 + 32];
            float4 a0 = wx0[kt * 32], a1 = wx1[kt * 32];
            MMA_C(a0, B0, B1);
            MMA_D(a1, B0, B1);
        }
#pragma unroll
        for (int s = 0; s < 2; ++s) {
            const int lr0 = (2 * warp + s) * 16 + gid, lr1 = lr0 + 8;
            float bb0 = bihs[512 + lr0], bb1 = bihs[512 + lr1];
            float e0 = s ? d0 : c0, e1 = s ? d1 : c1;
            float e2 = s ? d2 : c2, e3 = s ? d3 : c3;
            *reinterpret_cast<float2*>(&gin[lr0 * 8 + mc]) = make_float2(bb0 + e0, bb0 + e1);
            *reinterpret_cast<float2*>(&gin[lr1 * 8 + mc]) = make_float2(bb1 + e2, bb1 + e3);
        }
    }
    // ghn: W_hh tiles (2w+32, 2w+33)
    {
        const int ntA = 2 * warp + 32;
        float c0 = 0.f, c1 = 0.f, c2 = 0.f, c3 = 0.f;
        float d0 = 0.f, d1 = 0.f, d2 = 0.f, d3 = 0.f;
        const float4* __restrict__ wh0 =
            reinterpret_cast<const float4*>(g_WhhF) + (ntA * 16 * 32 + lane);
        const float4* __restrict__ wh1 = wh0 + 16 * 32;
#pragma unroll 4
        for (int kt = 0; kt < 16; ++kt) {
            unsigned B0 = bh[kt * 64], B1 = bh[kt * 64 + 32];
            float4 a0 = wh0[kt * 32], a1 = wh1[kt * 32];
            MMA_C(a0, B0, B1);
            MMA_D(a1, B0, B1);
        }
#pragma unroll
        for (int s = 0; s < 2; ++s) {
            const int lr0 = (2 * warp + s) * 16 + gid, lr1 = lr0 + 8;
            float bb0 = bhhs[512 + lr0], bb1 = bhhs[512 + lr1];
            float e0 = s ? d0 : c0, e1 = s ? d1 : c1;
            float e2 = s ? d2 : c2, e3 = s ? d3 : c3;
            *reinterpret_cast<float2*>(&ghn[lr0 * 8 + mc]) = make_float2(bb0 + e0, bb0 + e1);
            *reinterpret_cast<float2*>(&ghn[lr1 * 8 + mc]) = make_float2(bb1 + e2, bb1 + e3);
        }
    }
}

__global__ void __launch_bounds__(NT, 1)
odernn_kernel(const float* __restrict__ x,
              const float* __restrict__ t,
              const float* __restrict__ mask,
              const float* __restrict__ b_ih,
              const float* __restrict__ b_hh,
              const float* __restrict__ b1,
              const float* __restrict__ b2,
              const float* __restrict__ b3,
              float* __restrict__ out) {
    extern __shared__ float sm[];
    unsigned* w3s = reinterpret_cast<unsigned*>(sm);          // 32768 u32 (128KB)
    float* hT  = sm + 32768;          // 2048
    unsigned* hTp = reinterpret_cast<unsigned*>(sm + 34816);  // 1024
    unsigned* xTp = reinterpret_cast<unsigned*>(sm + 35840);  // 256
    float* U   = sm + 36096;          // union: 8192 floats
    float* g   = U;                   // 4096 (GRU phase)
    float* gin = U + 4096;            // 2048
    float* ghn = U + 6144;            // 2048
    float* yT  = U;                   // 2048 (RK4 phase)
    float* ka  = U + 2048;            // 2048
    unsigned* a1p = reinterpret_cast<unsigned*>(U + 4096);    // 1024
    unsigned* a2p = reinterpret_cast<unsigned*>(U + 5120);    // 1024
    unsigned* yTp = reinterpret_cast<unsigned*>(U + 6144);    // 1024
    float* bihs = sm + 44288;         // 768
    float* bhhs = bihs + 768;         // 768
    float* b1s  = bhhs + 768;         // 256
    float* b2s  = b1s + 256;          // 256
    float* b3s  = b2s + 256;          // 256
    float* w1ls = b3s + 256;          // 256
    // total 46848 floats = 187392 bytes

    const int tid = threadIdx.x;
    const int m0 = blockIdx.x * MBR;

    {
        float4* d = reinterpret_cast<float4*>(w3s);
        const float4* s = reinterpret_cast<const float4*>(g_W3F);
        for (int idx = tid; idx < 16 * 16 * 32; idx += NT) d[idx] = s[idx];
    }
    for (int idx = tid; idx < 768; idx += NT) { bihs[idx] = b_ih[idx]; bhhs[idx] = b_hh[idx]; }
    for (int idx = tid; idx < 256; idx += NT) {
        b1s[idx] = b1[idx]; b2s[idx] = b2[idx]; b3s[idx] = b3[idx];
        w1ls[idx] = g_W1last[idx];
    }
    for (int idx = tid; idx < 256 * 8; idx += NT) hT[idx] = 0.0f;
    for (int idx = tid; idx < 128 * 8; idx += NT) hTp[idx] = 0u;
    __syncthreads();

    // initial cross-barrier preload: W1 kt0..1 for tiles (2w, 2w+1)
    float4 pre[4];
    {
        const float4* w0 = reinterpret_cast<const float4*>(g_W1F) +
                           ((2 * (tid >> 5)) * 16 * 32 + (tid & 31));
        const float4* w1p = w0 + 16 * 32;
        pre[0] = w0[0];  pre[1] = w0[32];
        pre[2] = w1p[0]; pre[3] = w1p[32];
    }

    for (int i = 0; i < T_LEN; ++i) {
        for (int idx = tid; idx < 32 * 8; idx += NT) {
            int m = idx & 7, w2 = idx >> 3;
            int blk = w2 >> 3, q = w2 & 7;
            const float* xr = x + ((size_t)(m0 + m) * T_LEN + i) * 64;
            xTp[idx] = h2pack(xr[blk * 16 + q], xr[blk * 16 + q + 8]);
        }
        __syncthreads();

        gru_gemm(xTp, hTp, g, gin, ghn, bihs, bhhs);
        __syncthreads();

        // gate pointwise on row pairs (n, n+8); 256 threads -> 4 j-iters
        {
            const int pm = tid & 7;
            const int pid = tid >> 3;       // 0..31
            const int q = pid & 7;
            const int bblk = pid >> 3;      // 0..3
            const float mk = mask[(size_t)(m0 + pm) * T_LEN + i];
#pragma unroll
            for (int j = 0; j < 4; ++j) {
                int blk = bblk + 4 * j;
                float hobs2[2];
#pragma unroll
                for (int hh = 0; hh < 2; ++hh) {
                    int n = blk * 16 + q + 8 * hh;
                    float r = sigm(g[n * 8 + pm]);
                    float z = sigm(g[(256 + n) * 8 + pm]);
                    float h = hT[n * 8 + pm];
                    float nn = tanhf(gin[n * 8 + pm] + r * ghn[n * 8 + pm]);
                    float hnew = (1.0f - z) * nn + z * h;
                    float hobs = mk * hnew + (1.0f - mk) * h;
                    hT[n * 8 + pm] = hobs;
                    out[((size_t)(m0 + pm) * T_LEN + i) * 256 + n] = hobs;
                    hobs2[hh] = hobs;
                }
                hTp[(blk * 8 + q) * 8 + pm] = h2pack(hobs2[0], hobs2[1]);
            }
        }
        __syncthreads();

        if (i == T_LEN - 1) break;

        float t0v = t[i], t1v = t[i + 1];
        float dt = (t1v - t0v) * 0.25f;
        float tt = t0v;
        for (int sub = 0; sub < 4; ++sub) {
            // stage 1: f(tt, h)
            gemm8<0, false>(g_W1F, g_W2F, pre, hTp, a1p, b1s, w1ls, tt, true, 0, 0, 0, 0, 0, 0, 0.f); __syncthreads();
            gemm8<0, false>(g_W2F, g_W1F, pre, a1p, a2p, b2s, 0, 0.f, false, 0, 0, 0, 0, 0, 0, 0.f); __syncthreads();
            gemm8<1, true>(w3s, 0, pre, a2p, 0, 0, 0, 0.f, false, hT, hTp, yT, yTp, ka, b3s, dt); __syncthreads();
            // stage 2: f(tt+dt/2, y)
            gemm8<0, false>(g_W1F, g_W2F, pre, yTp, a1p, b1s, w1ls, tt + 0.5f * dt, true, 0, 0, 0, 0, 0, 0, 0.f); __syncthreads();
            gemm8<0, false>(g_W2F, g_W1F, pre, a1p, a2p, b2s, 0, 0.f, false, 0, 0, 0, 0, 0, 0, 0.f); __syncthreads();
            gemm8<2, true>(w3s, 0, pre, a2p, 0, 0, 0, 0.f, false, hT, hTp, yT, yTp, ka, b3s, dt); __syncthreads();
            // stage 3: f(tt+dt/2, y)
            gemm8<0, false>(g_W1F, g_W2F, pre, yTp, a1p, b1s, w1ls, tt + 0.5f * dt, true, 0, 0, 0, 0, 0, 0, 0.f); __syncthreads();
            gemm8<0, false>(g_W2F, g_W1F, pre, a1p, a2p, b2s, 0, 0.f, false, 0, 0, 0, 0, 0, 0, 0.f); __syncthreads();
            gemm8<3, true>(w3s, 0, pre, a2p, 0, 0, 0, 0.f, false, hT, hTp, yT, yTp, ka, b3s, dt); __syncthreads();
            // stage 4: f(tt+dt, y)
            gemm8<0, false>(g_W1F, g_W2F, pre, yTp, a1p, b1s, w1ls, tt + dt, true, 0, 0, 0, 0, 0, 0, 0.f); __syncthreads();
            gemm8<0, false>(g_W2F, g_W1F, pre, a1p, a2p, b2s, 0, 0.f, false, 0, 0, 0, 0, 0, 0, 0.f); __syncthreads();
            gemm8<4, true>(w3s, 0, pre, a2p, 0, 0, 0, 0.f, false, hT, hTp, yT, yTp, ka, b3s, dt); __syncthreads();
            tt += dt;
        }
    }
}

extern "C" void kernel_launch(void* const* d_in, const int* in_sizes, int n_in,
                              void* d_out, int out_size) {
    const float* x    = (const float*)d_in[0];
    const float* t    = (const float*)d_in[1];
    const float* mask = (const float*)d_in[2];
    const float* W_ih = (const float*)d_in[3];
    const float* W_hh = (const float*)d_in[4];
    const float* b_ih = (const float*)d_in[5];
    const float* b_hh = (const float*)d_in[6];
    const float* W1   = (const float*)d_in[7];
    const float* b1   = (const float*)d_in[8];
    const float* W2   = (const float*)d_in[9];
    const float* b2   = (const float*)d_in[10];
    const float* W3   = (const float*)d_in[11];
    const float* b3   = (const float*)d_in[12];
    float* out = (float*)d_out;

    prep_kernel<<<256, 256>>>(W_ih, W_hh, W1, W2, W3);

    const int smem_bytes = 46848 * sizeof(float);  // 187392
    cudaFuncSetAttribute(odernn_kernel,
                         cudaFuncAttributeMaxDynamicSharedMemorySize, smem_bytes);
    odernn_kernel<<<NCTA, NT, smem_bytes>>>(x, t, mask, b_ih, b_hh,
                                            b1, b2, b3, out);
}